// round 6
// baseline (speedup 1.0000x reference)
#include <cuda_runtime.h>
#include <cuda_bf16.h>
#include <cstdint>

#define NN     50000
#define EE     625000
#define IN_EDGE 64
#define HH     128
#define HH2    256
#define OUTD   112
#define TILES_M 391   // ceil(50000/128)
#define NB     196    // ceil(50000/256)

// packed-split layout: per row, features in octets of 8; each octet stored as
// [8 x bf16 hi | 8 x bf16 lo] = 32 bytes. Row byte size = K*4.

// ---------------- scratch (device globals; no allocation allowed) ----------
__device__ __align__(16) float g_eam[NN * HH];
__device__ __align__(16) float g_seg[NN * IN_EDGE];
__device__ float g_inv[NN];
__device__ int   g_degi[NN];
__device__ int   g_rowptr[NN + 1];
__device__ int   g_cursor[NN];
__device__ int   g_bsum[NB];
__device__ int   g_boff[NB];
__device__ int   g_csrc[EE];
__device__ int   g_ceid[EE];

__device__ __align__(16) __nv_bfloat16 g_xpk [NN * 2 * HH];   // node state packed
__device__ __align__(16) __nv_bfloat16 g_cpk [NN * 2 * HH];   // combined packed
__device__ __align__(16) __nv_bfloat16 g_h1pk[NN * 2 * HH2];  // W1 out packed

// packed weights, [N][K] transposed, byte offsets:
//   node 0, edge 65536, W1[l] 98304+l*131072, W2[l] 491520+l*131072, lin 884736
__device__ __align__(16) __nv_bfloat16 g_wpk[471040];

// ---------------------------------------------------------------------------
__device__ __forceinline__ uint32_t smem_u32(const void* p) {
    uint32_t a;
    asm("{ .reg .u64 t; cvta.to.shared.u64 t, %1; cvt.u32.u64 %0, t; }"
        : "=r"(a) : "l"(p));
    return a;
}
__device__ __forceinline__ void cp16(uint32_t dst, const void* src) {
    asm volatile("cp.async.cg.shared.global [%0], [%1], 16;"
                 :: "r"(dst), "l"(src) : "memory");
}
__device__ __forceinline__ void zero16(uint32_t dst) {
    asm volatile("st.shared.v4.b32 [%0], {%1,%1,%1,%1};" :: "r"(dst), "r"(0) : "memory");
}
__device__ __forceinline__ void ldsm4(uint32_t* r, uint32_t addr) {
    asm volatile("ldmatrix.sync.aligned.m8n8.x4.shared.b16 {%0,%1,%2,%3}, [%4];"
                 : "=r"(r[0]), "=r"(r[1]), "=r"(r[2]), "=r"(r[3]) : "r"(addr));
}
__device__ __forceinline__ void mma16816(float* d, const uint32_t* a, const uint32_t* b) {
    asm volatile("mma.sync.aligned.m16n8k16.row.col.f32.bf16.bf16.f32 "
                 "{%0,%1,%2,%3}, {%4,%5,%6,%7}, {%8,%9}, {%0,%1,%2,%3};"
                 : "+f"(d[0]), "+f"(d[1]), "+f"(d[2]), "+f"(d[3])
                 : "r"(a[0]), "r"(a[1]), "r"(a[2]), "r"(a[3]), "r"(b[0]), "r"(b[1]));
}
__device__ __forceinline__ void split2(float a, float b, uint32_t& hi, uint32_t& lo) {
    __nv_bfloat16 ha = __float2bfloat16(a), hb = __float2bfloat16(b);
    __nv_bfloat162 h = __halves2bfloat162(ha, hb);
    __nv_bfloat162 l = __halves2bfloat162(
        __float2bfloat16(a - __bfloat162float(ha)),
        __float2bfloat16(b - __bfloat162float(hb)));
    hi = *(uint32_t*)&h; lo = *(uint32_t*)&l;
}
// accumulate 8 bf16 (packed in uint4) into s[0..8)
__device__ __forceinline__ void acc8(uint4 v, float* s) {
    s[0] += __uint_as_float(v.x << 16); s[1] += __uint_as_float(v.x & 0xffff0000u);
    s[2] += __uint_as_float(v.y << 16); s[3] += __uint_as_float(v.y & 0xffff0000u);
    s[4] += __uint_as_float(v.z << 16); s[5] += __uint_as_float(v.z & 0xffff0000u);
    s[6] += __uint_as_float(v.w << 16); s[7] += __uint_as_float(v.w & 0xffff0000u);
}
// packed epilogue store of a feature pair (c, c+1)
__device__ __forceinline__ void store_pk(__nv_bfloat16* Cp, int Nc, int r, int c,
                                         float a, float b) {
    uint32_t h, l; split2(a, b, h, l);
    char* p = (char*)Cp + (size_t)r * Nc * 4 + ((c >> 3) * 32 + (c & 7) * 2);
    *(uint32_t*)p = h; *(uint32_t*)(p + 16) = l;
}

// ---------------------------------------------------------------------------
// front: fused weight prep (packed split) + degree histogram
// ---------------------------------------------------------------------------
__global__ void front_kernel(const float* __restrict__ node_W, const float* __restrict__ edge_W,
                             const float* __restrict__ W1, const float* __restrict__ W2,
                             const float* __restrict__ lin_W, char* __restrict__ wpk,
                             const int* __restrict__ ei, int* __restrict__ degi) {
    if (blockIdx.x < 920) {
        int i = blockIdx.x * 256 + threadIdx.x;
        if (i >= 235520) return;
        const float* src; int K, Nc, idx; size_t off;
        if (i < 16384)       { src = node_W; K = 128; Nc = 128; idx = i;          off = 0; }
        else if (i < 24576)  { src = edge_W; K =  64; Nc = 128; idx = i - 16384;  off = 65536; }
        else if (i < 122880) { int j = i - 24576;  src = W1 + (j / 32768) * 32768;
                               K = 128; Nc = 256; idx = j % 32768; off = 98304 + (size_t)(j / 32768) * 131072; }
        else if (i < 221184) { int j = i - 122880; src = W2 + (j / 32768) * 32768;
                               K = 256; Nc = 128; idx = j % 32768; off = 491520 + (size_t)(j / 32768) * 131072; }
        else                 { src = lin_W;  K = 128; Nc = 112; idx = i - 221184; off = 884736; }
        int n = idx / K, k = idx % K;
        float v = __ldg(&src[(size_t)k * Nc + n]);
        __nv_bfloat16 h = __float2bfloat16(v);
        __nv_bfloat16 l = __float2bfloat16(v - __bfloat162float(h));
        char* p = wpk + off + (size_t)n * K * 4 + (k >> 3) * 32 + (k & 7) * 2;
        *(__nv_bfloat16*)p = h;
        *(__nv_bfloat16*)(p + 16) = l;
    } else {
        int e = (blockIdx.x - 920) * 256 + threadIdx.x;
        if (e < EE) atomicAdd(&degi[ei[EE + e]], 1);
    }
}

// ---------------------------------------------------------------------------
// CSR build
// ---------------------------------------------------------------------------
__global__ void scan1(const int* __restrict__ d, int* __restrict__ bsum) {
    __shared__ int s[256];
    int i = blockIdx.x * 256 + threadIdx.x;
    s[threadIdx.x] = (i < NN) ? d[i] : 0;
    __syncthreads();
    for (int o = 128; o > 0; o >>= 1) {
        if (threadIdx.x < o) s[threadIdx.x] += s[threadIdx.x + o];
        __syncthreads();
    }
    if (threadIdx.x == 0) bsum[blockIdx.x] = s[0];
}
__global__ void scan2(const int* __restrict__ bsum, int* __restrict__ boff,
                      int* __restrict__ rowptr_last) {
    __shared__ int s[256];
    int t = threadIdx.x;
    int v = (t < NB) ? bsum[t] : 0;
    s[t] = v;
    __syncthreads();
    #pragma unroll
    for (int o = 1; o < 256; o <<= 1) {
        int tv = (t >= o) ? s[t - o] : 0;
        __syncthreads();
        s[t] += tv;
        __syncthreads();
    }
    if (t < NB) boff[t] = s[t] - v;
    if (t == 255) rowptr_last[0] = s[255];
}
__global__ void scan3(const int* __restrict__ d, const int* __restrict__ boff,
                      int* __restrict__ rowptr, int* __restrict__ cursor,
                      float* __restrict__ inv) {
    __shared__ int s[256];
    int i = blockIdx.x * 256 + threadIdx.x;
    int v = (i < NN) ? d[i] : 0;
    s[threadIdx.x] = v;
    __syncthreads();
    #pragma unroll
    for (int o = 1; o < 256; o <<= 1) {
        int t = (threadIdx.x >= o) ? s[threadIdx.x - o] : 0;
        __syncthreads();
        s[threadIdx.x] += t;
        __syncthreads();
    }
    if (i < NN) {
        int excl = s[threadIdx.x] - v + boff[blockIdx.x];
        rowptr[i] = excl;
        cursor[i] = excl;
        inv[i] = 1.0f / (float)max(v, 1);
    }
}
__global__ void csr_fill(const int* __restrict__ ei, int* __restrict__ cursor,
                         int* __restrict__ csrc, int* __restrict__ ceid) {
    int e = blockIdx.x * blockDim.x + threadIdx.x;
    if (e >= EE) return;
    int dst = __ldg(&ei[EE + e]);
    int p = atomicAdd(&cursor[dst], 1);
    csrc[p] = __ldg(&ei[e]);
    ceid[p] = e;
}

// seg[i] = sum of edge_attr rows with dst=i.  16 threads per node.
__global__ void seg_gather(const int* __restrict__ rowptr, const int* __restrict__ ceid,
                           const float* __restrict__ ea, float* __restrict__ seg) {
    int g = (blockIdx.x * blockDim.x + threadIdx.x) >> 4;
    if (g >= NN) return;
    int lane = threadIdx.x & 15;
    int beg = __ldg(&rowptr[g]), end = __ldg(&rowptr[g + 1]);
    float4 acc = make_float4(0.f, 0.f, 0.f, 0.f);
    for (int j = beg; j < end; j++) {
        int e = __ldg(&ceid[j]);
        float4 v = __ldg((const float4*)(ea + (size_t)e * IN_EDGE) + lane);
        acc.x += v.x; acc.y += v.y; acc.z += v.z; acc.w += v.w;
    }
    *(float4*)(seg + (size_t)g * IN_EDGE + lane * 4) = acc;
}

// fused gather + GIN combine + split, packed layout.
// warp/node; lane loads one uint4 (octet o=lane>>1, part=lane&1: 0=hi,1=lo).
__global__ void gather_combine(const int* __restrict__ rowptr, const int* __restrict__ csrc,
                               const __nv_bfloat16* __restrict__ xp,
                               const float* __restrict__ eam, const float* __restrict__ inv,
                               const float* __restrict__ eps_p, int layer,
                               __nv_bfloat16* __restrict__ cp) {
    int w = (blockIdx.x * blockDim.x + threadIdx.x) >> 5;
    if (w >= NN) return;
    int lane = threadIdx.x & 31;
    int beg = __ldg(&rowptr[w]), end = __ldg(&rowptr[w + 1]);
    float s[8] = {0.f, 0.f, 0.f, 0.f, 0.f, 0.f, 0.f, 0.f};
    const char* xb = (const char*)xp;
    for (int j = beg; j < end; j++) {
        int src = __ldg(&csrc[j]);
        uint4 v = __ldg((const uint4*)(xb + (size_t)src * 512) + lane);
        acc8(v, s);
    }
    // pair-reduce: combine hi-part lane with lo-part lane (same octet)
    #pragma unroll
    for (int k = 0; k < 8; k++) s[k] += __shfl_xor_sync(0xffffffffu, s[k], 1);
    // self row
    float xs[8] = {0.f, 0.f, 0.f, 0.f, 0.f, 0.f, 0.f, 0.f};
    {
        uint4 v = __ldg((const uint4*)(xb + (size_t)w * 512) + lane);
        acc8(v, xs);
        #pragma unroll
        for (int k = 0; k < 8; k++) xs[k] += __shfl_xor_sync(0xffffffffu, xs[k], 1);
    }
    float iv = __ldg(&inv[w]);
    float epsv = 1.f + __ldg(&eps_p[layer]);
    if ((lane & 1) == 0) {
        int o = lane >> 1;
        const float4* ep = (const float4*)(eam + (size_t)w * HH + o * 8);
        float4 e0 = __ldg(ep), e1 = __ldg(ep + 1);
        float v0 = epsv * xs[0] + s[0] * iv + e0.x;
        float v1 = epsv * xs[1] + s[1] * iv + e0.y;
        float v2 = epsv * xs[2] + s[2] * iv + e0.z;
        float v3 = epsv * xs[3] + s[3] * iv + e0.w;
        float v4 = epsv * xs[4] + s[4] * iv + e1.x;
        float v5 = epsv * xs[5] + s[5] * iv + e1.y;
        float v6 = epsv * xs[6] + s[6] * iv + e1.z;
        float v7 = epsv * xs[7] + s[7] * iv + e1.w;
        uint4 hv, lv;
        split2(v0, v1, hv.x, lv.x);
        split2(v2, v3, hv.y, lv.y);
        split2(v4, v5, hv.z, lv.z);
        split2(v6, v7, hv.w, lv.w);
        char* dst = (char*)cp + (size_t)w * 512 + o * 32;
        *(uint4*)dst = hv;
        *(uint4*)(dst + 16) = lv;
    }
}

// ---------------------------------------------------------------------------
// GEMM with fp32-A conversion loader (node & edge encoders), packed B.
// EPI: 0 = +bias; 2 = *inv + [deg>0]*bias
// OUTMODE: 0 = fp32 out; 1 = packed split out
// ---------------------------------------------------------------------------
#define ROWB 144
template <int KTOT, int EPI, int OUTMODE>
__global__ void __launch_bounds__(256, 2)
gemm_f32a(const float* __restrict__ A, const char* __restrict__ Bp,
          const float* __restrict__ bias, float* __restrict__ Cf,
          __nv_bfloat16* __restrict__ Cp, int Nc,
          const float* __restrict__ inv, const int* __restrict__ degi) {
    extern __shared__ char smem[];
    const uint32_t sb  = smem_u32(smem);
    const uint32_t sAh = sb,          sAl = sb + 18432;
    const uint32_t sBh = sb + 36864,  sBl = sb + 46080;

    const int tid  = threadIdx.x;
    const int lane = tid & 31;
    const int wid  = tid >> 5;
    const int wm   = wid & 3;
    const int wn   = wid >> 2;
    const int rowBase = blockIdx.x * 128;
    const int colBase = blockIdx.y * 64;
    constexpr int K4 = KTOT * 4;

    float acc[2][4][4];
    #pragma unroll
    for (int a = 0; a < 2; a++)
        #pragma unroll
        for (int b = 0; b < 4; b++)
            #pragma unroll
            for (int c = 0; c < 4; c++) acc[a][b][c] = 0.f;

    const uint32_t aRow  = (uint32_t)(lane & 15);
    const uint32_t aKoff = (uint32_t)((lane >> 4) << 3);
    const uint32_t bRow  = (uint32_t)((lane & 7) + ((lane >> 4) << 3));
    const uint32_t bKoff = (uint32_t)(((lane >> 3) & 1) << 3);

    for (int kb = 0; kb < KTOT; kb += 64) {
        if (kb) __syncthreads();
        #pragma unroll
        for (int i = 0; i < 2; i++) {
            int f = tid + i * 256;
            int nrow = f >> 3, oct = f & 7;
            uint32_t dh = sBh + nrow * ROWB + oct * 16;
            uint32_t dl = sBl + nrow * ROWB + oct * 16;
            int gn = colBase + nrow;
            if (gn < Nc) {
                const char* src = Bp + (size_t)gn * K4 + kb * 4 + oct * 32;
                cp16(dh, src);
                cp16(dl, src + 16);
            } else { zero16(dh); zero16(dl); }
        }
        asm volatile("cp.async.commit_group;" ::: "memory");

        #pragma unroll
        for (int i = 0; i < 8; i++) {
            int f = tid + i * 256;
            int row = f >> 4;
            int c4  = f & 15;
            int gr = rowBase + row;
            float4 v = make_float4(0.f, 0.f, 0.f, 0.f);
            if (gr < NN) v = __ldg((const float4*)(A + (size_t)gr * KTOT + kb + c4 * 4));
            uint32_t h01, h23, l01, l23;
            split2(v.x, v.y, h01, l01);
            split2(v.z, v.w, h23, l23);
            uint32_t addr = row * ROWB + c4 * 8;
            asm volatile("st.shared.v2.b32 [%0], {%1,%2};"
                         :: "r"(sAh + addr), "r"(h01), "r"(h23) : "memory");
            asm volatile("st.shared.v2.b32 [%0], {%1,%2};"
                         :: "r"(sAl + addr), "r"(l01), "r"(l23) : "memory");
        }
        asm volatile("cp.async.wait_group 0;" ::: "memory");
        __syncthreads();

        #pragma unroll
        for (int ks = 0; ks < 4; ks++) {
            uint32_t ah[2][4], al[2][4], bh[4][2], bl[4][2];
            #pragma unroll
            for (int mi = 0; mi < 2; mi++) {
                uint32_t off = (wm * 32 + mi * 16 + aRow) * ROWB + (ks * 16 + aKoff) * 2;
                ldsm4(ah[mi], sAh + off);
                ldsm4(al[mi], sAl + off);
            }
            #pragma unroll
            for (int pr = 0; pr < 2; pr++) {
                uint32_t off = (wn * 32 + pr * 16 + bRow) * ROWB + (ks * 16 + bKoff) * 2;
                uint32_t t[4];
                ldsm4(t, sBh + off);
                bh[pr*2][0] = t[0]; bh[pr*2][1] = t[1];
                bh[pr*2+1][0] = t[2]; bh[pr*2+1][1] = t[3];
                ldsm4(t, sBl + off);
                bl[pr*2][0] = t[0]; bl[pr*2][1] = t[1];
                bl[pr*2+1][0] = t[2]; bl[pr*2+1][1] = t[3];
            }
            #pragma unroll
            for (int mi = 0; mi < 2; mi++)
                #pragma unroll
                for (int ni = 0; ni < 4; ni++) {
                    mma16816(acc[mi][ni], ah[mi], bh[ni]);
                    mma16816(acc[mi][ni], ah[mi], bl[ni]);
                    mma16816(acc[mi][ni], al[mi], bh[ni]);
                }
        }
    }

    const int group = lane >> 2;
    const int qc    = (lane & 3) * 2;
    #pragma unroll
    for (int mi = 0; mi < 2; mi++) {
        int r0 = rowBase + wm * 32 + mi * 16 + group;
        int r1 = r0 + 8;
        float iv0 = 0.f, m0 = 0.f, iv1 = 0.f, m1 = 0.f;
        if (EPI == 2) {
            if (r0 < NN) { iv0 = __ldg(&inv[r0]); m0 = (__ldg(&degi[r0]) > 0) ? 1.f : 0.f; }
            if (r1 < NN) { iv1 = __ldg(&inv[r1]); m1 = (__ldg(&degi[r1]) > 0) ? 1.f : 0.f; }
        }
        #pragma unroll
        for (int ni = 0; ni < 4; ni++) {
            int c = colBase + wn * 32 + ni * 8 + qc;
            if (c >= Nc) continue;
            float b0 = __ldg(&bias[c]), b1 = __ldg(&bias[c + 1]);
            float2 v0, v1;
            if (EPI == 2) {
                v0.x = acc[mi][ni][0] * iv0 + m0 * b0;
                v0.y = acc[mi][ni][1] * iv0 + m0 * b1;
                v1.x = acc[mi][ni][2] * iv1 + m1 * b0;
                v1.y = acc[mi][ni][3] * iv1 + m1 * b1;
            } else {
                v0.x = acc[mi][ni][0] + b0; v0.y = acc[mi][ni][1] + b1;
                v1.x = acc[mi][ni][2] + b0; v1.y = acc[mi][ni][3] + b1;
            }
            if (r0 < NN) {
                if (OUTMODE == 0) *(float2*)(Cf + (size_t)r0 * Nc + c) = v0;
                else store_pk(Cp, Nc, r0, c, v0.x, v0.y);
            }
            if (r1 < NN) {
                if (OUTMODE == 0) *(float2*)(Cf + (size_t)r1 * Nc + c) = v1;
                else store_pk(Cp, Nc, r1, c, v1.x, v1.y);
            }
        }
    }
}

// ---------------------------------------------------------------------------
// Pipelined packed-split GEMM (A and B both packed bf16 hi/lo).
// EPI: 0 = +bias, 1 = relu(+bias);  OUTMODE: 0 = fp32, 1 = packed split
// ---------------------------------------------------------------------------
template <int KTOT, int EPI, int OUTMODE>
__global__ void __launch_bounds__(256, 2)
gemm_pk(const __nv_bfloat16* __restrict__ Ap, const char* __restrict__ Bp,
        const float* __restrict__ bias, float* __restrict__ Cf,
        __nv_bfloat16* __restrict__ Cp, int Nc) {
    constexpr int CHUNKS = KTOT / 64;
    constexpr int STG = 49152;
    constexpr int K4 = KTOT * 4;
    extern __shared__ char smem[];
    const uint32_t sb = smem_u32(smem);

    const int tid  = threadIdx.x;
    const int lane = tid & 31;
    const int wid  = tid >> 5;
    const int wm   = wid & 3;
    const int wn   = wid >> 2;
    const int rowBase = blockIdx.x * 128;
    const int colBase = blockIdx.y * 64;
    const char* Ab = (const char*)Ap;

    float acc[2][4][4];
    #pragma unroll
    for (int a = 0; a < 2; a++)
        #pragma unroll
        for (int b = 0; b < 4; b++)
            #pragma unroll
            for (int c = 0; c < 4; c++) acc[a][b][c] = 0.f;

    auto load_slab = [&](int stage, int c) {
        uint32_t base = sb + stage * STG;
        int kb4 = c * 256;
        #pragma unroll
        for (int i = 0; i < 4; i++) {            // A: 128 rows x 8 octets
            int f = tid + i * 256;
            int row = f >> 3, oct = f & 7;
            uint32_t da = base + row * 128 + ((uint32_t)(oct * 16) ^ ((row & 7) << 4));
            int gr = rowBase + row;
            if (gr < NN) {
                const char* src = Ab + (size_t)gr * K4 + kb4 + oct * 32;
                cp16(da, src);
                cp16(da + 16384, src + 16);
            } else { zero16(da); zero16(da + 16384); }
        }
        #pragma unroll
        for (int i = 0; i < 2; i++) {            // B: 64 rows x 8 octets
            int f = tid + i * 256;
            int row = f >> 3, oct = f & 7;
            uint32_t db = base + 32768 + row * 128 + ((uint32_t)(oct * 16) ^ ((row & 7) << 4));
            int gn = colBase + row;
            if (gn < Nc) {
                const char* src = Bp + (size_t)gn * K4 + kb4 + oct * 32;
                cp16(db, src);
                cp16(db + 8192, src + 16);
            } else { zero16(db); zero16(db + 8192); }
        }
        asm volatile("cp.async.commit_group;" ::: "memory");
    };

    const uint32_t aRowIdx = (uint32_t)(lane & 15);
    const uint32_t aK16    = (uint32_t)((lane >> 4) << 4);
    const uint32_t bRowIdx = (uint32_t)((lane & 7) + ((lane >> 4) << 3));
    const uint32_t bK16    = (uint32_t)(((lane >> 3) & 1) << 4);

    load_slab(0, 0);

    for (int c = 0; c < CHUNKS; c++) {
        if (c + 1 < CHUNKS) {
            load_slab((c + 1) & 1, c + 1);
            asm volatile("cp.async.wait_group 1;" ::: "memory");
        } else {
            asm volatile("cp.async.wait_group 0;" ::: "memory");
        }
        __syncthreads();

        uint32_t bA = sb + (c & 1) * STG;
        uint32_t bB = bA + 32768;
        #pragma unroll
        for (int ks = 0; ks < 4; ks++) {
            uint32_t ah[2][4], al[2][4], bh[4][2], bl[4][2];
            #pragma unroll
            for (int mi = 0; mi < 2; mi++) {
                uint32_t row = wm * 32 + mi * 16 + aRowIdx;
                uint32_t cb = (uint32_t)(ks * 32) + aK16;
                uint32_t off = row * 128 + (cb ^ ((row & 7) << 4));
                ldsm4(ah[mi], bA + off);
                ldsm4(al[mi], bA + 16384 + off);
            }
            #pragma unroll
            for (int pr = 0; pr < 2; pr++) {
                uint32_t row = wn * 32 + pr * 16 + bRowIdx;
                uint32_t cb = (uint32_t)(ks * 32) + bK16;
                uint32_t off = row * 128 + (cb ^ ((row & 7) << 4));
                uint32_t t[4];
                ldsm4(t, bB + off);
                bh[pr*2][0] = t[0]; bh[pr*2][1] = t[1];
                bh[pr*2+1][0] = t[2]; bh[pr*2+1][1] = t[3];
                ldsm4(t, bB + 8192 + off);
                bl[pr*2][0] = t[0]; bl[pr*2][1] = t[1];
                bl[pr*2+1][0] = t[2]; bl[pr*2+1][1] = t[3];
            }
            #pragma unroll
            for (int mi = 0; mi < 2; mi++)
                #pragma unroll
                for (int ni = 0; ni < 4; ni++) {
                    mma16816(acc[mi][ni], ah[mi], bh[ni]);
                    mma16816(acc[mi][ni], ah[mi], bl[ni]);
                    mma16816(acc[mi][ni], al[mi], bh[ni]);
                }
        }
        if (c + 1 < CHUNKS) __syncthreads();
    }

    const int group = lane >> 2;
    const int qc    = (lane & 3) * 2;
    #pragma unroll
    for (int mi = 0; mi < 2; mi++) {
        int r0 = rowBase + wm * 32 + mi * 16 + group;
        int r1 = r0 + 8;
        #pragma unroll
        for (int ni = 0; ni < 4; ni++) {
            int c = colBase + wn * 32 + ni * 8 + qc;
            if (c >= Nc) continue;
            float b0 = __ldg(&bias[c]), b1 = __ldg(&bias[c + 1]);
            float2 v0, v1;
            v0.x = acc[mi][ni][0] + b0; v0.y = acc[mi][ni][1] + b1;
            v1.x = acc[mi][ni][2] + b0; v1.y = acc[mi][ni][3] + b1;
            if (EPI == 1) {
                v0.x = fmaxf(v0.x, 0.f); v0.y = fmaxf(v0.y, 0.f);
                v1.x = fmaxf(v1.x, 0.f); v1.y = fmaxf(v1.y, 0.f);
            }
            if (r0 < NN) {
                if (OUTMODE == 0) *(float2*)(Cf + (size_t)r0 * Nc + c) = v0;
                else store_pk(Cp, Nc, r0, c, v0.x, v0.y);
            }
            if (r1 < NN) {
                if (OUTMODE == 0) *(float2*)(Cf + (size_t)r1 * Nc + c) = v1;
                else store_pk(Cp, Nc, r1, c, v1.x, v1.y);
            }
        }
    }
}

// ---------------------------------------------------------------------------
extern "C" void kernel_launch(void* const* d_in, const int* in_sizes, int n_in,
                              void* d_out, int out_size) {
    const float* x_in   = (const float*)d_in[0];
    const float* eattr  = (const float*)d_in[1];
    const int*   eidx   = (const int*)  d_in[2];
    const float* node_W = (const float*)d_in[3];
    const float* node_b = (const float*)d_in[4];
    const float* edge_W = (const float*)d_in[5];
    const float* edge_b = (const float*)d_in[6];
    const float* W1     = (const float*)d_in[7];
    const float* b1     = (const float*)d_in[8];
    const float* W2     = (const float*)d_in[9];
    const float* b2     = (const float*)d_in[10];
    const float* eps    = (const float*)d_in[11];
    const float* lin_W  = (const float*)d_in[12];
    const float* lin_b  = (const float*)d_in[13];
    float* out = (float*)d_out;

    float *peam, *pseg, *pinv;
    int *pdegi, *prowptr, *pcursor, *pbsum, *pboff, *pcsrc, *pceid;
    __nv_bfloat16 *pwpk, *pxpk, *pcpk, *ph1pk;
    cudaGetSymbolAddress((void**)&peam, g_eam);
    cudaGetSymbolAddress((void**)&pseg, g_seg);
    cudaGetSymbolAddress((void**)&pinv, g_inv);
    cudaGetSymbolAddress((void**)&pdegi, g_degi);
    cudaGetSymbolAddress((void**)&prowptr, g_rowptr);
    cudaGetSymbolAddress((void**)&pcursor, g_cursor);
    cudaGetSymbolAddress((void**)&pbsum, g_bsum);
    cudaGetSymbolAddress((void**)&pboff, g_boff);
    cudaGetSymbolAddress((void**)&pcsrc, g_csrc);
    cudaGetSymbolAddress((void**)&pceid, g_ceid);
    cudaGetSymbolAddress((void**)&pwpk, g_wpk);
    cudaGetSymbolAddress((void**)&pxpk, g_xpk);
    cudaGetSymbolAddress((void**)&pcpk, g_cpk);
    cudaGetSymbolAddress((void**)&ph1pk, g_h1pk);
    char* wpkb = (char*)pwpk;

    constexpr int SM_F32A = 55296;
    constexpr int SM_PK   = 98304;
    auto setsm = [](const void* f, int b) {
        cudaFuncSetAttribute(f, cudaFuncAttributeMaxDynamicSharedMemorySize, b);
    };
    setsm((const void*)gemm_f32a<128, 0, 1>, SM_F32A);
    setsm((const void*)gemm_f32a< 64, 2, 0>, SM_F32A);
    setsm((const void*)gemm_pk<128, 1, 1>, SM_PK);
    setsm((const void*)gemm_pk<256, 1, 1>, SM_PK);
    setsm((const void*)gemm_pk<128, 0, 0>, SM_PK);

    // ---- front: weight prep + degree histogram ----
    cudaMemsetAsync(pdegi, 0, NN * sizeof(int));
    front_kernel<<<920 + 2442, 256>>>(node_W, edge_W, W1, W2, lin_W, wpkb, eidx, pdegi);

    // ---- CSR build ----
    scan1<<<NB, 256>>>(pdegi, pbsum);
    scan2<<<1, 256>>>(pbsum, pboff, prowptr + NN);
    scan3<<<NB, 256>>>(pdegi, pboff, prowptr, pcursor, pinv);
    csr_fill<<<(EE + 255) / 256, 256>>>(eidx, pcursor, pcsrc, pceid);

    // seg[i] = sum edge_attr over incoming edges
    seg_gather<<<(NN * 16 + 255) / 256, 256>>>(prowptr, pceid, eattr, pseg);

    dim3 g2(TILES_M, 2), g4(TILES_M, 4);

    // node encoder: x(packed) = x_in @ node_W + node_b
    gemm_f32a<128, 0, 1><<<g2, 256, SM_F32A>>>(x_in, wpkb, node_b,
        nullptr, pxpk, HH, nullptr, nullptr);
    // edge agg through encoder: eam = (seg @ edge_W)*inv + [deg>0]*edge_b (fp32)
    gemm_f32a<64, 2, 0><<<g2, 256, SM_F32A>>>(pseg, wpkb + 65536, edge_b,
        peam, nullptr, HH, pinv, pdegi);

    for (int l = 0; l < 3; l++) {
        gather_combine<<<(NN * 32 + 255) / 256, 256>>>(prowptr, pcsrc, pxpk,
            peam, pinv, eps, l, pcpk);
        // h1(packed) = relu( c @ W1[l] + b1[l] )
        gemm_pk<128, 1, 1><<<g4, 256, SM_PK>>>(pcpk, wpkb + 98304 + (size_t)l * 131072,
            b1 + (size_t)l * HH2, nullptr, ph1pk, HH2);
        // x(packed) = relu( h1 @ W2[l] + b2[l] )
        gemm_pk<256, 1, 1><<<g2, 256, SM_PK>>>(ph1pk, wpkb + 491520 + (size_t)l * 131072,
            b2 + (size_t)l * HH, nullptr, pxpk, HH);
    }

    // head: out = x @ lin_W + lin_b
    gemm_pk<128, 0, 0><<<g2, 256, SM_PK>>>(pxpk, wpkb + 884736, lin_b,
        out, nullptr, OUTD);
}

// round 7
// speedup vs baseline: 1.4178x; 1.4178x over previous
#include <cuda_runtime.h>
#include <cuda_bf16.h>
#include <cstdint>

#define NN     50000
#define EE     625000
#define IN_EDGE 64
#define HH     128
#define HH2    256
#define OUTD   112
#define TILES_M 391   // ceil(50000/128)
#define NB     196    // ceil(50000/256)

// ---------------- scratch (device globals; no allocation allowed) ----------
__device__ __align__(16) float g_eam[NN * HH];
__device__ __align__(16) float g_seg[NN * IN_EDGE];
__device__ float g_inv[NN];
__device__ int   g_degi[NN];
__device__ int   g_rowptr[NN + 1];
__device__ int   g_cursor[NN];
__device__ int   g_bsum[NB];
__device__ int   g_boff[NB];
__device__ int   g_csrc[EE];
__device__ int   g_ceid[EE];

// split activations (bf16 hi/lo)
__device__ __align__(16) __nv_bfloat16 g_ch [NN * HH];    // combined, W1 input
__device__ __align__(16) __nv_bfloat16 g_cl [NN * HH];
__device__ __align__(16) __nv_bfloat16 g_h1h[NN * HH2];   // W1 output, W2 input
__device__ __align__(16) __nv_bfloat16 g_h1l[NN * HH2];
__device__ __align__(16) __nv_bfloat16 g_xh [NN * HH];    // node state (split)
__device__ __align__(16) __nv_bfloat16 g_xl [NN * HH];

// pre-split transposed weights, layout [N][K] bf16, hi/lo
__device__ __align__(16) __nv_bfloat16 g_whi[235520];
__device__ __align__(16) __nv_bfloat16 g_wlo[235520];

// ---------------------------------------------------------------------------
__device__ __forceinline__ uint32_t smem_u32(const void* p) {
    uint32_t a;
    asm("{ .reg .u64 t; cvta.to.shared.u64 t, %1; cvt.u32.u64 %0, t; }"
        : "=r"(a) : "l"(p));
    return a;
}
__device__ __forceinline__ void cp16(uint32_t dst, const void* src) {
    asm volatile("cp.async.cg.shared.global [%0], [%1], 16;"
                 :: "r"(dst), "l"(src) : "memory");
}
__device__ __forceinline__ void zero16(uint32_t dst) {
    asm volatile("st.shared.v4.b32 [%0], {%1,%1,%1,%1};" :: "r"(dst), "r"(0) : "memory");
}
__device__ __forceinline__ void ldsm4(uint32_t* r, uint32_t addr) {
    asm volatile("ldmatrix.sync.aligned.m8n8.x4.shared.b16 {%0,%1,%2,%3}, [%4];"
                 : "=r"(r[0]), "=r"(r[1]), "=r"(r[2]), "=r"(r[3]) : "r"(addr));
}
__device__ __forceinline__ void mma16816(float* d, const uint32_t* a, const uint32_t* b) {
    asm volatile("mma.sync.aligned.m16n8k16.row.col.f32.bf16.bf16.f32 "
                 "{%0,%1,%2,%3}, {%4,%5,%6,%7}, {%8,%9}, {%0,%1,%2,%3};"
                 : "+f"(d[0]), "+f"(d[1]), "+f"(d[2]), "+f"(d[3])
                 : "r"(a[0]), "r"(a[1]), "r"(a[2]), "r"(a[3]), "r"(b[0]), "r"(b[1]));
}
__device__ __forceinline__ void split2(float a, float b, uint32_t& hi, uint32_t& lo) {
    __nv_bfloat16 ha = __float2bfloat16(a), hb = __float2bfloat16(b);
    __nv_bfloat162 h = __halves2bfloat162(ha, hb);
    __nv_bfloat162 l = __halves2bfloat162(
        __float2bfloat16(a - __bfloat162float(ha)),
        __float2bfloat16(b - __bfloat162float(hb)));
    hi = *(uint32_t*)&h; lo = *(uint32_t*)&l;
}
__device__ __forceinline__ float2 unpack2(uint32_t h, uint32_t l) {
    __nv_bfloat162 hh = *(__nv_bfloat162*)&h;
    __nv_bfloat162 ll = *(__nv_bfloat162*)&l;
    return make_float2(__low2float(hh) + __low2float(ll),
                       __high2float(hh) + __high2float(ll));
}

// ---------------------------------------------------------------------------
// front: fused weight prep (split + transpose) + degree histogram
// ---------------------------------------------------------------------------
__global__ void front_kernel(const float* __restrict__ node_W, const float* __restrict__ edge_W,
                             const float* __restrict__ W1, const float* __restrict__ W2,
                             const float* __restrict__ lin_W,
                             __nv_bfloat16* __restrict__ hi, __nv_bfloat16* __restrict__ lo,
                             const int* __restrict__ ei, int* __restrict__ degi) {
    if (blockIdx.x < 920) {
        int i = blockIdx.x * 256 + threadIdx.x;
        if (i >= 235520) return;
        const float* src; int K, Nc, idx;
        if (i < 16384)       { src = node_W;                 K = 128; Nc = 128; idx = i; }
        else if (i < 24576)  { src = edge_W;                 K =  64; Nc = 128; idx = i - 16384; }
        else if (i < 122880) { int j = i - 24576;  src = W1 + (j / 32768) * 32768; K = 128; Nc = 256; idx = j % 32768; }
        else if (i < 221184) { int j = i - 122880; src = W2 + (j / 32768) * 32768; K = 256; Nc = 128; idx = j % 32768; }
        else                 { src = lin_W;                  K = 128; Nc = 112; idx = i - 221184; }
        int n = idx / K, k = idx % K;
        float v = __ldg(&src[(size_t)k * Nc + n]);
        __nv_bfloat16 h = __float2bfloat16(v);
        hi[i] = h;
        lo[i] = __float2bfloat16(v - __bfloat162float(h));
    } else {
        int e = (blockIdx.x - 920) * 256 + threadIdx.x;
        if (e < EE) atomicAdd(&degi[ei[EE + e]], 1);
    }
}

// ---------------------------------------------------------------------------
// CSR build
// ---------------------------------------------------------------------------
__global__ void scan1(const int* __restrict__ d, int* __restrict__ bsum) {
    __shared__ int s[256];
    int i = blockIdx.x * 256 + threadIdx.x;
    s[threadIdx.x] = (i < NN) ? d[i] : 0;
    __syncthreads();
    for (int o = 128; o > 0; o >>= 1) {
        if (threadIdx.x < o) s[threadIdx.x] += s[threadIdx.x + o];
        __syncthreads();
    }
    if (threadIdx.x == 0) bsum[blockIdx.x] = s[0];
}
__global__ void scan2(const int* __restrict__ bsum, int* __restrict__ boff,
                      int* __restrict__ rowptr_last) {
    __shared__ int s[256];
    int t = threadIdx.x;
    int v = (t < NB) ? bsum[t] : 0;
    s[t] = v;
    __syncthreads();
    #pragma unroll
    for (int o = 1; o < 256; o <<= 1) {
        int tv = (t >= o) ? s[t - o] : 0;
        __syncthreads();
        s[t] += tv;
        __syncthreads();
    }
    if (t < NB) boff[t] = s[t] - v;
    if (t == 255) rowptr_last[0] = s[255];
}
__global__ void scan3(const int* __restrict__ d, const int* __restrict__ boff,
                      int* __restrict__ rowptr, int* __restrict__ cursor,
                      float* __restrict__ inv) {
    __shared__ int s[256];
    int i = blockIdx.x * 256 + threadIdx.x;
    int v = (i < NN) ? d[i] : 0;
    s[threadIdx.x] = v;
    __syncthreads();
    #pragma unroll
    for (int o = 1; o < 256; o <<= 1) {
        int t = (threadIdx.x >= o) ? s[threadIdx.x - o] : 0;
        __syncthreads();
        s[threadIdx.x] += t;
        __syncthreads();
    }
    if (i < NN) {
        int excl = s[threadIdx.x] - v + boff[blockIdx.x];
        rowptr[i] = excl;
        cursor[i] = excl;
        inv[i] = 1.0f / (float)max(v, 1);
    }
}
__global__ void csr_fill(const int* __restrict__ ei, int* __restrict__ cursor,
                         int* __restrict__ csrc, int* __restrict__ ceid) {
    int e = blockIdx.x * blockDim.x + threadIdx.x;
    if (e >= EE) return;
    int dst = __ldg(&ei[EE + e]);
    int p = atomicAdd(&cursor[dst], 1);
    csrc[p] = __ldg(&ei[e]);
    ceid[p] = e;
}

// seg[i] = sum of edge_attr rows with dst=i.  16 threads per node.
__global__ void seg_gather(const int* __restrict__ rowptr, const int* __restrict__ ceid,
                           const float* __restrict__ ea, float* __restrict__ seg) {
    int g = (blockIdx.x * blockDim.x + threadIdx.x) >> 4;
    if (g >= NN) return;
    int lane = threadIdx.x & 15;
    int beg = __ldg(&rowptr[g]), end = __ldg(&rowptr[g + 1]);
    float4 acc = make_float4(0.f, 0.f, 0.f, 0.f);
    for (int j = beg; j < end; j++) {
        int e = __ldg(&ceid[j]);
        float4 v = __ldg((const float4*)(ea + (size_t)e * IN_EDGE) + lane);
        acc.x += v.x; acc.y += v.y; acc.z += v.z; acc.w += v.w;
    }
    *(float4*)(seg + (size_t)g * IN_EDGE + lane * 4) = acc;
}

// fused: agg = sum_neighbors(x) ; c = (1+eps)*x + agg*inv + eam -> ch/cl (bf16 split)
// one warp per node; lane owns 4 features.
__global__ void gather_combine(const int* __restrict__ rowptr, const int* __restrict__ csrc,
                               const __nv_bfloat16* __restrict__ xh,
                               const __nv_bfloat16* __restrict__ xl,
                               const float* __restrict__ eam, const float* __restrict__ inv,
                               const float* __restrict__ eps_p, int layer,
                               __nv_bfloat16* __restrict__ ch, __nv_bfloat16* __restrict__ cl) {
    int w = (blockIdx.x * blockDim.x + threadIdx.x) >> 5;
    if (w >= NN) return;
    int lane = threadIdx.x & 31;
    int beg = __ldg(&rowptr[w]), end = __ldg(&rowptr[w + 1]);
    float a0 = 0.f, a1 = 0.f, a2 = 0.f, a3 = 0.f;
    for (int j = beg; j < end; j++) {
        int s = __ldg(&csrc[j]);
        uint2 hv = __ldg((const uint2*)(xh + (size_t)s * HH) + lane);
        uint2 lv = __ldg((const uint2*)(xl + (size_t)s * HH) + lane);
        float2 p01 = unpack2(hv.x, lv.x);
        float2 p23 = unpack2(hv.y, lv.y);
        a0 += p01.x; a1 += p01.y; a2 += p23.x; a3 += p23.y;
    }
    float iv = __ldg(&inv[w]);
    float epsv = 1.f + __ldg(&eps_p[layer]);
    uint2 hs = __ldg((const uint2*)(xh + (size_t)w * HH) + lane);
    uint2 ls = __ldg((const uint2*)(xl + (size_t)w * HH) + lane);
    float2 x01 = unpack2(hs.x, ls.x);
    float2 x23 = unpack2(hs.y, ls.y);
    float4 em = __ldg((const float4*)(eam + (size_t)w * HH) + lane);
    float v0 = epsv * x01.x + a0 * iv + em.x;
    float v1 = epsv * x01.y + a1 * iv + em.y;
    float v2 = epsv * x23.x + a2 * iv + em.z;
    float v3 = epsv * x23.y + a3 * iv + em.w;
    uint2 h, l;
    split2(v0, v1, h.x, l.x);
    split2(v2, v3, h.y, l.y);
    *(uint2*)(ch + (size_t)w * HH + lane * 4) = h;
    *(uint2*)(cl + (size_t)w * HH + lane * 4) = l;
}

// ---------------------------------------------------------------------------
// GEMM with fp32-A conversion loader (node & edge encoders).
// EPI: 0 = +bias; 2 = *inv + [deg>0]*bias
// OUTMODE: 0 = fp32 out; 1 = bf16 split out
// ---------------------------------------------------------------------------
#define ROWB 144
template <int KTOT, int EPI, int OUTMODE>
__global__ void __launch_bounds__(256, 2)
gemm_f32a(const float* __restrict__ A,
          const __nv_bfloat16* __restrict__ Bhi, const __nv_bfloat16* __restrict__ Blo,
          const float* __restrict__ bias, float* __restrict__ Cf,
          __nv_bfloat16* __restrict__ Ch, __nv_bfloat16* __restrict__ Cl, int Nc,
          const float* __restrict__ inv, const int* __restrict__ degi) {
    extern __shared__ char smem[];
    const uint32_t sb  = smem_u32(smem);
    const uint32_t sAh = sb,          sAl = sb + 18432;
    const uint32_t sBh = sb + 36864,  sBl = sb + 46080;

    const int tid  = threadIdx.x;
    const int lane = tid & 31;
    const int wid  = tid >> 5;
    const int wm   = wid & 3;
    const int wn   = wid >> 2;
    const int rowBase = blockIdx.x * 128;
    const int colBase = blockIdx.y * 64;

    float acc[2][4][4];
    #pragma unroll
    for (int a = 0; a < 2; a++)
        #pragma unroll
        for (int b = 0; b < 4; b++)
            #pragma unroll
            for (int c = 0; c < 4; c++) acc[a][b][c] = 0.f;

    const uint32_t aRow  = (uint32_t)(lane & 15);
    const uint32_t aKoff = (uint32_t)((lane >> 4) << 3);
    const uint32_t bRow  = (uint32_t)((lane & 7) + ((lane >> 4) << 3));
    const uint32_t bKoff = (uint32_t)(((lane >> 3) & 1) << 3);

    for (int kb = 0; kb < KTOT; kb += 64) {
        if (kb) __syncthreads();
        #pragma unroll
        for (int i = 0; i < 2; i++) {
            int f = tid + i * 256;
            int nrow = f >> 3, chunk = f & 7;
            uint32_t dh = sBh + nrow * ROWB + chunk * 16;
            uint32_t dl = sBl + nrow * ROWB + chunk * 16;
            int gn = colBase + nrow;
            if (gn < Nc) {
                size_t off = (size_t)gn * KTOT + kb + chunk * 8;
                cp16(dh, Bhi + off);
                cp16(dl, Blo + off);
            } else { zero16(dh); zero16(dl); }
        }
        asm volatile("cp.async.commit_group;" ::: "memory");

        #pragma unroll
        for (int i = 0; i < 8; i++) {
            int f = tid + i * 256;
            int row = f >> 4;
            int c4  = f & 15;
            int gr = rowBase + row;
            float4 v = make_float4(0.f, 0.f, 0.f, 0.f);
            if (gr < NN) v = __ldg((const float4*)(A + (size_t)gr * KTOT + kb + c4 * 4));
            uint32_t h01, h23, l01, l23;
            split2(v.x, v.y, h01, l01);
            split2(v.z, v.w, h23, l23);
            uint32_t addr = row * ROWB + c4 * 8;
            asm volatile("st.shared.v2.b32 [%0], {%1,%2};"
                         :: "r"(sAh + addr), "r"(h01), "r"(h23) : "memory");
            asm volatile("st.shared.v2.b32 [%0], {%1,%2};"
                         :: "r"(sAl + addr), "r"(l01), "r"(l23) : "memory");
        }
        asm volatile("cp.async.wait_group 0;" ::: "memory");
        __syncthreads();

        #pragma unroll
        for (int ks = 0; ks < 4; ks++) {
            uint32_t ah[2][4], al[2][4], bh[4][2], bl[4][2];
            #pragma unroll
            for (int mi = 0; mi < 2; mi++) {
                uint32_t off = (wm * 32 + mi * 16 + aRow) * ROWB + (ks * 16 + aKoff) * 2;
                ldsm4(ah[mi], sAh + off);
                ldsm4(al[mi], sAl + off);
            }
            #pragma unroll
            for (int pr = 0; pr < 2; pr++) {
                uint32_t off = (wn * 32 + pr * 16 + bRow) * ROWB + (ks * 16 + bKoff) * 2;
                uint32_t t[4];
                ldsm4(t, sBh + off);
                bh[pr*2][0] = t[0]; bh[pr*2][1] = t[1];
                bh[pr*2+1][0] = t[2]; bh[pr*2+1][1] = t[3];
                ldsm4(t, sBl + off);
                bl[pr*2][0] = t[0]; bl[pr*2][1] = t[1];
                bl[pr*2+1][0] = t[2]; bl[pr*2+1][1] = t[3];
            }
            #pragma unroll
            for (int mi = 0; mi < 2; mi++)
                #pragma unroll
                for (int ni = 0; ni < 4; ni++) {
                    mma16816(acc[mi][ni], ah[mi], bh[ni]);
                    mma16816(acc[mi][ni], ah[mi], bl[ni]);
                    mma16816(acc[mi][ni], al[mi], bh[ni]);
                }
        }
    }

    const int group = lane >> 2;
    const int qc    = (lane & 3) * 2;
    #pragma unroll
    for (int mi = 0; mi < 2; mi++) {
        int r0 = rowBase + wm * 32 + mi * 16 + group;
        int r1 = r0 + 8;
        float iv0 = 0.f, m0 = 0.f, iv1 = 0.f, m1 = 0.f;
        if (EPI == 2) {
            if (r0 < NN) { iv0 = __ldg(&inv[r0]); m0 = (__ldg(&degi[r0]) > 0) ? 1.f : 0.f; }
            if (r1 < NN) { iv1 = __ldg(&inv[r1]); m1 = (__ldg(&degi[r1]) > 0) ? 1.f : 0.f; }
        }
        #pragma unroll
        for (int ni = 0; ni < 4; ni++) {
            int c = colBase + wn * 32 + ni * 8 + qc;
            if (c >= Nc) continue;
            float b0 = __ldg(&bias[c]), b1 = __ldg(&bias[c + 1]);
            float2 v0, v1;
            if (EPI == 2) {
                v0.x = acc[mi][ni][0] * iv0 + m0 * b0;
                v0.y = acc[mi][ni][1] * iv0 + m0 * b1;
                v1.x = acc[mi][ni][2] * iv1 + m1 * b0;
                v1.y = acc[mi][ni][3] * iv1 + m1 * b1;
            } else {
                v0.x = acc[mi][ni][0] + b0; v0.y = acc[mi][ni][1] + b1;
                v1.x = acc[mi][ni][2] + b0; v1.y = acc[mi][ni][3] + b1;
            }
            if (r0 < NN) {
                if (OUTMODE == 0) *(float2*)(Cf + (size_t)r0 * Nc + c) = v0;
                else {
                    uint32_t h, l; split2(v0.x, v0.y, h, l);
                    *(uint32_t*)(Ch + (size_t)r0 * Nc + c) = h;
                    *(uint32_t*)(Cl + (size_t)r0 * Nc + c) = l;
                }
            }
            if (r1 < NN) {
                if (OUTMODE == 0) *(float2*)(Cf + (size_t)r1 * Nc + c) = v1;
                else {
                    uint32_t h, l; split2(v1.x, v1.y, h, l);
                    *(uint32_t*)(Ch + (size_t)r1 * Nc + c) = h;
                    *(uint32_t*)(Cl + (size_t)r1 * Nc + c) = l;
                }
            }
        }
    }
}

// ---------------------------------------------------------------------------
// Pipelined split-bf16 GEMM, A pre-split.
// EPI: 0 = +bias, 1 = relu(+bias)
// OUTMODE: 0 = fp32 only; 1 = bf16 split only
// ---------------------------------------------------------------------------
template <int KTOT, int EPI, int OUTMODE>
__global__ void __launch_bounds__(256, 2)
gemm_bf16(const __nv_bfloat16* __restrict__ Ah, const __nv_bfloat16* __restrict__ Al,
          const __nv_bfloat16* __restrict__ Bhi, const __nv_bfloat16* __restrict__ Blo,
          const float* __restrict__ bias, float* __restrict__ Cf,
          __nv_bfloat16* __restrict__ Ch, __nv_bfloat16* __restrict__ Cl, int Nc) {
    constexpr int CHUNKS = KTOT / 64;
    constexpr int STG = 49152;
    extern __shared__ char smem[];
    const uint32_t sb = smem_u32(smem);

    const int tid  = threadIdx.x;
    const int lane = tid & 31;
    const int wid  = tid >> 5;
    const int wm   = wid & 3;
    const int wn   = wid >> 2;
    const int rowBase = blockIdx.x * 128;
    const int colBase = blockIdx.y * 64;

    float acc[2][4][4];
    #pragma unroll
    for (int a = 0; a < 2; a++)
        #pragma unroll
        for (int b = 0; b < 4; b++)
            #pragma unroll
            for (int c = 0; c < 4; c++) acc[a][b][c] = 0.f;

    auto load_slab = [&](int stage, int c) {
        uint32_t base = sb + stage * STG;
        int kb = c * 64;
        #pragma unroll
        for (int i = 0; i < 4; i++) {
            int f = tid + i * 256;
            int row = f >> 3, chn = f & 7;
            uint32_t sw = (uint32_t)(chn * 16) ^ (uint32_t)((row & 7) << 4);
            uint32_t da = base + row * 128 + sw;
            int gr = rowBase + row;
            if (gr < NN) {
                size_t off = (size_t)gr * KTOT + kb + chn * 8;
                cp16(da, Ah + off);
                cp16(da + 16384, Al + off);
            } else { zero16(da); zero16(da + 16384); }
        }
        #pragma unroll
        for (int i = 0; i < 2; i++) {
            int f = tid + i * 256;
            int row = f >> 3, chn = f & 7;
            uint32_t sw = (uint32_t)(chn * 16) ^ (uint32_t)((row & 7) << 4);
            uint32_t db = base + 32768 + row * 128 + sw;
            int gn = colBase + row;
            if (gn < Nc) {
                size_t off = (size_t)gn * KTOT + kb + chn * 8;
                cp16(db, Bhi + off);
                cp16(db + 8192, Blo + off);
            } else { zero16(db); zero16(db + 8192); }
        }
        asm volatile("cp.async.commit_group;" ::: "memory");
    };

    const uint32_t aRowIdx = (uint32_t)(lane & 15);
    const uint32_t aK16    = (uint32_t)((lane >> 4) << 4);
    const uint32_t bRowIdx = (uint32_t)((lane & 7) + ((lane >> 4) << 3));
    const uint32_t bK16    = (uint32_t)(((lane >> 3) & 1) << 4);

    load_slab(0, 0);

    for (int c = 0; c < CHUNKS; c++) {
        if (c + 1 < CHUNKS) {
            load_slab((c + 1) & 1, c + 1);
            asm volatile("cp.async.wait_group 1;" ::: "memory");
        } else {
            asm volatile("cp.async.wait_group 0;" ::: "memory");
        }
        __syncthreads();

        uint32_t bA = sb + (c & 1) * STG;
        uint32_t bB = bA + 32768;
        #pragma unroll
        for (int ks = 0; ks < 4; ks++) {
            uint32_t ah[2][4], al[2][4], bh[4][2], bl[4][2];
            #pragma unroll
            for (int mi = 0; mi < 2; mi++) {
                uint32_t row = wm * 32 + mi * 16 + aRowIdx;
                uint32_t cb = (uint32_t)(ks * 32) + aK16;
                uint32_t off = row * 128 + (cb ^ ((row & 7) << 4));
                ldsm4(ah[mi], bA + off);
                ldsm4(al[mi], bA + 16384 + off);
            }
            #pragma unroll
            for (int pr = 0; pr < 2; pr++) {
                uint32_t row = wn * 32 + pr * 16 + bRowIdx;
                uint32_t cb = (uint32_t)(ks * 32) + bK16;
                uint32_t off = row * 128 + (cb ^ ((row & 7) << 4));
                uint32_t t[4];
                ldsm4(t, bB + off);
                bh[pr*2][0] = t[0]; bh[pr*2][1] = t[1];
                bh[pr*2+1][0] = t[2]; bh[pr*2+1][1] = t[3];
                ldsm4(t, bB + 8192 + off);
                bl[pr*2][0] = t[0]; bl[pr*2][1] = t[1];
                bl[pr*2+1][0] = t[2]; bl[pr*2+1][1] = t[3];
            }
            #pragma unroll
            for (int mi = 0; mi < 2; mi++)
                #pragma unroll
                for (int ni = 0; ni < 4; ni++) {
                    mma16816(acc[mi][ni], ah[mi], bh[ni]);
                    mma16816(acc[mi][ni], ah[mi], bl[ni]);
                    mma16816(acc[mi][ni], al[mi], bh[ni]);
                }
        }
        if (c + 1 < CHUNKS) __syncthreads();
    }

    const int group = lane >> 2;
    const int qc    = (lane & 3) * 2;
    #pragma unroll
    for (int mi = 0; mi < 2; mi++) {
        int r0 = rowBase + wm * 32 + mi * 16 + group;
        int r1 = r0 + 8;
        #pragma unroll
        for (int ni = 0; ni < 4; ni++) {
            int c = colBase + wn * 32 + ni * 8 + qc;
            if (c >= Nc) continue;
            float b0 = __ldg(&bias[c]), b1 = __ldg(&bias[c + 1]);
            float2 v0, v1;
            v0.x = acc[mi][ni][0] + b0; v0.y = acc[mi][ni][1] + b1;
            v1.x = acc[mi][ni][2] + b0; v1.y = acc[mi][ni][3] + b1;
            if (EPI == 1) {
                v0.x = fmaxf(v0.x, 0.f); v0.y = fmaxf(v0.y, 0.f);
                v1.x = fmaxf(v1.x, 0.f); v1.y = fmaxf(v1.y, 0.f);
            }
            if (r0 < NN) {
                if (OUTMODE == 0) *(float2*)(Cf + (size_t)r0 * Nc + c) = v0;
                else {
                    uint32_t h, l; split2(v0.x, v0.y, h, l);
                    *(uint32_t*)(Ch + (size_t)r0 * Nc + c) = h;
                    *(uint32_t*)(Cl + (size_t)r0 * Nc + c) = l;
                }
            }
            if (r1 < NN) {
                if (OUTMODE == 0) *(float2*)(Cf + (size_t)r1 * Nc + c) = v1;
                else {
                    uint32_t h, l; split2(v1.x, v1.y, h, l);
                    *(uint32_t*)(Ch + (size_t)r1 * Nc + c) = h;
                    *(uint32_t*)(Cl + (size_t)r1 * Nc + c) = l;
                }
            }
        }
    }
}

// ---------------------------------------------------------------------------
extern "C" void kernel_launch(void* const* d_in, const int* in_sizes, int n_in,
                              void* d_out, int out_size) {
    const float* x_in   = (const float*)d_in[0];
    const float* eattr  = (const float*)d_in[1];
    const int*   eidx   = (const int*)  d_in[2];
    const float* node_W = (const float*)d_in[3];
    const float* node_b = (const float*)d_in[4];
    const float* edge_W = (const float*)d_in[5];
    const float* edge_b = (const float*)d_in[6];
    const float* W1     = (const float*)d_in[7];
    const float* b1     = (const float*)d_in[8];
    const float* W2     = (const float*)d_in[9];
    const float* b2     = (const float*)d_in[10];
    const float* eps    = (const float*)d_in[11];
    const float* lin_W  = (const float*)d_in[12];
    const float* lin_b  = (const float*)d_in[13];
    float* out = (float*)d_out;

    float *peam, *pseg, *pinv;
    int *pdegi, *prowptr, *pcursor, *pbsum, *pboff, *pcsrc, *pceid;
    __nv_bfloat16 *pwh, *pwl, *pch, *pcl, *ph1h, *ph1l, *pxh, *pxl;
    cudaGetSymbolAddress((void**)&peam, g_eam);
    cudaGetSymbolAddress((void**)&pseg, g_seg);
    cudaGetSymbolAddress((void**)&pinv, g_inv);
    cudaGetSymbolAddress((void**)&pdegi, g_degi);
    cudaGetSymbolAddress((void**)&prowptr, g_rowptr);
    cudaGetSymbolAddress((void**)&pcursor, g_cursor);
    cudaGetSymbolAddress((void**)&pbsum, g_bsum);
    cudaGetSymbolAddress((void**)&pboff, g_boff);
    cudaGetSymbolAddress((void**)&pcsrc, g_csrc);
    cudaGetSymbolAddress((void**)&pceid, g_ceid);
    cudaGetSymbolAddress((void**)&pwh,  g_whi);
    cudaGetSymbolAddress((void**)&pwl,  g_wlo);
    cudaGetSymbolAddress((void**)&pch,  g_ch);
    cudaGetSymbolAddress((void**)&pcl,  g_cl);
    cudaGetSymbolAddress((void**)&ph1h, g_h1h);
    cudaGetSymbolAddress((void**)&ph1l, g_h1l);
    cudaGetSymbolAddress((void**)&pxh,  g_xh);
    cudaGetSymbolAddress((void**)&pxl,  g_xl);

    constexpr int SM_F32A = 55296;
    constexpr int SM_BF16 = 98304;
    auto setsm = [](const void* f, int b) {
        cudaFuncSetAttribute(f, cudaFuncAttributeMaxDynamicSharedMemorySize, b);
    };
    setsm((const void*)gemm_f32a<128, 0, 1>, SM_F32A);
    setsm((const void*)gemm_f32a< 64, 2, 0>, SM_F32A);
    setsm((const void*)gemm_bf16<128, 1, 1>, SM_BF16);
    setsm((const void*)gemm_bf16<256, 1, 1>, SM_BF16);
    setsm((const void*)gemm_bf16<128, 0, 0>, SM_BF16);

    // ---- front: weight prep + degree histogram (fused) ----
    cudaMemsetAsync(pdegi, 0, NN * sizeof(int));
    front_kernel<<<920 + 2442, 256>>>(node_W, edge_W, W1, W2, lin_W, pwh, pwl,
                                      eidx, pdegi);

    // ---- CSR build ----
    scan1<<<NB, 256>>>(pdegi, pbsum);
    scan2<<<1, 256>>>(pbsum, pboff, prowptr + NN);
    scan3<<<NB, 256>>>(pdegi, pboff, prowptr, pcursor, pinv);
    csr_fill<<<(EE + 255) / 256, 256>>>(eidx, pcursor, pcsrc, pceid);

    // seg[i] = sum edge_attr over incoming edges
    seg_gather<<<(NN * 16 + 255) / 256, 256>>>(prowptr, pceid, eattr, pseg);

    dim3 g2(TILES_M, 2), g4(TILES_M, 4);

    // node encoder: x(split) = x_in @ node_W + node_b
    gemm_f32a<128, 0, 1><<<g2, 256, SM_F32A>>>(x_in, pwh, pwl, node_b,
        nullptr, pxh, pxl, HH, nullptr, nullptr);
    // edge agg through encoder: eam = (seg @ edge_W)*inv + [deg>0]*edge_b (fp32)
    gemm_f32a<64, 2, 0><<<g2, 256, SM_F32A>>>(pseg, pwh + 16384, pwl + 16384,
        edge_b, peam, nullptr, nullptr, HH, pinv, pdegi);

    for (int l = 0; l < 3; l++) {
        gather_combine<<<(NN * 32 + 255) / 256, 256>>>(prowptr, pcsrc, pxh, pxl,
            peam, pinv, eps, l, pch, pcl);
        // h1(split) = relu( c @ W1[l] + b1[l] )
        gemm_bf16<128, 1, 1><<<g4, 256, SM_BF16>>>(pch, pcl,
            pwh + 24576 + l * 32768, pwl + 24576 + l * 32768,
            b1 + (size_t)l * HH2, nullptr, ph1h, ph1l, HH2);
        // x(split) = relu( h1 @ W2[l] + b2[l] )
        gemm_bf16<256, 1, 1><<<g2, 256, SM_BF16>>>(ph1h, ph1l,
            pwh + 122880 + l * 32768, pwl + 122880 + l * 32768,
            b2 + (size_t)l * HH, nullptr, pxh, pxl, HH);
    }

    // head: out = x @ lin_W + lin_b
    gemm_bf16<128, 0, 0><<<g2, 256, SM_BF16>>>(pxh, pxl, pwh + 221184, pwl + 221184,
        lin_b, out, nullptr, nullptr, OUTD);
}

// round 8
// speedup vs baseline: 1.5629x; 1.1024x over previous
#include <cuda_runtime.h>
#include <cuda_fp16.h>
#include <cstdint>

#define NN     50000
#define EE     625000
#define IN_EDGE 64
#define HH     128
#define HH2    256
#define OUTD   112
#define TILES_M 391   // ceil(50000/128)
#define NB     196    // ceil(50000/256)

// ---------------- scratch (device globals; no allocation allowed) ----------
__device__ __align__(16) float g_eam[NN * HH];
__device__ __align__(16) float g_seg[NN * IN_EDGE];
__device__ float g_inv[NN];
__device__ int   g_degi[NN];
__device__ int   g_rowptr[NN + 1];
__device__ int   g_cursor[NN];
__device__ int   g_bsum[NB];
__device__ int   g_boff[NB];
__device__ int   g_csrc[EE];
__device__ int   g_ceid[EE];

// split activations (fp16 hi/lo; hi+lo reconstructs ~22-bit mantissa)
__device__ __align__(16) __half g_ch [NN * HH];    // combined, W1 input
__device__ __align__(16) __half g_cl [NN * HH];
__device__ __align__(16) __half g_h1h[NN * HH2];   // W1 output, W2 input
__device__ __align__(16) __half g_h1l[NN * HH2];
__device__ __align__(16) __half g_xh [NN * HH];    // node state (split)
__device__ __align__(16) __half g_xl [NN * HH];

// pre-rounded transposed weights, layout [N][K] fp16 (hi only; B-side single)
__device__ __align__(16) __half g_whi[235520];

// ---------------------------------------------------------------------------
__device__ __forceinline__ uint32_t smem_u32(const void* p) {
    uint32_t a;
    asm("{ .reg .u64 t; cvta.to.shared.u64 t, %1; cvt.u32.u64 %0, t; }"
        : "=r"(a) : "l"(p));
    return a;
}
__device__ __forceinline__ void cp16(uint32_t dst, const void* src) {
    asm volatile("cp.async.cg.shared.global [%0], [%1], 16;"
                 :: "r"(dst), "l"(src) : "memory");
}
__device__ __forceinline__ void zero16(uint32_t dst) {
    asm volatile("st.shared.v4.b32 [%0], {%1,%1,%1,%1};" :: "r"(dst), "r"(0) : "memory");
}
__device__ __forceinline__ void ldsm4(uint32_t* r, uint32_t addr) {
    asm volatile("ldmatrix.sync.aligned.m8n8.x4.shared.b16 {%0,%1,%2,%3}, [%4];"
                 : "=r"(r[0]), "=r"(r[1]), "=r"(r[2]), "=r"(r[3]) : "r"(addr));
}
__device__ __forceinline__ void mma16816(float* d, const uint32_t* a, const uint32_t* b) {
    asm volatile("mma.sync.aligned.m16n8k16.row.col.f32.f16.f16.f32 "
                 "{%0,%1,%2,%3}, {%4,%5,%6,%7}, {%8,%9}, {%0,%1,%2,%3};"
                 : "+f"(d[0]), "+f"(d[1]), "+f"(d[2]), "+f"(d[3])
                 : "r"(a[0]), "r"(a[1]), "r"(a[2]), "r"(a[3]), "r"(b[0]), "r"(b[1]));
}
__device__ __forceinline__ void split2(float a, float b, uint32_t& hi, uint32_t& lo) {
    __half ha = __float2half(a), hb = __float2half(b);
    __half2 h = __halves2half2(ha, hb);
    __half2 l = __halves2half2(
        __float2half(a - __half2float(ha)),
        __float2half(b - __half2float(hb)));
    hi = *(uint32_t*)&h; lo = *(uint32_t*)&l;
}
__device__ __forceinline__ float2 unpack2(uint32_t h, uint32_t l) {
    __half2 hh = *(__half2*)&h;
    __half2 ll = *(__half2*)&l;
    return make_float2(__low2float(hh) + __low2float(ll),
                       __high2float(hh) + __high2float(ll));
}

// ---------------------------------------------------------------------------
// front: fused weight prep (fp16 round + transpose) + degree histogram
// ---------------------------------------------------------------------------
__global__ void front_kernel(const float* __restrict__ node_W, const float* __restrict__ edge_W,
                             const float* __restrict__ W1, const float* __restrict__ W2,
                             const float* __restrict__ lin_W,
                             __half* __restrict__ hi,
                             const int* __restrict__ ei, int* __restrict__ degi) {
    if (blockIdx.x < 920) {
        int i = blockIdx.x * 256 + threadIdx.x;
        if (i >= 235520) return;
        const float* src; int K, Nc, idx;
        if (i < 16384)       { src = node_W;                 K = 128; Nc = 128; idx = i; }
        else if (i < 24576)  { src = edge_W;                 K =  64; Nc = 128; idx = i - 16384; }
        else if (i < 122880) { int j = i - 24576;  src = W1 + (j / 32768) * 32768; K = 128; Nc = 256; idx = j % 32768; }
        else if (i < 221184) { int j = i - 122880; src = W2 + (j / 32768) * 32768; K = 256; Nc = 128; idx = j % 32768; }
        else                 { src = lin_W;                  K = 128; Nc = 112; idx = i - 221184; }
        int n = idx / K, k = idx % K;
        float v = __ldg(&src[(size_t)k * Nc + n]);
        hi[i] = __float2half(v);
    } else {
        int e = (blockIdx.x - 920) * 256 + threadIdx.x;
        if (e < EE) atomicAdd(&degi[ei[EE + e]], 1);
    }
}

// ---------------------------------------------------------------------------
// CSR build
// ---------------------------------------------------------------------------
__global__ void scan1(const int* __restrict__ d, int* __restrict__ bsum) {
    __shared__ int s[256];
    int i = blockIdx.x * 256 + threadIdx.x;
    s[threadIdx.x] = (i < NN) ? d[i] : 0;
    __syncthreads();
    for (int o = 128; o > 0; o >>= 1) {
        if (threadIdx.x < o) s[threadIdx.x] += s[threadIdx.x + o];
        __syncthreads();
    }
    if (threadIdx.x == 0) bsum[blockIdx.x] = s[0];
}
__global__ void scan2(const int* __restrict__ bsum, int* __restrict__ boff,
                      int* __restrict__ rowptr_last) {
    __shared__ int s[256];
    int t = threadIdx.x;
    int v = (t < NB) ? bsum[t] : 0;
    s[t] = v;
    __syncthreads();
    #pragma unroll
    for (int o = 1; o < 256; o <<= 1) {
        int tv = (t >= o) ? s[t - o] : 0;
        __syncthreads();
        s[t] += tv;
        __syncthreads();
    }
    if (t < NB) boff[t] = s[t] - v;
    if (t == 255) rowptr_last[0] = s[255];
}
__global__ void scan3(const int* __restrict__ d, const int* __restrict__ boff,
                      int* __restrict__ rowptr, int* __restrict__ cursor,
                      float* __restrict__ inv) {
    __shared__ int s[256];
    int i = blockIdx.x * 256 + threadIdx.x;
    int v = (i < NN) ? d[i] : 0;
    s[threadIdx.x] = v;
    __syncthreads();
    #pragma unroll
    for (int o = 1; o < 256; o <<= 1) {
        int t = (threadIdx.x >= o) ? s[threadIdx.x - o] : 0;
        __syncthreads();
        s[threadIdx.x] += t;
        __syncthreads();
    }
    if (i < NN) {
        int excl = s[threadIdx.x] - v + boff[blockIdx.x];
        rowptr[i] = excl;
        cursor[i] = excl;
        inv[i] = 1.0f / (float)max(v, 1);
    }
}
__global__ void csr_fill(const int* __restrict__ ei, int* __restrict__ cursor,
                         int* __restrict__ csrc, int* __restrict__ ceid) {
    int e = blockIdx.x * blockDim.x + threadIdx.x;
    if (e >= EE) return;
    int dst = __ldg(&ei[EE + e]);
    int p = atomicAdd(&cursor[dst], 1);
    csrc[p] = __ldg(&ei[e]);
    ceid[p] = e;
}

// seg[i] = sum of edge_attr rows with dst=i.  16 threads per node.
__global__ void seg_gather(const int* __restrict__ rowptr, const int* __restrict__ ceid,
                           const float* __restrict__ ea, float* __restrict__ seg) {
    int g = (blockIdx.x * blockDim.x + threadIdx.x) >> 4;
    if (g >= NN) return;
    int lane = threadIdx.x & 15;
    int beg = __ldg(&rowptr[g]), end = __ldg(&rowptr[g + 1]);
    float4 acc = make_float4(0.f, 0.f, 0.f, 0.f);
    for (int j = beg; j < end; j++) {
        int e = __ldg(&ceid[j]);
        float4 v = __ldg((const float4*)(ea + (size_t)e * IN_EDGE) + lane);
        acc.x += v.x; acc.y += v.y; acc.z += v.z; acc.w += v.w;
    }
    *(float4*)(seg + (size_t)g * IN_EDGE + lane * 4) = acc;
}

// fused: agg = sum_neighbors(x) ; c = (1+eps)*x + agg*inv + eam -> ch/cl (fp16 split)
// one warp per node; lane owns 4 features.
__global__ void gather_combine(const int* __restrict__ rowptr, const int* __restrict__ csrc,
                               const __half* __restrict__ xh,
                               const __half* __restrict__ xl,
                               const float* __restrict__ eam, const float* __restrict__ inv,
                               const float* __restrict__ eps_p, int layer,
                               __half* __restrict__ ch, __half* __restrict__ cl) {
    int w = (blockIdx.x * blockDim.x + threadIdx.x) >> 5;
    if (w >= NN) return;
    int lane = threadIdx.x & 31;
    int beg = __ldg(&rowptr[w]), end = __ldg(&rowptr[w + 1]);
    float a0 = 0.f, a1 = 0.f, a2 = 0.f, a3 = 0.f;
    for (int j = beg; j < end; j++) {
        int s = __ldg(&csrc[j]);
        uint2 hv = __ldg((const uint2*)(xh + (size_t)s * HH) + lane);
        uint2 lv = __ldg((const uint2*)(xl + (size_t)s * HH) + lane);
        float2 p01 = unpack2(hv.x, lv.x);
        float2 p23 = unpack2(hv.y, lv.y);
        a0 += p01.x; a1 += p01.y; a2 += p23.x; a3 += p23.y;
    }
    float iv = __ldg(&inv[w]);
    float epsv = 1.f + __ldg(&eps_p[layer]);
    uint2 hs = __ldg((const uint2*)(xh + (size_t)w * HH) + lane);
    uint2 ls = __ldg((const uint2*)(xl + (size_t)w * HH) + lane);
    float2 x01 = unpack2(hs.x, ls.x);
    float2 x23 = unpack2(hs.y, ls.y);
    float4 em = __ldg((const float4*)(eam + (size_t)w * HH) + lane);
    float v0 = epsv * x01.x + a0 * iv + em.x;
    float v1 = epsv * x01.y + a1 * iv + em.y;
    float v2 = epsv * x23.x + a2 * iv + em.z;
    float v3 = epsv * x23.y + a3 * iv + em.w;
    uint2 h, l;
    split2(v0, v1, h.x, l.x);
    split2(v2, v3, h.y, l.y);
    *(uint2*)(ch + (size_t)w * HH + lane * 4) = h;
    *(uint2*)(cl + (size_t)w * HH + lane * 4) = l;
}

// ---------------------------------------------------------------------------
// GEMM with fp32-A conversion loader (node & edge encoders). B = fp16 hi only.
// D = (Ah+Al) @ Bh   (2 MMA products)
// EPI: 0 = +bias; 2 = *inv + [deg>0]*bias.  OUTMODE: 0 fp32; 1 fp16 split.
// ---------------------------------------------------------------------------
#define ROWB 144
template <int KTOT, int EPI, int OUTMODE>
__global__ void __launch_bounds__(256, 2)
gemm_f32a(const float* __restrict__ A, const __half* __restrict__ Bhi,
          const float* __restrict__ bias, float* __restrict__ Cf,
          __half* __restrict__ Ch, __half* __restrict__ Cl, int Nc,
          const float* __restrict__ inv, const int* __restrict__ degi) {
    extern __shared__ char smem[];
    const uint32_t sb  = smem_u32(smem);
    const uint32_t sAh = sb, sAl = sb + 18432, sBh = sb + 36864;

    const int tid  = threadIdx.x;
    const int lane = tid & 31;
    const int wid  = tid >> 5;
    const int wm   = wid & 3;
    const int wn   = wid >> 2;
    const int rowBase = blockIdx.x * 128;
    const int colBase = blockIdx.y * 64;

    float acc[2][4][4];
    #pragma unroll
    for (int a = 0; a < 2; a++)
        #pragma unroll
        for (int b = 0; b < 4; b++)
            #pragma unroll
            for (int c = 0; c < 4; c++) acc[a][b][c] = 0.f;

    const uint32_t aRow  = (uint32_t)(lane & 15);
    const uint32_t aKoff = (uint32_t)((lane >> 4) << 3);
    const uint32_t bRow  = (uint32_t)((lane & 7) + ((lane >> 4) << 3));
    const uint32_t bKoff = (uint32_t)(((lane >> 3) & 1) << 3);

    for (int kb = 0; kb < KTOT; kb += 64) {
        if (kb) __syncthreads();
        #pragma unroll
        for (int i = 0; i < 2; i++) {
            int f = tid + i * 256;
            int nrow = f >> 3, chunk = f & 7;
            uint32_t dh = sBh + nrow * ROWB + chunk * 16;
            int gn = colBase + nrow;
            if (gn < Nc) cp16(dh, Bhi + (size_t)gn * KTOT + kb + chunk * 8);
            else         zero16(dh);
        }
        asm volatile("cp.async.commit_group;" ::: "memory");

        #pragma unroll
        for (int i = 0; i < 8; i++) {
            int f = tid + i * 256;
            int row = f >> 4;
            int c4  = f & 15;
            int gr = rowBase + row;
            float4 v = make_float4(0.f, 0.f, 0.f, 0.f);
            if (gr < NN) v = __ldg((const float4*)(A + (size_t)gr * KTOT + kb + c4 * 4));
            uint32_t h01, h23, l01, l23;
            split2(v.x, v.y, h01, l01);
            split2(v.z, v.w, h23, l23);
            uint32_t addr = row * ROWB + c4 * 8;
            asm volatile("st.shared.v2.b32 [%0], {%1,%2};"
                         :: "r"(sAh + addr), "r"(h01), "r"(h23) : "memory");
            asm volatile("st.shared.v2.b32 [%0], {%1,%2};"
                         :: "r"(sAl + addr), "r"(l01), "r"(l23) : "memory");
        }
        asm volatile("cp.async.wait_group 0;" ::: "memory");
        __syncthreads();

        #pragma unroll
        for (int ks = 0; ks < 4; ks++) {
            uint32_t ah[2][4], al[2][4], bh[4][2];
            #pragma unroll
            for (int mi = 0; mi < 2; mi++) {
                uint32_t off = (wm * 32 + mi * 16 + aRow) * ROWB + (ks * 16 + aKoff) * 2;
                ldsm4(ah[mi], sAh + off);
                ldsm4(al[mi], sAl + off);
            }
            #pragma unroll
            for (int pr = 0; pr < 2; pr++) {
                uint32_t off = (wn * 32 + pr * 16 + bRow) * ROWB + (ks * 16 + bKoff) * 2;
                uint32_t t[4];
                ldsm4(t, sBh + off);
                bh[pr*2][0] = t[0]; bh[pr*2][1] = t[1];
                bh[pr*2+1][0] = t[2]; bh[pr*2+1][1] = t[3];
            }
            #pragma unroll
            for (int mi = 0; mi < 2; mi++)
                #pragma unroll
                for (int ni = 0; ni < 4; ni++) {
                    mma16816(acc[mi][ni], ah[mi], bh[ni]);
                    mma16816(acc[mi][ni], al[mi], bh[ni]);
                }
        }
    }

    const int group = lane >> 2;
    const int qc    = (lane & 3) * 2;
    #pragma unroll
    for (int mi = 0; mi < 2; mi++) {
        int r0 = rowBase + wm * 32 + mi * 16 + group;
        int r1 = r0 + 8;
        float iv0 = 0.f, m0 = 0.f, iv1 = 0.f, m1 = 0.f;
        if (EPI == 2) {
            if (r0 < NN) { iv0 = __ldg(&inv[r0]); m0 = (__ldg(&degi[r0]) > 0) ? 1.f : 0.f; }
            if (r1 < NN) { iv1 = __ldg(&inv[r1]); m1 = (__ldg(&degi[r1]) > 0) ? 1.f : 0.f; }
        }
        #pragma unroll
        for (int ni = 0; ni < 4; ni++) {
            int c = colBase + wn * 32 + ni * 8 + qc;
            if (c >= Nc) continue;
            float b0 = __ldg(&bias[c]), b1 = __ldg(&bias[c + 1]);
            float2 v0, v1;
            if (EPI == 2) {
                v0.x = acc[mi][ni][0] * iv0 + m0 * b0;
                v0.y = acc[mi][ni][1] * iv0 + m0 * b1;
                v1.x = acc[mi][ni][2] * iv1 + m1 * b0;
                v1.y = acc[mi][ni][3] * iv1 + m1 * b1;
            } else {
                v0.x = acc[mi][ni][0] + b0; v0.y = acc[mi][ni][1] + b1;
                v1.x = acc[mi][ni][2] + b0; v1.y = acc[mi][ni][3] + b1;
            }
            if (r0 < NN) {
                if (OUTMODE == 0) *(float2*)(Cf + (size_t)r0 * Nc + c) = v0;
                else {
                    uint32_t h, l; split2(v0.x, v0.y, h, l);
                    *(uint32_t*)(Ch + (size_t)r0 * Nc + c) = h;
                    *(uint32_t*)(Cl + (size_t)r0 * Nc + c) = l;
                }
            }
            if (r1 < NN) {
                if (OUTMODE == 0) *(float2*)(Cf + (size_t)r1 * Nc + c) = v1;
                else {
                    uint32_t h, l; split2(v1.x, v1.y, h, l);
                    *(uint32_t*)(Ch + (size_t)r1 * Nc + c) = h;
                    *(uint32_t*)(Cl + (size_t)r1 * Nc + c) = l;
                }
            }
        }
    }
}

// ---------------------------------------------------------------------------
// Pipelined fp16 GEMM, A pre-split (hi/lo), B fp16 hi only: D = (Ah+Al)@Bh.
// EPI: 0 = +bias, 1 = relu(+bias);  OUTMODE: 0 fp32; 1 fp16 split
// ---------------------------------------------------------------------------
template <int KTOT, int EPI, int OUTMODE>
__global__ void __launch_bounds__(256, 2)
gemm_hf(const __half* __restrict__ Ah, const __half* __restrict__ Al,
        const __half* __restrict__ Bhi,
        const float* __restrict__ bias, float* __restrict__ Cf,
        __half* __restrict__ Ch, __half* __restrict__ Cl, int Nc) {
    constexpr int CHUNKS = KTOT / 64;
    constexpr int STG = 40960;   // Ah 16K | Al 16K | Bh 8K
    extern __shared__ char smem[];
    const uint32_t sb = smem_u32(smem);

    const int tid  = threadIdx.x;
    const int lane = tid & 31;
    const int wid  = tid >> 5;
    const int wm   = wid & 3;
    const int wn   = wid >> 2;
    const int rowBase = blockIdx.x * 128;
    const int colBase = blockIdx.y * 64;

    float acc[2][4][4];
    #pragma unroll
    for (int a = 0; a < 2; a++)
        #pragma unroll
        for (int b = 0; b < 4; b++)
            #pragma unroll
            for (int c = 0; c < 4; c++) acc[a][b][c] = 0.f;

    auto load_slab = [&](int stage, int c) {
        uint32_t base = sb + stage * STG;
        int kb = c * 64;
        #pragma unroll
        for (int i = 0; i < 4; i++) {
            int f = tid + i * 256;
            int row = f >> 3, chn = f & 7;
            uint32_t sw = (uint32_t)(chn * 16) ^ (uint32_t)((row & 7) << 4);
            uint32_t da = base + row * 128 + sw;
            int gr = rowBase + row;
            if (gr < NN) {
                size_t off = (size_t)gr * KTOT + kb + chn * 8;
                cp16(da, Ah + off);
                cp16(da + 16384, Al + off);
            } else { zero16(da); zero16(da + 16384); }
        }
        #pragma unroll
        for (int i = 0; i < 2; i++) {
            int f = tid + i * 256;
            int row = f >> 3, chn = f & 7;
            uint32_t sw = (uint32_t)(chn * 16) ^ (uint32_t)((row & 7) << 4);
            uint32_t db = base + 32768 + row * 128 + sw;
            int gn = colBase + row;
            if (gn < Nc) cp16(db, Bhi + (size_t)gn * KTOT + kb + chn * 8);
            else         zero16(db);
        }
        asm volatile("cp.async.commit_group;" ::: "memory");
    };

    const uint32_t aRowIdx = (uint32_t)(lane & 15);
    const uint32_t aK16    = (uint32_t)((lane >> 4) << 4);
    const uint32_t bRowIdx = (uint32_t)((lane & 7) + ((lane >> 4) << 3));
    const uint32_t bK16    = (uint32_t)(((lane >> 3) & 1) << 4);

    load_slab(0, 0);

    for (int c = 0; c < CHUNKS; c++) {
        if (c + 1 < CHUNKS) {
            load_slab((c + 1) & 1, c + 1);
            asm volatile("cp.async.wait_group 1;" ::: "memory");
        } else {
            asm volatile("cp.async.wait_group 0;" ::: "memory");
        }
        __syncthreads();

        uint32_t bA = sb + (c & 1) * STG;
        uint32_t bB = bA + 32768;
        #pragma unroll
        for (int ks = 0; ks < 4; ks++) {
            uint32_t ah[2][4], al[2][4], bh[4][2];
            #pragma unroll
            for (int mi = 0; mi < 2; mi++) {
                uint32_t row = wm * 32 + mi * 16 + aRowIdx;
                uint32_t cb = (uint32_t)(ks * 32) + aK16;
                uint32_t off = row * 128 + (cb ^ ((row & 7) << 4));
                ldsm4(ah[mi], bA + off);
                ldsm4(al[mi], bA + 16384 + off);
            }
            #pragma unroll
            for (int pr = 0; pr < 2; pr++) {
                uint32_t row = wn * 32 + pr * 16 + bRowIdx;
                uint32_t cb = (uint32_t)(ks * 32) + bK16;
                uint32_t off = row * 128 + (cb ^ ((row & 7) << 4));
                uint32_t t[4];
                ldsm4(t, bB + off);
                bh[pr*2][0] = t[0]; bh[pr*2][1] = t[1];
                bh[pr*2+1][0] = t[2]; bh[pr*2+1][1] = t[3];
            }
            #pragma unroll
            for (int mi = 0; mi < 2; mi++)
                #pragma unroll
                for (int ni = 0; ni < 4; ni++) {
                    mma16816(acc[mi][ni], ah[mi], bh[ni]);
                    mma16816(acc[mi][ni], al[mi], bh[ni]);
                }
        }
        if (c + 1 < CHUNKS) __syncthreads();
    }

    const int group = lane >> 2;
    const int qc    = (lane & 3) * 2;
    #pragma unroll
    for (int mi = 0; mi < 2; mi++) {
        int r0 = rowBase + wm * 32 + mi * 16 + group;
        int r1 = r0 + 8;
        #pragma unroll
        for (int ni = 0; ni < 4; ni++) {
            int c = colBase + wn * 32 + ni * 8 + qc;
            if (c >= Nc) continue;
            float b0 = __ldg(&bias[c]), b1 = __ldg(&bias[c + 1]);
            float2 v0, v1;
            v0.x = acc[mi][ni][0] + b0; v0.y = acc[mi][ni][1] + b1;
            v1.x = acc[mi][ni][2] + b0; v1.y = acc[mi][ni][3] + b1;
            if (EPI == 1) {
                v0.x = fmaxf(v0.x, 0.f); v0.y = fmaxf(v0.y, 0.f);
                v1.x = fmaxf(v1.x, 0.f); v1.y = fmaxf(v1.y, 0.f);
            }
            if (r0 < NN) {
                if (OUTMODE == 0) *(float2*)(Cf + (size_t)r0 * Nc + c) = v0;
                else {
                    uint32_t h, l; split2(v0.x, v0.y, h, l);
                    *(uint32_t*)(Ch + (size_t)r0 * Nc + c) = h;
                    *(uint32_t*)(Cl + (size_t)r0 * Nc + c) = l;
                }
            }
            if (r1 < NN) {
                if (OUTMODE == 0) *(float2*)(Cf + (size_t)r1 * Nc + c) = v1;
                else {
                    uint32_t h, l; split2(v1.x, v1.y, h, l);
                    *(uint32_t*)(Ch + (size_t)r1 * Nc + c) = h;
                    *(uint32_t*)(Cl + (size_t)r1 * Nc + c) = l;
                }
            }
        }
    }
}

// ---------------------------------------------------------------------------
extern "C" void kernel_launch(void* const* d_in, const int* in_sizes, int n_in,
                              void* d_out, int out_size) {
    const float* x_in   = (const float*)d_in[0];
    const float* eattr  = (const float*)d_in[1];
    const int*   eidx   = (const int*)  d_in[2];
    const float* node_W = (const float*)d_in[3];
    const float* node_b = (const float*)d_in[4];
    const float* edge_W = (const float*)d_in[5];
    const float* edge_b = (const float*)d_in[6];
    const float* W1     = (const float*)d_in[7];
    const float* b1     = (const float*)d_in[8];
    const float* W2     = (const float*)d_in[9];
    const float* b2     = (const float*)d_in[10];
    const float* eps    = (const float*)d_in[11];
    const float* lin_W  = (const float*)d_in[12];
    const float* lin_b  = (const float*)d_in[13];
    float* out = (float*)d_out;

    float *peam, *pseg, *pinv;
    int *pdegi, *prowptr, *pcursor, *pbsum, *pboff, *pcsrc, *pceid;
    __half *pwh, *pch, *pcl, *ph1h, *ph1l, *pxh, *pxl;
    cudaGetSymbolAddress((void**)&peam, g_eam);
    cudaGetSymbolAddress((void**)&pseg, g_seg);
    cudaGetSymbolAddress((void**)&pinv, g_inv);
    cudaGetSymbolAddress((void**)&pdegi, g_degi);
    cudaGetSymbolAddress((void**)&prowptr, g_rowptr);
    cudaGetSymbolAddress((void**)&pcursor, g_cursor);
    cudaGetSymbolAddress((void**)&pbsum, g_bsum);
    cudaGetSymbolAddress((void**)&pboff, g_boff);
    cudaGetSymbolAddress((void**)&pcsrc, g_csrc);
    cudaGetSymbolAddress((void**)&pceid, g_ceid);
    cudaGetSymbolAddress((void**)&pwh,  g_whi);
    cudaGetSymbolAddress((void**)&pch,  g_ch);
    cudaGetSymbolAddress((void**)&pcl,  g_cl);
    cudaGetSymbolAddress((void**)&ph1h, g_h1h);
    cudaGetSymbolAddress((void**)&ph1l, g_h1l);
    cudaGetSymbolAddress((void**)&pxh,  g_xh);
    cudaGetSymbolAddress((void**)&pxl,  g_xl);

    constexpr int SM_F32A = 46080;
    constexpr int SM_HF   = 81920;
    auto setsm = [](const void* f, int b) {
        cudaFuncSetAttribute(f, cudaFuncAttributeMaxDynamicSharedMemorySize, b);
    };
    setsm((const void*)gemm_f32a<128, 0, 1>, SM_F32A);
    setsm((const void*)gemm_f32a< 64, 2, 0>, SM_F32A);
    setsm((const void*)gemm_hf<128, 1, 1>, SM_HF);
    setsm((const void*)gemm_hf<256, 1, 1>, SM_HF);
    setsm((const void*)gemm_hf<128, 0, 0>, SM_HF);

    // ---- front: weight prep + degree histogram (fused) ----
    cudaMemsetAsync(pdegi, 0, NN * sizeof(int));
    front_kernel<<<920 + 2442, 256>>>(node_W, edge_W, W1, W2, lin_W, pwh,
                                      eidx, pdegi);

    // ---- CSR build ----
    scan1<<<NB, 256>>>(pdegi, pbsum);
    scan2<<<1, 256>>>(pbsum, pboff, prowptr + NN);
    scan3<<<NB, 256>>>(pdegi, pboff, prowptr, pcursor, pinv);
    csr_fill<<<(EE + 255) / 256, 256>>>(eidx, pcursor, pcsrc, pceid);

    // seg[i] = sum edge_attr over incoming edges
    seg_gather<<<(NN * 16 + 255) / 256, 256>>>(prowptr, pceid, eattr, pseg);

    dim3 g2(TILES_M, 2), g4(TILES_M, 4);

    // node encoder: x(split) = x_in @ node_W + node_b
    gemm_f32a<128, 0, 1><<<g2, 256, SM_F32A>>>(x_in, pwh, node_b,
        nullptr, pxh, pxl, HH, nullptr, nullptr);
    // edge agg through encoder: eam = (seg @ edge_W)*inv + [deg>0]*edge_b (fp32)
    gemm_f32a<64, 2, 0><<<g2, 256, SM_F32A>>>(pseg, pwh + 16384, edge_b,
        peam, nullptr, nullptr, HH, pinv, pdegi);

    for (int l = 0; l < 3; l++) {
        gather_combine<<<(NN * 32 + 255) / 256, 256>>>(prowptr, pcsrc, pxh, pxl,
            peam, pinv, eps, l, pch, pcl);
        // h1(split) = relu( c @ W1[l] + b1[l] )
        gemm_hf<128, 1, 1><<<g4, 256, SM_HF>>>(pch, pcl,
            pwh + 24576 + l * 32768,
            b1 + (size_t)l * HH2, nullptr, ph1h, ph1l, HH2);
        // x(split) = relu( h1 @ W2[l] + b2[l] )
        gemm_hf<256, 1, 1><<<g2, 256, SM_HF>>>(ph1h, ph1l,
            pwh + 122880 + l * 32768,
            b2 + (size_t)l * HH, nullptr, pxh, pxl, HH);
    }

    // head: out = x @ lin_W + lin_b
    gemm_hf<128, 0, 0><<<g2, 256, SM_HF>>>(pxh, pxl, pwh + 221184,
        lin_b, out, nullptr, nullptr, OUTD);
}

// round 9
// speedup vs baseline: 1.6275x; 1.0413x over previous
#include <cuda_runtime.h>
#include <cuda_fp16.h>
#include <cstdint>

#define NN     50000
#define EE     625000
#define IN_EDGE 64
#define HH     128
#define HH2    256
#define OUTD   112
#define TILES_M 391   // ceil(50000/128)
#define NB     196    // ceil(50000/256)

// ---------------- scratch (device globals; no allocation allowed) ----------
__device__ __align__(16) float g_seg[NN * IN_EDGE];
__device__ float g_inv[NN];
__device__ int   g_degi[NN];
__device__ int   g_rowptr[NN + 1];
__device__ int   g_cursor[NN];
__device__ int   g_bsum[NB];
__device__ int   g_boff[NB];
__device__ int   g_csrc[EE];

// split activations (fp16 hi/lo; hi+lo reconstructs ~22-bit mantissa)
__device__ __align__(16) __half g_ch  [NN * HH];    // combined, W1 input
__device__ __align__(16) __half g_cl  [NN * HH];
__device__ __align__(16) __half g_h1h [NN * HH2];   // W1 output, W2 input
__device__ __align__(16) __half g_h1l [NN * HH2];
__device__ __align__(16) __half g_xh  [NN * HH];    // node state (split)
__device__ __align__(16) __half g_xl  [NN * HH];
__device__ __align__(16) __half g_eamh[NN * HH];    // edge-agg-mean (split)
__device__ __align__(16) __half g_eaml[NN * HH];

// pre-rounded transposed weights, layout [N][K] fp16
__device__ __align__(16) __half g_whi[235520];

// ---------------------------------------------------------------------------
__device__ __forceinline__ uint32_t smem_u32(const void* p) {
    uint32_t a;
    asm("{ .reg .u64 t; cvta.to.shared.u64 t, %1; cvt.u32.u64 %0, t; }"
        : "=r"(a) : "l"(p));
    return a;
}
__device__ __forceinline__ void cp16(uint32_t dst, const void* src) {
    asm volatile("cp.async.cg.shared.global [%0], [%1], 16;"
                 :: "r"(dst), "l"(src) : "memory");
}
__device__ __forceinline__ void zero16(uint32_t dst) {
    asm volatile("st.shared.v4.b32 [%0], {%1,%1,%1,%1};" :: "r"(dst), "r"(0) : "memory");
}
__device__ __forceinline__ void ldsm4(uint32_t* r, uint32_t addr) {
    asm volatile("ldmatrix.sync.aligned.m8n8.x4.shared.b16 {%0,%1,%2,%3}, [%4];"
                 : "=r"(r[0]), "=r"(r[1]), "=r"(r[2]), "=r"(r[3]) : "r"(addr));
}
__device__ __forceinline__ void mma16816(float* d, const uint32_t* a, const uint32_t* b) {
    asm volatile("mma.sync.aligned.m16n8k16.row.col.f32.f16.f16.f32 "
                 "{%0,%1,%2,%3}, {%4,%5,%6,%7}, {%8,%9}, {%0,%1,%2,%3};"
                 : "+f"(d[0]), "+f"(d[1]), "+f"(d[2]), "+f"(d[3])
                 : "r"(a[0]), "r"(a[1]), "r"(a[2]), "r"(a[3]), "r"(b[0]), "r"(b[1]));
}
__device__ __forceinline__ void split2(float a, float b, uint32_t& hi, uint32_t& lo) {
    __half ha = __float2half(a), hb = __float2half(b);
    __half2 h = __halves2half2(ha, hb);
    __half2 l = __halves2half2(
        __float2half(a - __half2float(ha)),
        __float2half(b - __half2float(hb)));
    hi = *(uint32_t*)&h; lo = *(uint32_t*)&l;
}
__device__ __forceinline__ float2 unpack2(uint32_t h, uint32_t l) {
    __half2 hh = *(__half2*)&h;
    __half2 ll = *(__half2*)&l;
    return make_float2(__low2float(hh) + __low2float(ll),
                       __high2float(hh) + __high2float(ll));
}
__device__ __forceinline__ void red_add_v4(float* addr, float4 v) {
    asm volatile("red.global.add.v4.f32 [%0], {%1,%2,%3,%4};"
                 :: "l"(addr), "f"(v.x), "f"(v.y), "f"(v.z), "f"(v.w) : "memory");
}

// ---------------------------------------------------------------------------
// front: fused weight prep (fp16 round + transpose) + degree histogram
// ---------------------------------------------------------------------------
__global__ void front_kernel(const float* __restrict__ node_W, const float* __restrict__ edge_W,
                             const float* __restrict__ W1, const float* __restrict__ W2,
                             const float* __restrict__ lin_W,
                             __half* __restrict__ hi,
                             const int* __restrict__ ei, int* __restrict__ degi) {
    if (blockIdx.x < 920) {
        int i = blockIdx.x * 256 + threadIdx.x;
        if (i >= 235520) return;
        const float* src; int K, Nc, idx;
        if (i < 16384)       { src = node_W;                 K = 128; Nc = 128; idx = i; }
        else if (i < 24576)  { src = edge_W;                 K =  64; Nc = 128; idx = i - 16384; }
        else if (i < 122880) { int j = i - 24576;  src = W1 + (j / 32768) * 32768; K = 128; Nc = 256; idx = j % 32768; }
        else if (i < 221184) { int j = i - 122880; src = W2 + (j / 32768) * 32768; K = 256; Nc = 128; idx = j % 32768; }
        else                 { src = lin_W;                  K = 128; Nc = 112; idx = i - 221184; }
        int n = idx / K, k = idx % K;
        float v = __ldg(&src[(size_t)k * Nc + n]);
        hi[i] = __float2half(v);
    } else {
        int e = (blockIdx.x - 920) * 256 + threadIdx.x;
        if (e < EE) atomicAdd(&degi[ei[EE + e]], 1);
    }
}

// ---------------------------------------------------------------------------
// CSR build
// ---------------------------------------------------------------------------
__global__ void scan1(const int* __restrict__ d, int* __restrict__ bsum) {
    __shared__ int s[256];
    int i = blockIdx.x * 256 + threadIdx.x;
    s[threadIdx.x] = (i < NN) ? d[i] : 0;
    __syncthreads();
    for (int o = 128; o > 0; o >>= 1) {
        if (threadIdx.x < o) s[threadIdx.x] += s[threadIdx.x + o];
        __syncthreads();
    }
    if (threadIdx.x == 0) bsum[blockIdx.x] = s[0];
}
__global__ void scan2(const int* __restrict__ bsum, int* __restrict__ boff,
                      int* __restrict__ rowptr_last) {
    __shared__ int s[256];
    int t = threadIdx.x;
    int v = (t < NB) ? bsum[t] : 0;
    s[t] = v;
    __syncthreads();
    #pragma unroll
    for (int o = 1; o < 256; o <<= 1) {
        int tv = (t >= o) ? s[t - o] : 0;
        __syncthreads();
        s[t] += tv;
        __syncthreads();
    }
    if (t < NB) boff[t] = s[t] - v;
    if (t == 255) rowptr_last[0] = s[255];
}
__global__ void scan3(const int* __restrict__ d, const int* __restrict__ boff,
                      int* __restrict__ rowptr, int* __restrict__ cursor,
                      float* __restrict__ inv) {
    __shared__ int s[256];
    int i = blockIdx.x * 256 + threadIdx.x;
    int v = (i < NN) ? d[i] : 0;
    s[threadIdx.x] = v;
    __syncthreads();
    #pragma unroll
    for (int o = 1; o < 256; o <<= 1) {
        int t = (threadIdx.x >= o) ? s[threadIdx.x - o] : 0;
        __syncthreads();
        s[threadIdx.x] += t;
        __syncthreads();
    }
    if (i < NN) {
        int excl = s[threadIdx.x] - v + boff[blockIdx.x];
        rowptr[i] = excl;
        cursor[i] = excl;
        inv[i] = 1.0f / (float)max(v, 1);
    }
}
__global__ void csr_fill(const int* __restrict__ ei, int* __restrict__ cursor,
                         int* __restrict__ csrc) {
    int e = blockIdx.x * blockDim.x + threadIdx.x;
    if (e >= EE) return;
    int dst = __ldg(&ei[EE + e]);
    int p = atomicAdd(&cursor[dst], 1);
    csrc[p] = __ldg(&ei[e]);
}

// seg[dst] += edge_attr[e]  (16 threads per edge, streaming read + red.v4)
__global__ void seg_scatter(const float* __restrict__ ea, const int* __restrict__ ei,
                            float* __restrict__ seg) {
    int gid = blockIdx.x * blockDim.x + threadIdx.x;
    if (gid >= EE * 16) return;
    int e = gid >> 4, g = gid & 15;
    int dst = __ldg(&ei[EE + e]);
    float4 v = __ldg(((const float4*)ea) + (size_t)e * 16 + g);
    red_add_v4(seg + (size_t)dst * IN_EDGE + g * 4, v);
}

// fused: agg = sum_neighbors(x_hi) ; c = (1+eps)*x + agg*inv + eam -> ch/cl
// one warp per node; lane owns 4 features. Neighbor loop reads hi ONLY
// (fp16 rounding error averages out over deg in the mean).
__global__ void gather_combine(const int* __restrict__ rowptr, const int* __restrict__ csrc,
                               const __half* __restrict__ xh,
                               const __half* __restrict__ xl,
                               const __half* __restrict__ eamh,
                               const __half* __restrict__ eaml,
                               const float* __restrict__ inv,
                               const float* __restrict__ eps_p, int layer,
                               __half* __restrict__ ch, __half* __restrict__ cl) {
    int w = (blockIdx.x * blockDim.x + threadIdx.x) >> 5;
    if (w >= NN) return;
    int lane = threadIdx.x & 31;
    int beg = __ldg(&rowptr[w]), end = __ldg(&rowptr[w + 1]);
    float a0 = 0.f, a1 = 0.f, a2 = 0.f, a3 = 0.f;
    for (int j = beg; j < end; j++) {
        int s = __ldg(&csrc[j]);
        uint2 hv = __ldg((const uint2*)(xh + (size_t)s * HH) + lane);
        __half2 h0 = *(__half2*)&hv.x;
        __half2 h1 = *(__half2*)&hv.y;
        a0 += __low2float(h0); a1 += __high2float(h0);
        a2 += __low2float(h1); a3 += __high2float(h1);
    }
    float iv = __ldg(&inv[w]);
    float epsv = 1.f + __ldg(&eps_p[layer]);
    // self term: full hi+lo precision
    uint2 hs = __ldg((const uint2*)(xh + (size_t)w * HH) + lane);
    uint2 ls = __ldg((const uint2*)(xl + (size_t)w * HH) + lane);
    float2 x01 = unpack2(hs.x, ls.x);
    float2 x23 = unpack2(hs.y, ls.y);
    // eam: fp16 split
    uint2 eh = __ldg((const uint2*)(eamh + (size_t)w * HH) + lane);
    uint2 el = __ldg((const uint2*)(eaml + (size_t)w * HH) + lane);
    float2 e01 = unpack2(eh.x, el.x);
    float2 e23 = unpack2(eh.y, el.y);
    float v0 = epsv * x01.x + a0 * iv + e01.x;
    float v1 = epsv * x01.y + a1 * iv + e01.y;
    float v2 = epsv * x23.x + a2 * iv + e23.x;
    float v3 = epsv * x23.y + a3 * iv + e23.y;
    uint2 h, l;
    split2(v0, v1, h.x, l.x);
    split2(v2, v3, h.y, l.y);
    *(uint2*)(ch + (size_t)w * HH + lane * 4) = h;
    *(uint2*)(cl + (size_t)w * HH + lane * 4) = l;
}

// ---------------------------------------------------------------------------
// GEMM with fp32-A conversion loader (node & edge encoders). B = fp16 hi only.
// D = (Ah+Al) @ Bh   (2 MMA products)
// EPI: 0 = +bias; 2 = *inv + [deg>0]*bias.  OUTMODE: 0 fp32; 1 fp16 split.
// ---------------------------------------------------------------------------
#define ROWB 144
template <int KTOT, int EPI, int OUTMODE>
__global__ void __launch_bounds__(256, 2)
gemm_f32a(const float* __restrict__ A, const __half* __restrict__ Bhi,
          const float* __restrict__ bias, float* __restrict__ Cf,
          __half* __restrict__ Ch, __half* __restrict__ Cl, int Nc,
          const float* __restrict__ inv, const int* __restrict__ degi) {
    extern __shared__ char smem[];
    const uint32_t sb  = smem_u32(smem);
    const uint32_t sAh = sb, sAl = sb + 18432, sBh = sb + 36864;

    const int tid  = threadIdx.x;
    const int lane = tid & 31;
    const int wid  = tid >> 5;
    const int wm   = wid & 3;
    const int wn   = wid >> 2;
    const int rowBase = blockIdx.x * 128;
    const int colBase = blockIdx.y * 64;

    float acc[2][4][4];
    #pragma unroll
    for (int a = 0; a < 2; a++)
        #pragma unroll
        for (int b = 0; b < 4; b++)
            #pragma unroll
            for (int c = 0; c < 4; c++) acc[a][b][c] = 0.f;

    const uint32_t aRow  = (uint32_t)(lane & 15);
    const uint32_t aKoff = (uint32_t)((lane >> 4) << 3);
    const uint32_t bRow  = (uint32_t)((lane & 7) + ((lane >> 4) << 3));
    const uint32_t bKoff = (uint32_t)(((lane >> 3) & 1) << 3);

    for (int kb = 0; kb < KTOT; kb += 64) {
        if (kb) __syncthreads();
        #pragma unroll
        for (int i = 0; i < 2; i++) {
            int f = tid + i * 256;
            int nrow = f >> 3, chunk = f & 7;
            uint32_t dh = sBh + nrow * ROWB + chunk * 16;
            int gn = colBase + nrow;
            if (gn < Nc) cp16(dh, Bhi + (size_t)gn * KTOT + kb + chunk * 8);
            else         zero16(dh);
        }
        asm volatile("cp.async.commit_group;" ::: "memory");

        #pragma unroll
        for (int i = 0; i < 8; i++) {
            int f = tid + i * 256;
            int row = f >> 4;
            int c4  = f & 15;
            int gr = rowBase + row;
            float4 v = make_float4(0.f, 0.f, 0.f, 0.f);
            if (gr < NN) v = __ldg((const float4*)(A + (size_t)gr * KTOT + kb + c4 * 4));
            uint32_t h01, h23, l01, l23;
            split2(v.x, v.y, h01, l01);
            split2(v.z, v.w, h23, l23);
            uint32_t addr = row * ROWB + c4 * 8;
            asm volatile("st.shared.v2.b32 [%0], {%1,%2};"
                         :: "r"(sAh + addr), "r"(h01), "r"(h23) : "memory");
            asm volatile("st.shared.v2.b32 [%0], {%1,%2};"
                         :: "r"(sAl + addr), "r"(l01), "r"(l23) : "memory");
        }
        asm volatile("cp.async.wait_group 0;" ::: "memory");
        __syncthreads();

        #pragma unroll
        for (int ks = 0; ks < 4; ks++) {
            uint32_t ah[2][4], al[2][4], bh[4][2];
            #pragma unroll
            for (int mi = 0; mi < 2; mi++) {
                uint32_t off = (wm * 32 + mi * 16 + aRow) * ROWB + (ks * 16 + aKoff) * 2;
                ldsm4(ah[mi], sAh + off);
                ldsm4(al[mi], sAl + off);
            }
            #pragma unroll
            for (int pr = 0; pr < 2; pr++) {
                uint32_t off = (wn * 32 + pr * 16 + bRow) * ROWB + (ks * 16 + bKoff) * 2;
                uint32_t t[4];
                ldsm4(t, sBh + off);
                bh[pr*2][0] = t[0]; bh[pr*2][1] = t[1];
                bh[pr*2+1][0] = t[2]; bh[pr*2+1][1] = t[3];
            }
            #pragma unroll
            for (int mi = 0; mi < 2; mi++)
                #pragma unroll
                for (int ni = 0; ni < 4; ni++) {
                    mma16816(acc[mi][ni], ah[mi], bh[ni]);
                    mma16816(acc[mi][ni], al[mi], bh[ni]);
                }
        }
    }

    const int group = lane >> 2;
    const int qc    = (lane & 3) * 2;
    #pragma unroll
    for (int mi = 0; mi < 2; mi++) {
        int r0 = rowBase + wm * 32 + mi * 16 + group;
        int r1 = r0 + 8;
        float iv0 = 0.f, m0 = 0.f, iv1 = 0.f, m1 = 0.f;
        if (EPI == 2) {
            if (r0 < NN) { iv0 = __ldg(&inv[r0]); m0 = (__ldg(&degi[r0]) > 0) ? 1.f : 0.f; }
            if (r1 < NN) { iv1 = __ldg(&inv[r1]); m1 = (__ldg(&degi[r1]) > 0) ? 1.f : 0.f; }
        }
        #pragma unroll
        for (int ni = 0; ni < 4; ni++) {
            int c = colBase + wn * 32 + ni * 8 + qc;
            if (c >= Nc) continue;
            float b0 = __ldg(&bias[c]), b1 = __ldg(&bias[c + 1]);
            float2 v0, v1;
            if (EPI == 2) {
                v0.x = acc[mi][ni][0] * iv0 + m0 * b0;
                v0.y = acc[mi][ni][1] * iv0 + m0 * b1;
                v1.x = acc[mi][ni][2] * iv1 + m1 * b0;
                v1.y = acc[mi][ni][3] * iv1 + m1 * b1;
            } else {
                v0.x = acc[mi][ni][0] + b0; v0.y = acc[mi][ni][1] + b1;
                v1.x = acc[mi][ni][2] + b0; v1.y = acc[mi][ni][3] + b1;
            }
            if (r0 < NN) {
                if (OUTMODE == 0) *(float2*)(Cf + (size_t)r0 * Nc + c) = v0;
                else {
                    uint32_t h, l; split2(v0.x, v0.y, h, l);
                    *(uint32_t*)(Ch + (size_t)r0 * Nc + c) = h;
                    *(uint32_t*)(Cl + (size_t)r0 * Nc + c) = l;
                }
            }
            if (r1 < NN) {
                if (OUTMODE == 0) *(float2*)(Cf + (size_t)r1 * Nc + c) = v1;
                else {
                    uint32_t h, l; split2(v1.x, v1.y, h, l);
                    *(uint32_t*)(Ch + (size_t)r1 * Nc + c) = h;
                    *(uint32_t*)(Cl + (size_t)r1 * Nc + c) = l;
                }
            }
        }
    }
}

// ---------------------------------------------------------------------------
// Pipelined fp16 GEMM, A pre-split (hi/lo), B fp16 hi only: D = (Ah+Al)@Bh.
// EPI: 0 = +bias, 1 = relu(+bias);  OUTMODE: 0 fp32; 1 fp16 split
// ---------------------------------------------------------------------------
template <int KTOT, int EPI, int OUTMODE>
__global__ void __launch_bounds__(256, 2)
gemm_hf(const __half* __restrict__ Ah, const __half* __restrict__ Al,
        const __half* __restrict__ Bhi,
        const float* __restrict__ bias, float* __restrict__ Cf,
        __half* __restrict__ Ch, __half* __restrict__ Cl, int Nc) {
    constexpr int CHUNKS = KTOT / 64;
    constexpr int STG = 40960;   // Ah 16K | Al 16K | Bh 8K
    extern __shared__ char smem[];
    const uint32_t sb = smem_u32(smem);

    const int tid  = threadIdx.x;
    const int lane = tid & 31;
    const int wid  = tid >> 5;
    const int wm   = wid & 3;
    const int wn   = wid >> 2;
    const int rowBase = blockIdx.x * 128;
    const int colBase = blockIdx.y * 64;

    float acc[2][4][4];
    #pragma unroll
    for (int a = 0; a < 2; a++)
        #pragma unroll
        for (int b = 0; b < 4; b++)
            #pragma unroll
            for (int c = 0; c < 4; c++) acc[a][b][c] = 0.f;

    auto load_slab = [&](int stage, int c) {
        uint32_t base = sb + stage * STG;
        int kb = c * 64;
        #pragma unroll
        for (int i = 0; i < 4; i++) {
            int f = tid + i * 256;
            int row = f >> 3, chn = f & 7;
            uint32_t sw = (uint32_t)(chn * 16) ^ (uint32_t)((row & 7) << 4);
            uint32_t da = base + row * 128 + sw;
            int gr = rowBase + row;
            if (gr < NN) {
                size_t off = (size_t)gr * KTOT + kb + chn * 8;
                cp16(da, Ah + off);
                cp16(da + 16384, Al + off);
            } else { zero16(da); zero16(da + 16384); }
        }
        #pragma unroll
        for (int i = 0; i < 2; i++) {
            int f = tid + i * 256;
            int row = f >> 3, chn = f & 7;
            uint32_t sw = (uint32_t)(chn * 16) ^ (uint32_t)((row & 7) << 4);
            uint32_t db = base + 32768 + row * 128 + sw;
            int gn = colBase + row;
            if (gn < Nc) cp16(db, Bhi + (size_t)gn * KTOT + kb + chn * 8);
            else         zero16(db);
        }
        asm volatile("cp.async.commit_group;" ::: "memory");
    };

    const uint32_t aRowIdx = (uint32_t)(lane & 15);
    const uint32_t aK16    = (uint32_t)((lane >> 4) << 4);
    const uint32_t bRowIdx = (uint32_t)((lane & 7) + ((lane >> 4) << 3));
    const uint32_t bK16    = (uint32_t)(((lane >> 3) & 1) << 4);

    load_slab(0, 0);

    for (int c = 0; c < CHUNKS; c++) {
        if (c + 1 < CHUNKS) {
            load_slab((c + 1) & 1, c + 1);
            asm volatile("cp.async.wait_group 1;" ::: "memory");
        } else {
            asm volatile("cp.async.wait_group 0;" ::: "memory");
        }
        __syncthreads();

        uint32_t bA = sb + (c & 1) * STG;
        uint32_t bB = bA + 32768;
        #pragma unroll
        for (int ks = 0; ks < 4; ks++) {
            uint32_t ah[2][4], al[2][4], bh[4][2];
            #pragma unroll
            for (int mi = 0; mi < 2; mi++) {
                uint32_t row = wm * 32 + mi * 16 + aRowIdx;
                uint32_t cb = (uint32_t)(ks * 32) + aK16;
                uint32_t off = row * 128 + (cb ^ ((row & 7) << 4));
                ldsm4(ah[mi], bA + off);
                ldsm4(al[mi], bA + 16384 + off);
            }
            #pragma unroll
            for (int pr = 0; pr < 2; pr++) {
                uint32_t row = wn * 32 + pr * 16 + bRowIdx;
                uint32_t cb = (uint32_t)(ks * 32) + bK16;
                uint32_t off = row * 128 + (cb ^ ((row & 7) << 4));
                uint32_t t[4];
                ldsm4(t, bB + off);
                bh[pr*2][0] = t[0]; bh[pr*2][1] = t[1];
                bh[pr*2+1][0] = t[2]; bh[pr*2+1][1] = t[3];
            }
            #pragma unroll
            for (int mi = 0; mi < 2; mi++)
                #pragma unroll
                for (int ni = 0; ni < 4; ni++) {
                    mma16816(acc[mi][ni], ah[mi], bh[ni]);
                    mma16816(acc[mi][ni], al[mi], bh[ni]);
                }
        }
        if (c + 1 < CHUNKS) __syncthreads();
    }

    const int group = lane >> 2;
    const int qc    = (lane & 3) * 2;
    #pragma unroll
    for (int mi = 0; mi < 2; mi++) {
        int r0 = rowBase + wm * 32 + mi * 16 + group;
        int r1 = r0 + 8;
        #pragma unroll
        for (int ni = 0; ni < 4; ni++) {
            int c = colBase + wn * 32 + ni * 8 + qc;
            if (c >= Nc) continue;
            float b0 = __ldg(&bias[c]), b1 = __ldg(&bias[c + 1]);
            float2 v0, v1;
            v0.x = acc[mi][ni][0] + b0; v0.y = acc[mi][ni][1] + b1;
            v1.x = acc[mi][ni][2] + b0; v1.y = acc[mi][ni][3] + b1;
            if (EPI == 1) {
                v0.x = fmaxf(v0.x, 0.f); v0.y = fmaxf(v0.y, 0.f);
                v1.x = fmaxf(v1.x, 0.f); v1.y = fmaxf(v1.y, 0.f);
            }
            if (r0 < NN) {
                if (OUTMODE == 0) *(float2*)(Cf + (size_t)r0 * Nc + c) = v0;
                else {
                    uint32_t h, l; split2(v0.x, v0.y, h, l);
                    *(uint32_t*)(Ch + (size_t)r0 * Nc + c) = h;
                    *(uint32_t*)(Cl + (size_t)r0 * Nc + c) = l;
                }
            }
            if (r1 < NN) {
                if (OUTMODE == 0) *(float2*)(Cf + (size_t)r1 * Nc + c) = v1;
                else {
                    uint32_t h, l; split2(v1.x, v1.y, h, l);
                    *(uint32_t*)(Ch + (size_t)r1 * Nc + c) = h;
                    *(uint32_t*)(Cl + (size_t)r1 * Nc + c) = l;
                }
            }
        }
    }
}

// ---------------------------------------------------------------------------
extern "C" void kernel_launch(void* const* d_in, const int* in_sizes, int n_in,
                              void* d_out, int out_size) {
    const float* x_in   = (const float*)d_in[0];
    const float* eattr  = (const float*)d_in[1];
    const int*   eidx   = (const int*)  d_in[2];
    const float* node_W = (const float*)d_in[3];
    const float* node_b = (const float*)d_in[4];
    const float* edge_W = (const float*)d_in[5];
    const float* edge_b = (const float*)d_in[6];
    const float* W1     = (const float*)d_in[7];
    const float* b1     = (const float*)d_in[8];
    const float* W2     = (const float*)d_in[9];
    const float* b2     = (const float*)d_in[10];
    const float* eps    = (const float*)d_in[11];
    const float* lin_W  = (const float*)d_in[12];
    const float* lin_b  = (const float*)d_in[13];
    float* out = (float*)d_out;

    float *pseg, *pinv;
    int *pdegi, *prowptr, *pcursor, *pbsum, *pboff, *pcsrc;
    __half *pwh, *pch, *pcl, *ph1h, *ph1l, *pxh, *pxl, *peamh, *peaml;
    cudaGetSymbolAddress((void**)&pseg, g_seg);
    cudaGetSymbolAddress((void**)&pinv, g_inv);
    cudaGetSymbolAddress((void**)&pdegi, g_degi);
    cudaGetSymbolAddress((void**)&prowptr, g_rowptr);
    cudaGetSymbolAddress((void**)&pcursor, g_cursor);
    cudaGetSymbolAddress((void**)&pbsum, g_bsum);
    cudaGetSymbolAddress((void**)&pboff, g_boff);
    cudaGetSymbolAddress((void**)&pcsrc, g_csrc);
    cudaGetSymbolAddress((void**)&pwh,  g_whi);
    cudaGetSymbolAddress((void**)&pch,  g_ch);
    cudaGetSymbolAddress((void**)&pcl,  g_cl);
    cudaGetSymbolAddress((void**)&ph1h, g_h1h);
    cudaGetSymbolAddress((void**)&ph1l, g_h1l);
    cudaGetSymbolAddress((void**)&pxh,  g_xh);
    cudaGetSymbolAddress((void**)&pxl,  g_xl);
    cudaGetSymbolAddress((void**)&peamh, g_eamh);
    cudaGetSymbolAddress((void**)&peaml, g_eaml);

    constexpr int SM_F32A = 46080;
    constexpr int SM_HF   = 81920;
    auto setsm = [](const void* f, int b) {
        cudaFuncSetAttribute(f, cudaFuncAttributeMaxDynamicSharedMemorySize, b);
    };
    setsm((const void*)gemm_f32a<128, 0, 1>, SM_F32A);
    setsm((const void*)gemm_f32a< 64, 2, 1>, SM_F32A);
    setsm((const void*)gemm_hf<128, 1, 1>, SM_HF);
    setsm((const void*)gemm_hf<256, 1, 1>, SM_HF);
    setsm((const void*)gemm_hf<128, 0, 0>, SM_HF);

    // ---- front: weight prep + degree histogram (fused) ----
    cudaMemsetAsync(pdegi, 0, NN * sizeof(int));
    cudaMemsetAsync(pseg, 0, (size_t)NN * IN_EDGE * sizeof(float));
    front_kernel<<<920 + 2442, 256>>>(node_W, edge_W, W1, W2, lin_W, pwh,
                                      eidx, pdegi);

    // ---- seg scatter (independent of CSR): seg[dst] += edge_attr[e] ----
    seg_scatter<<<(EE * 16 + 255) / 256, 256>>>(eattr, eidx, pseg);

    // ---- CSR build ----
    scan1<<<NB, 256>>>(pdegi, pbsum);
    scan2<<<1, 256>>>(pbsum, pboff, prowptr + NN);
    scan3<<<NB, 256>>>(pdegi, pboff, prowptr, pcursor, pinv);
    csr_fill<<<(EE + 255) / 256, 256>>>(eidx, pcursor, pcsrc);

    dim3 g2(TILES_M, 2), g4(TILES_M, 4);

    // node encoder: x(split) = x_in @ node_W + node_b
    gemm_f32a<128, 0, 1><<<g2, 256, SM_F32A>>>(x_in, pwh, node_b,
        nullptr, pxh, pxl, HH, nullptr, nullptr);
    // edge agg through encoder: eam(split) = (seg @ edge_W)*inv + [deg>0]*edge_b
    gemm_f32a<64, 2, 1><<<g2, 256, SM_F32A>>>(pseg, pwh + 16384, edge_b,
        nullptr, peamh, peaml, HH, pinv, pdegi);

    for (int l = 0; l < 3; l++) {
        gather_combine<<<(NN * 32 + 255) / 256, 256>>>(prowptr, pcsrc, pxh, pxl,
            peamh, peaml, pinv, eps, l, pch, pcl);
        // h1(split) = relu( c @ W1[l] + b1[l] )
        gemm_hf<128, 1, 1><<<g4, 256, SM_HF>>>(pch, pcl,
            pwh + 24576 + l * 32768,
            b1 + (size_t)l * HH2, nullptr, ph1h, ph1l, HH2);
        // x(split) = relu( h1 @ W2[l] + b2[l] )
        gemm_hf<256, 1, 1><<<g2, 256, SM_HF>>>(ph1h, ph1l,
            pwh + 122880 + l * 32768,
            b2 + (size_t)l * HH, nullptr, pxh, pxl, HH);
    }

    // head: out = x @ lin_W + lin_b
    gemm_hf<128, 0, 0><<<g2, 256, SM_HF>>>(pxh, pxl, pwh + 221184,
        lin_b, out, nullptr, nullptr, OUTD);
}

// round 10
// speedup vs baseline: 1.9658x; 1.2079x over previous
#include <cuda_runtime.h>
#include <cuda_fp16.h>
#include <cstdint>

#define NN     50000
#define EE     625000
#define IN_EDGE 64
#define HH     128
#define HH2    256
#define OUTD   112
#define TILES_M 391   // ceil(50000/128)
#define NB     196    // ceil(50000/256)

// ---------------- scratch (device globals; no allocation allowed) ----------
__device__ __align__(16) float g_seg[NN * IN_EDGE];
__device__ float g_inv[NN];
__device__ int   g_degi[NN];
__device__ int   g_rowptr[NN + 1];
__device__ int   g_cursor[NN];
__device__ int   g_bsum[NB];
__device__ int   g_boff[NB];
__device__ int   g_csrc[EE];

// activations
__device__ __align__(16) __half g_ch  [NN * HH];    // combined (hi only), W1 input
__device__ __align__(16) __half g_h1h [NN * HH2];   // W1 output (hi only), W2 input
__device__ __align__(16) __half g_xh  [NN * HH];    // node state (split hi)
__device__ __align__(16) __half g_xl  [NN * HH];    // node state (split lo)
__device__ __align__(16) __half g_eamh[NN * HH];    // edge-agg-mean (split)
__device__ __align__(16) __half g_eaml[NN * HH];

// pre-rounded transposed weights, layout [N][K] fp16
__device__ __align__(16) __half g_whi[235520];

// ---------------------------------------------------------------------------
__device__ __forceinline__ uint32_t smem_u32(const void* p) {
    uint32_t a;
    asm("{ .reg .u64 t; cvta.to.shared.u64 t, %1; cvt.u32.u64 %0, t; }"
        : "=r"(a) : "l"(p));
    return a;
}
__device__ __forceinline__ void cp16(uint32_t dst, const void* src) {
    asm volatile("cp.async.cg.shared.global [%0], [%1], 16;"
                 :: "r"(dst), "l"(src) : "memory");
}
__device__ __forceinline__ void zero16(uint32_t dst) {
    asm volatile("st.shared.v4.b32 [%0], {%1,%1,%1,%1};" :: "r"(dst), "r"(0) : "memory");
}
__device__ __forceinline__ void ldsm4(uint32_t* r, uint32_t addr) {
    asm volatile("ldmatrix.sync.aligned.m8n8.x4.shared.b16 {%0,%1,%2,%3}, [%4];"
                 : "=r"(r[0]), "=r"(r[1]), "=r"(r[2]), "=r"(r[3]) : "r"(addr));
}
__device__ __forceinline__ void mma16816(float* d, const uint32_t* a, const uint32_t* b) {
    asm volatile("mma.sync.aligned.m16n8k16.row.col.f32.f16.f16.f32 "
                 "{%0,%1,%2,%3}, {%4,%5,%6,%7}, {%8,%9}, {%0,%1,%2,%3};"
                 : "+f"(d[0]), "+f"(d[1]), "+f"(d[2]), "+f"(d[3])
                 : "r"(a[0]), "r"(a[1]), "r"(a[2]), "r"(a[3]), "r"(b[0]), "r"(b[1]));
}
__device__ __forceinline__ void split2(float a, float b, uint32_t& hi, uint32_t& lo) {
    __half ha = __float2half(a), hb = __float2half(b);
    __half2 h = __halves2half2(ha, hb);
    __half2 l = __halves2half2(
        __float2half(a - __half2float(ha)),
        __float2half(b - __half2float(hb)));
    hi = *(uint32_t*)&h; lo = *(uint32_t*)&l;
}
__device__ __forceinline__ uint32_t pack2(float a, float b) {
    __half2 h = __halves2half2(__float2half(a), __float2half(b));
    return *(uint32_t*)&h;
}
__device__ __forceinline__ float2 unpack2(uint32_t h, uint32_t l) {
    __half2 hh = *(__half2*)&h;
    __half2 ll = *(__half2*)&l;
    return make_float2(__low2float(hh) + __low2float(ll),
                       __high2float(hh) + __high2float(ll));
}
__device__ __forceinline__ void red_add_v4(float* addr, float4 v) {
    asm volatile("red.global.add.v4.f32 [%0], {%1,%2,%3,%4};"
                 :: "l"(addr), "f"(v.x), "f"(v.y), "f"(v.z), "f"(v.w) : "memory");
}

// ---------------------------------------------------------------------------
// front: fused weight prep (fp16 round + transpose) + degree histogram
// ---------------------------------------------------------------------------
__global__ void front_kernel(const float* __restrict__ node_W, const float* __restrict__ edge_W,
                             const float* __restrict__ W1, const float* __restrict__ W2,
                             const float* __restrict__ lin_W,
                             __half* __restrict__ hi,
                             const int* __restrict__ ei, int* __restrict__ degi) {
    if (blockIdx.x < 920) {
        int i = blockIdx.x * 256 + threadIdx.x;
        if (i >= 235520) return;
        const float* src; int K, Nc, idx;
        if (i < 16384)       { src = node_W;                 K = 128; Nc = 128; idx = i; }
        else if (i < 24576)  { src = edge_W;                 K =  64; Nc = 128; idx = i - 16384; }
        else if (i < 122880) { int j = i - 24576;  src = W1 + (j / 32768) * 32768; K = 128; Nc = 256; idx = j % 32768; }
        else if (i < 221184) { int j = i - 122880; src = W2 + (j / 32768) * 32768; K = 256; Nc = 128; idx = j % 32768; }
        else                 { src = lin_W;                  K = 128; Nc = 112; idx = i - 221184; }
        int n = idx / K, k = idx % K;
        float v = __ldg(&src[(size_t)k * Nc + n]);
        hi[i] = __float2half(v);
    } else {
        int e = (blockIdx.x - 920) * 256 + threadIdx.x;
        if (e < EE) atomicAdd(&degi[ei[EE + e]], 1);
    }
}

// ---------------------------------------------------------------------------
// CSR build
// ---------------------------------------------------------------------------
__global__ void scan1(const int* __restrict__ d, int* __restrict__ bsum) {
    __shared__ int s[256];
    int i = blockIdx.x * 256 + threadIdx.x;
    s[threadIdx.x] = (i < NN) ? d[i] : 0;
    __syncthreads();
    for (int o = 128; o > 0; o >>= 1) {
        if (threadIdx.x < o) s[threadIdx.x] += s[threadIdx.x + o];
        __syncthreads();
    }
    if (threadIdx.x == 0) bsum[blockIdx.x] = s[0];
}
__global__ void scan2(const int* __restrict__ bsum, int* __restrict__ boff,
                      int* __restrict__ rowptr_last) {
    __shared__ int s[256];
    int t = threadIdx.x;
    int v = (t < NB) ? bsum[t] : 0;
    s[t] = v;
    __syncthreads();
    #pragma unroll
    for (int o = 1; o < 256; o <<= 1) {
        int tv = (t >= o) ? s[t - o] : 0;
        __syncthreads();
        s[t] += tv;
        __syncthreads();
    }
    if (t < NB) boff[t] = s[t] - v;
    if (t == 255) rowptr_last[0] = s[255];
}
__global__ void scan3(const int* __restrict__ d, const int* __restrict__ boff,
                      int* __restrict__ rowptr, int* __restrict__ cursor,
                      float* __restrict__ inv) {
    __shared__ int s[256];
    int i = blockIdx.x * 256 + threadIdx.x;
    int v = (i < NN) ? d[i] : 0;
    s[threadIdx.x] = v;
    __syncthreads();
    #pragma unroll
    for (int o = 1; o < 256; o <<= 1) {
        int t = (threadIdx.x >= o) ? s[threadIdx.x - o] : 0;
        __syncthreads();
        s[threadIdx.x] += t;
        __syncthreads();
    }
    if (i < NN) {
        int excl = s[threadIdx.x] - v + boff[blockIdx.x];
        rowptr[i] = excl;
        cursor[i] = excl;
        inv[i] = 1.0f / (float)max(v, 1);
    }
}
__global__ void csr_fill(const int* __restrict__ ei, int* __restrict__ cursor,
                         int* __restrict__ csrc) {
    int e = blockIdx.x * blockDim.x + threadIdx.x;
    if (e >= EE) return;
    int dst = __ldg(&ei[EE + e]);
    int p = atomicAdd(&cursor[dst], 1);
    csrc[p] = __ldg(&ei[e]);
}

// seg[dst] += edge_attr[e]  (16 threads per edge, streaming read + red.v4)
__global__ void seg_scatter(const float* __restrict__ ea, const int* __restrict__ ei,
                            float* __restrict__ seg) {
    int gid = blockIdx.x * blockDim.x + threadIdx.x;
    if (gid >= EE * 16) return;
    int e = gid >> 4, g = gid & 15;
    int dst = __ldg(&ei[EE + e]);
    float4 v = __ldg(((const float4*)ea) + (size_t)e * 16 + g);
    red_add_v4(seg + (size_t)dst * IN_EDGE + g * 4, v);
}

// fused: agg = sum_neighbors(x_hi) ; c = (1+eps)*x + agg*inv + eam -> ch (fp16 hi)
// one warp per node; lane owns 4 features.
__global__ void gather_combine(const int* __restrict__ rowptr, const int* __restrict__ csrc,
                               const __half* __restrict__ xh,
                               const __half* __restrict__ xl,
                               const __half* __restrict__ eamh,
                               const __half* __restrict__ eaml,
                               const float* __restrict__ inv,
                               const float* __restrict__ eps_p, int layer,
                               __half* __restrict__ ch) {
    int w = (blockIdx.x * blockDim.x + threadIdx.x) >> 5;
    if (w >= NN) return;
    int lane = threadIdx.x & 31;
    int beg = __ldg(&rowptr[w]), end = __ldg(&rowptr[w + 1]);
    float a0 = 0.f, a1 = 0.f, a2 = 0.f, a3 = 0.f;
    for (int j = beg; j < end; j++) {
        int s = __ldg(&csrc[j]);
        uint2 hv = __ldg((const uint2*)(xh + (size_t)s * HH) + lane);
        __half2 h0 = *(__half2*)&hv.x;
        __half2 h1 = *(__half2*)&hv.y;
        a0 += __low2float(h0); a1 += __high2float(h0);
        a2 += __low2float(h1); a3 += __high2float(h1);
    }
    float iv = __ldg(&inv[w]);
    float epsv = 1.f + __ldg(&eps_p[layer]);
    // self term: full hi+lo precision
    uint2 hs = __ldg((const uint2*)(xh + (size_t)w * HH) + lane);
    uint2 ls = __ldg((const uint2*)(xl + (size_t)w * HH) + lane);
    float2 x01 = unpack2(hs.x, ls.x);
    float2 x23 = unpack2(hs.y, ls.y);
    // eam: fp16 split
    uint2 eh = __ldg((const uint2*)(eamh + (size_t)w * HH) + lane);
    uint2 el = __ldg((const uint2*)(eaml + (size_t)w * HH) + lane);
    float2 e01 = unpack2(eh.x, el.x);
    float2 e23 = unpack2(eh.y, el.y);
    float v0 = epsv * x01.x + a0 * iv + e01.x;
    float v1 = epsv * x01.y + a1 * iv + e01.y;
    float v2 = epsv * x23.x + a2 * iv + e23.x;
    float v3 = epsv * x23.y + a3 * iv + e23.y;
    uint2 h;
    h.x = pack2(v0, v1);
    h.y = pack2(v2, v3);
    *(uint2*)(ch + (size_t)w * HH + lane * 4) = h;
}

// ---------------------------------------------------------------------------
// GEMM with fp32-A conversion loader (node & edge encoders). B = fp16 hi only.
// D = (Ah+Al) @ Bh   (2 MMA products; A split computed on the fly)
// EPI: 0 = +bias; 2 = *inv + [deg>0]*bias.  Output: fp16 split (Ch, Cl).
// ---------------------------------------------------------------------------
#define ROWB 144
template <int KTOT, int EPI>
__global__ void __launch_bounds__(256, 2)
gemm_f32a(const float* __restrict__ A, const __half* __restrict__ Bhi,
          const float* __restrict__ bias,
          __half* __restrict__ Ch, __half* __restrict__ Cl, int Nc,
          const float* __restrict__ inv, const int* __restrict__ degi) {
    extern __shared__ char smem[];
    const uint32_t sb  = smem_u32(smem);
    const uint32_t sAh = sb, sAl = sb + 18432, sBh = sb + 36864;

    const int tid  = threadIdx.x;
    const int lane = tid & 31;
    const int wid  = tid >> 5;
    const int wm   = wid & 3;
    const int wn   = wid >> 2;
    const int rowBase = blockIdx.x * 128;
    const int colBase = blockIdx.y * 64;

    float acc[2][4][4];
    #pragma unroll
    for (int a = 0; a < 2; a++)
        #pragma unroll
        for (int b = 0; b < 4; b++)
            #pragma unroll
            for (int c = 0; c < 4; c++) acc[a][b][c] = 0.f;

    const uint32_t aRow  = (uint32_t)(lane & 15);
    const uint32_t aKoff = (uint32_t)((lane >> 4) << 3);
    const uint32_t bRow  = (uint32_t)((lane & 7) + ((lane >> 4) << 3));
    const uint32_t bKoff = (uint32_t)(((lane >> 3) & 1) << 3);

    for (int kb = 0; kb < KTOT; kb += 64) {
        if (kb) __syncthreads();
        #pragma unroll
        for (int i = 0; i < 2; i++) {
            int f = tid + i * 256;
            int nrow = f >> 3, chunk = f & 7;
            uint32_t dh = sBh + nrow * ROWB + chunk * 16;
            int gn = colBase + nrow;
            if (gn < Nc) cp16(dh, Bhi + (size_t)gn * KTOT + kb + chunk * 8);
            else         zero16(dh);
        }
        asm volatile("cp.async.commit_group;" ::: "memory");

        #pragma unroll
        for (int i = 0; i < 8; i++) {
            int f = tid + i * 256;
            int row = f >> 4;
            int c4  = f & 15;
            int gr = rowBase + row;
            float4 v = make_float4(0.f, 0.f, 0.f, 0.f);
            if (gr < NN) v = __ldg((const float4*)(A + (size_t)gr * KTOT + kb + c4 * 4));
            uint32_t h01, h23, l01, l23;
            split2(v.x, v.y, h01, l01);
            split2(v.z, v.w, h23, l23);
            uint32_t addr = row * ROWB + c4 * 8;
            asm volatile("st.shared.v2.b32 [%0], {%1,%2};"
                         :: "r"(sAh + addr), "r"(h01), "r"(h23) : "memory");
            asm volatile("st.shared.v2.b32 [%0], {%1,%2};"
                         :: "r"(sAl + addr), "r"(l01), "r"(l23) : "memory");
        }
        asm volatile("cp.async.wait_group 0;" ::: "memory");
        __syncthreads();

        #pragma unroll
        for (int ks = 0; ks < 4; ks++) {
            uint32_t ah[2][4], al[2][4], bh[4][2];
            #pragma unroll
            for (int mi = 0; mi < 2; mi++) {
                uint32_t off = (wm * 32 + mi * 16 + aRow) * ROWB + (ks * 16 + aKoff) * 2;
                ldsm4(ah[mi], sAh + off);
                ldsm4(al[mi], sAl + off);
            }
            #pragma unroll
            for (int pr = 0; pr < 2; pr++) {
                uint32_t off = (wn * 32 + pr * 16 + bRow) * ROWB + (ks * 16 + bKoff) * 2;
                uint32_t t[4];
                ldsm4(t, sBh + off);
                bh[pr*2][0] = t[0]; bh[pr*2][1] = t[1];
                bh[pr*2+1][0] = t[2]; bh[pr*2+1][1] = t[3];
            }
            #pragma unroll
            for (int mi = 0; mi < 2; mi++)
                #pragma unroll
                for (int ni = 0; ni < 4; ni++) {
                    mma16816(acc[mi][ni], ah[mi], bh[ni]);
                    mma16816(acc[mi][ni], al[mi], bh[ni]);
                }
        }
    }

    const int group = lane >> 2;
    const int qc    = (lane & 3) * 2;
    #pragma unroll
    for (int mi = 0; mi < 2; mi++) {
        int r0 = rowBase + wm * 32 + mi * 16 + group;
        int r1 = r0 + 8;
        float iv0 = 0.f, m0 = 0.f, iv1 = 0.f, m1 = 0.f;
        if (EPI == 2) {
            if (r0 < NN) { iv0 = __ldg(&inv[r0]); m0 = (__ldg(&degi[r0]) > 0) ? 1.f : 0.f; }
            if (r1 < NN) { iv1 = __ldg(&inv[r1]); m1 = (__ldg(&degi[r1]) > 0) ? 1.f : 0.f; }
        }
        #pragma unroll
        for (int ni = 0; ni < 4; ni++) {
            int c = colBase + wn * 32 + ni * 8 + qc;
            if (c >= Nc) continue;
            float b0 = __ldg(&bias[c]), b1 = __ldg(&bias[c + 1]);
            float2 v0, v1;
            if (EPI == 2) {
                v0.x = acc[mi][ni][0] * iv0 + m0 * b0;
                v0.y = acc[mi][ni][1] * iv0 + m0 * b1;
                v1.x = acc[mi][ni][2] * iv1 + m1 * b0;
                v1.y = acc[mi][ni][3] * iv1 + m1 * b1;
            } else {
                v0.x = acc[mi][ni][0] + b0; v0.y = acc[mi][ni][1] + b1;
                v1.x = acc[mi][ni][2] + b0; v1.y = acc[mi][ni][3] + b1;
            }
            if (r0 < NN) {
                uint32_t h, l; split2(v0.x, v0.y, h, l);
                *(uint32_t*)(Ch + (size_t)r0 * Nc + c) = h;
                *(uint32_t*)(Cl + (size_t)r0 * Nc + c) = l;
            }
            if (r1 < NN) {
                uint32_t h, l; split2(v1.x, v1.y, h, l);
                *(uint32_t*)(Ch + (size_t)r1 * Nc + c) = h;
                *(uint32_t*)(Cl + (size_t)r1 * Nc + c) = l;
            }
        }
    }
}

// ---------------------------------------------------------------------------
// Pipelined fp16 GEMM. NPROD=1: D = A@Bh (A fp16). NPROD=2: D = (Ah+Al)@Bh.
// EPI: 0 = +bias, 1 = relu(+bias)
// OUTMODE: 0 fp32; 1 fp16 hi only; 2 fp16 split
// ---------------------------------------------------------------------------
template <int KTOT, int EPI, int OUTMODE, int NPROD>
__global__ void __launch_bounds__(256, 2)
gemm_hf(const __half* __restrict__ Ah, const __half* __restrict__ Al,
        const __half* __restrict__ Bhi,
        const float* __restrict__ bias, float* __restrict__ Cf,
        __half* __restrict__ Ch, __half* __restrict__ Cl, int Nc) {
    constexpr int CHUNKS = KTOT / 64;
    constexpr int ASZ = 16384 * NPROD;
    constexpr int STG = ASZ + 8192;
    extern __shared__ char smem[];
    const uint32_t sb = smem_u32(smem);

    const int tid  = threadIdx.x;
    const int lane = tid & 31;
    const int wid  = tid >> 5;
    const int wm   = wid & 3;
    const int wn   = wid >> 2;
    const int rowBase = blockIdx.x * 128;
    const int colBase = blockIdx.y * 64;

    float acc[2][4][4];
    #pragma unroll
    for (int a = 0; a < 2; a++)
        #pragma unroll
        for (int b = 0; b < 4; b++)
            #pragma unroll
            for (int c = 0; c < 4; c++) acc[a][b][c] = 0.f;

    auto load_slab = [&](int stage, int c) {
        uint32_t base = sb + stage * STG;
        int kb = c * 64;
        #pragma unroll
        for (int i = 0; i < 4; i++) {
            int f = tid + i * 256;
            int row = f >> 3, chn = f & 7;
            uint32_t sw = (uint32_t)(chn * 16) ^ (uint32_t)((row & 7) << 4);
            uint32_t da = base + row * 128 + sw;
            int gr = rowBase + row;
            if (gr < NN) {
                size_t off = (size_t)gr * KTOT + kb + chn * 8;
                cp16(da, Ah + off);
                if (NPROD == 2) cp16(da + 16384, Al + off);
            } else {
                zero16(da);
                if (NPROD == 2) zero16(da + 16384);
            }
        }
        #pragma unroll
        for (int i = 0; i < 2; i++) {
            int f = tid + i * 256;
            int row = f >> 3, chn = f & 7;
            uint32_t sw = (uint32_t)(chn * 16) ^ (uint32_t)((row & 7) << 4);
            uint32_t db = base + ASZ + row * 128 + sw;
            int gn = colBase + row;
            if (gn < Nc) cp16(db, Bhi + (size_t)gn * KTOT + kb + chn * 8);
            else         zero16(db);
        }
        asm volatile("cp.async.commit_group;" ::: "memory");
    };

    const uint32_t aRowIdx = (uint32_t)(lane & 15);
    const uint32_t aK16    = (uint32_t)((lane >> 4) << 4);
    const uint32_t bRowIdx = (uint32_t)((lane & 7) + ((lane >> 4) << 3));
    const uint32_t bK16    = (uint32_t)(((lane >> 3) & 1) << 4);

    load_slab(0, 0);

    for (int c = 0; c < CHUNKS; c++) {
        if (c + 1 < CHUNKS) {
            load_slab((c + 1) & 1, c + 1);
            asm volatile("cp.async.wait_group 1;" ::: "memory");
        } else {
            asm volatile("cp.async.wait_group 0;" ::: "memory");
        }
        __syncthreads();

        uint32_t bA = sb + (c & 1) * STG;
        uint32_t bB = bA + ASZ;
        #pragma unroll
        for (int ks = 0; ks < 4; ks++) {
            uint32_t ah[2][4], al[2][4], bh[4][2];
            #pragma unroll
            for (int mi = 0; mi < 2; mi++) {
                uint32_t row = wm * 32 + mi * 16 + aRowIdx;
                uint32_t cb = (uint32_t)(ks * 32) + aK16;
                uint32_t off = row * 128 + (cb ^ ((row & 7) << 4));
                ldsm4(ah[mi], bA + off);
                if (NPROD == 2) ldsm4(al[mi], bA + 16384 + off);
            }
            #pragma unroll
            for (int pr = 0; pr < 2; pr++) {
                uint32_t row = wn * 32 + pr * 16 + bRowIdx;
                uint32_t cb = (uint32_t)(ks * 32) + bK16;
                uint32_t off = row * 128 + (cb ^ ((row & 7) << 4));
                uint32_t t[4];
                ldsm4(t, bB + off);
                bh[pr*2][0] = t[0]; bh[pr*2][1] = t[1];
                bh[pr*2+1][0] = t[2]; bh[pr*2+1][1] = t[3];
            }
            #pragma unroll
            for (int mi = 0; mi < 2; mi++)
                #pragma unroll
                for (int ni = 0; ni < 4; ni++) {
                    mma16816(acc[mi][ni], ah[mi], bh[ni]);
                    if (NPROD == 2) mma16816(acc[mi][ni], al[mi], bh[ni]);
                }
        }
        if (c + 1 < CHUNKS) __syncthreads();
    }

    const int group = lane >> 2;
    const int qc    = (lane & 3) * 2;
    #pragma unroll
    for (int mi = 0; mi < 2; mi++) {
        int r0 = rowBase + wm * 32 + mi * 16 + group;
        int r1 = r0 + 8;
        #pragma unroll
        for (int ni = 0; ni < 4; ni++) {
            int c = colBase + wn * 32 + ni * 8 + qc;
            if (c >= Nc) continue;
            float b0 = __ldg(&bias[c]), b1 = __ldg(&bias[c + 1]);
            float2 v0, v1;
            v0.x = acc[mi][ni][0] + b0; v0.y = acc[mi][ni][1] + b1;
            v1.x = acc[mi][ni][2] + b0; v1.y = acc[mi][ni][3] + b1;
            if (EPI == 1) {
                v0.x = fmaxf(v0.x, 0.f); v0.y = fmaxf(v0.y, 0.f);
                v1.x = fmaxf(v1.x, 0.f); v1.y = fmaxf(v1.y, 0.f);
            }
            if (r0 < NN) {
                if (OUTMODE == 0) *(float2*)(Cf + (size_t)r0 * Nc + c) = v0;
                else if (OUTMODE == 1) {
                    *(uint32_t*)(Ch + (size_t)r0 * Nc + c) = pack2(v0.x, v0.y);
                } else {
                    uint32_t h, l; split2(v0.x, v0.y, h, l);
                    *(uint32_t*)(Ch + (size_t)r0 * Nc + c) = h;
                    *(uint32_t*)(Cl + (size_t)r0 * Nc + c) = l;
                }
            }
            if (r1 < NN) {
                if (OUTMODE == 0) *(float2*)(Cf + (size_t)r1 * Nc + c) = v1;
                else if (OUTMODE == 1) {
                    *(uint32_t*)(Ch + (size_t)r1 * Nc + c) = pack2(v1.x, v1.y);
                } else {
                    uint32_t h, l; split2(v1.x, v1.y, h, l);
                    *(uint32_t*)(Ch + (size_t)r1 * Nc + c) = h;
                    *(uint32_t*)(Cl + (size_t)r1 * Nc + c) = l;
                }
            }
        }
    }
}

// ---------------------------------------------------------------------------
extern "C" void kernel_launch(void* const* d_in, const int* in_sizes, int n_in,
                              void* d_out, int out_size) {
    const float* x_in   = (const float*)d_in[0];
    const float* eattr  = (const float*)d_in[1];
    const int*   eidx   = (const int*)  d_in[2];
    const float* node_W = (const float*)d_in[3];
    const float* node_b = (const float*)d_in[4];
    const float* edge_W = (const float*)d_in[5];
    const float* edge_b = (const float*)d_in[6];
    const float* W1     = (const float*)d_in[7];
    const float* b1     = (const float*)d_in[8];
    const float* W2     = (const float*)d_in[9];
    const float* b2     = (const float*)d_in[10];
    const float* eps    = (const float*)d_in[11];
    const float* lin_W  = (const float*)d_in[12];
    const float* lin_b  = (const float*)d_in[13];
    float* out = (float*)d_out;

    float *pseg, *pinv;
    int *pdegi, *prowptr, *pcursor, *pbsum, *pboff, *pcsrc;
    __half *pwh, *pch, *ph1h, *pxh, *pxl, *peamh, *peaml;
    cudaGetSymbolAddress((void**)&pseg, g_seg);
    cudaGetSymbolAddress((void**)&pinv, g_inv);
    cudaGetSymbolAddress((void**)&pdegi, g_degi);
    cudaGetSymbolAddress((void**)&prowptr, g_rowptr);
    cudaGetSymbolAddress((void**)&pcursor, g_cursor);
    cudaGetSymbolAddress((void**)&pbsum, g_bsum);
    cudaGetSymbolAddress((void**)&pboff, g_boff);
    cudaGetSymbolAddress((void**)&pcsrc, g_csrc);
    cudaGetSymbolAddress((void**)&pwh,  g_whi);
    cudaGetSymbolAddress((void**)&pch,  g_ch);
    cudaGetSymbolAddress((void**)&ph1h, g_h1h);
    cudaGetSymbolAddress((void**)&pxh,  g_xh);
    cudaGetSymbolAddress((void**)&pxl,  g_xl);
    cudaGetSymbolAddress((void**)&peamh, g_eamh);
    cudaGetSymbolAddress((void**)&peaml, g_eaml);

    constexpr int SM_F32A = 46080;
    constexpr int SM_HF1  = 49152;   // single product: 2*(16K+8K)
    constexpr int SM_HF2  = 81920;   // dual product: 2*(32K+8K)
    auto setsm = [](const void* f, int b) {
        cudaFuncSetAttribute(f, cudaFuncAttributeMaxDynamicSharedMemorySize, b);
    };
    setsm((const void*)gemm_f32a<128, 0>, SM_F32A);
    setsm((const void*)gemm_f32a< 64, 2>, SM_F32A);
    setsm((const void*)gemm_hf<128, 1, 1, 1>, SM_HF1);
    setsm((const void*)gemm_hf<256, 1, 2, 1>, SM_HF1);
    setsm((const void*)gemm_hf<128, 0, 0, 2>, SM_HF2);

    // ---- front: weight prep + degree histogram (fused) ----
    cudaMemsetAsync(pdegi, 0, NN * sizeof(int));
    cudaMemsetAsync(pseg, 0, (size_t)NN * IN_EDGE * sizeof(float));
    front_kernel<<<920 + 2442, 256>>>(node_W, edge_W, W1, W2, lin_W, pwh,
                                      eidx, pdegi);

    // ---- seg scatter: seg[dst] += edge_attr[e] ----
    seg_scatter<<<(EE * 16 + 255) / 256, 256>>>(eattr, eidx, pseg);

    // ---- CSR build ----
    scan1<<<NB, 256>>>(pdegi, pbsum);
    scan2<<<1, 256>>>(pbsum, pboff, prowptr + NN);
    scan3<<<NB, 256>>>(pdegi, pboff, prowptr, pcursor, pinv);
    csr_fill<<<(EE + 255) / 256, 256>>>(eidx, pcursor, pcsrc);

    dim3 g2(TILES_M, 2), g4(TILES_M, 4);

    // node encoder: x(split) = x_in @ node_W + node_b
    gemm_f32a<128, 0><<<g2, 256, SM_F32A>>>(x_in, pwh, node_b,
        pxh, pxl, HH, nullptr, nullptr);
    // edge agg through encoder: eam(split) = (seg @ edge_W)*inv + [deg>0]*edge_b
    gemm_f32a<64, 2><<<g2, 256, SM_F32A>>>(pseg, pwh + 16384, edge_b,
        peamh, peaml, HH, pinv, pdegi);

    for (int l = 0; l < 3; l++) {
        gather_combine<<<(NN * 32 + 255) / 256, 256>>>(prowptr, pcsrc, pxh, pxl,
            peamh, peaml, pinv, eps, l, pch);
        // h1(hi) = relu( c @ W1[l] + b1[l] )    — single-product fp16
        gemm_hf<128, 1, 1, 1><<<g4, 256, SM_HF1>>>(pch, nullptr,
            pwh + 24576 + l * 32768,
            b1 + (size_t)l * HH2, nullptr, ph1h, nullptr, HH2);
        // x(split) = relu( h1 @ W2[l] + b2[l] ) — single-product fp16
        gemm_hf<256, 1, 2, 1><<<g2, 256, SM_HF1>>>(ph1h, nullptr,
            pwh + 122880 + l * 32768,
            b2 + (size_t)l * HH, nullptr, pxh, pxl, HH);
    }

    // head: out = x @ lin_W + lin_b  — dual product (xh + xl), fp32 out
    gemm_hf<128, 0, 0, 2><<<g2, 256, SM_HF2>>>(pxh, pxl, pwh + 221184,
        lin_b, out, nullptr, nullptr, OUTD);
}

// round 11
// speedup vs baseline: 2.2118x; 1.1251x over previous
#include <cuda_runtime.h>
#include <cuda_fp16.h>
#include <cstdint>

#define NN     50000
#define EE     625000
#define IN_EDGE 64
#define HH     128
#define HH2    256
#define OUTD   112
#define TILES_M 391   // ceil(50000/128)
#define NBM    782    // ceil(50000/64)
#define NB     196    // ceil(50000/256)

// ---------------- scratch (device globals; no allocation allowed) ----------
__device__ __align__(16) float g_seg[NN * IN_EDGE];
__device__ float g_inv[NN];
__device__ int   g_degi[NN];
__device__ int   g_rowptr[NN + 1];
__device__ int   g_cursor[NN];
__device__ int   g_bflag[NB];      // lookback: aggregate+1 (0 = not ready)
__device__ int   g_csrc[EE];

// activations
__device__ __align__(16) __half g_ch  [NN * HH];    // combined (hi), W1 input
__device__ __align__(16) __half g_xh  [NN * HH];    // node state (split hi)
__device__ __align__(16) __half g_xl  [NN * HH];    // node state (split lo)
__device__ __align__(16) __half g_eamh[NN * HH];    // edge-agg-mean (split)
__device__ __align__(16) __half g_eaml[NN * HH];

// pre-rounded transposed weights, layout [N][K] fp16
__device__ __align__(16) __half g_whi[235520];

// ---------------------------------------------------------------------------
__device__ __forceinline__ uint32_t smem_u32(const void* p) {
    uint32_t a;
    asm("{ .reg .u64 t; cvta.to.shared.u64 t, %1; cvt.u32.u64 %0, t; }"
        : "=r"(a) : "l"(p));
    return a;
}
__device__ __forceinline__ void cp16(uint32_t dst, const void* src) {
    asm volatile("cp.async.cg.shared.global [%0], [%1], 16;"
                 :: "r"(dst), "l"(src) : "memory");
}
__device__ __forceinline__ void zero16(uint32_t dst) {
    asm volatile("st.shared.v4.b32 [%0], {%1,%1,%1,%1};" :: "r"(dst), "r"(0) : "memory");
}
__device__ __forceinline__ void ldsm4(uint32_t* r, uint32_t addr) {
    asm volatile("ldmatrix.sync.aligned.m8n8.x4.shared.b16 {%0,%1,%2,%3}, [%4];"
                 : "=r"(r[0]), "=r"(r[1]), "=r"(r[2]), "=r"(r[3]) : "r"(addr));
}
__device__ __forceinline__ void mma16816(float* d, const uint32_t* a, const uint32_t* b) {
    asm volatile("mma.sync.aligned.m16n8k16.row.col.f32.f16.f16.f32 "
                 "{%0,%1,%2,%3}, {%4,%5,%6,%7}, {%8,%9}, {%0,%1,%2,%3};"
                 : "+f"(d[0]), "+f"(d[1]), "+f"(d[2]), "+f"(d[3])
                 : "r"(a[0]), "r"(a[1]), "r"(a[2]), "r"(a[3]), "r"(b[0]), "r"(b[1]));
}
__device__ __forceinline__ void split2(float a, float b, uint32_t& hi, uint32_t& lo) {
    __half ha = __float2half(a), hb = __float2half(b);
    __half2 h = __halves2half2(ha, hb);
    __half2 l = __halves2half2(
        __float2half(a - __half2float(ha)),
        __float2half(b - __half2float(hb)));
    hi = *(uint32_t*)&h; lo = *(uint32_t*)&l;
}
__device__ __forceinline__ uint32_t pack2(float a, float b) {
    __half2 h = __halves2half2(__float2half(a), __float2half(b));
    return *(uint32_t*)&h;
}
__device__ __forceinline__ float2 unpack2(uint32_t h, uint32_t l) {
    __half2 hh = *(__half2*)&h;
    __half2 ll = *(__half2*)&l;
    return make_float2(__low2float(hh) + __low2float(ll),
                       __high2float(hh) + __high2float(ll));
}
__device__ __forceinline__ void red_add_v4(float* addr, float4 v) {
    asm volatile("red.global.add.v4.f32 [%0], {%1,%2,%3,%4};"
                 :: "l"(addr), "f"(v.x), "f"(v.y), "f"(v.z), "f"(v.w) : "memory");
}

// ---------------------------------------------------------------------------
// front: weight prep + degree histogram + seg scatter (all independent)
// ---------------------------------------------------------------------------
#define FB_W   920
#define FB_DEG 2442
#define FB_SEG 39063
__global__ void front_kernel(const float* __restrict__ node_W, const float* __restrict__ edge_W,
                             const float* __restrict__ W1, const float* __restrict__ W2,
                             const float* __restrict__ lin_W,
                             __half* __restrict__ hi,
                             const int* __restrict__ ei, int* __restrict__ degi,
                             const float* __restrict__ ea, float* __restrict__ seg) {
    if (blockIdx.x < FB_W) {
        int i = blockIdx.x * 256 + threadIdx.x;
        if (i >= 235520) return;
        const float* src; int K, Nc, idx;
        if (i < 16384)       { src = node_W;                 K = 128; Nc = 128; idx = i; }
        else if (i < 24576)  { src = edge_W;                 K =  64; Nc = 128; idx = i - 16384; }
        else if (i < 122880) { int j = i - 24576;  src = W1 + (j / 32768) * 32768; K = 128; Nc = 256; idx = j % 32768; }
        else if (i < 221184) { int j = i - 122880; src = W2 + (j / 32768) * 32768; K = 256; Nc = 128; idx = j % 32768; }
        else                 { src = lin_W;                  K = 128; Nc = 112; idx = i - 221184; }
        int n = idx / K, k = idx % K;
        hi[i] = __float2half(__ldg(&src[(size_t)k * Nc + n]));
    } else if (blockIdx.x < FB_W + FB_DEG) {
        int e = (blockIdx.x - FB_W) * 256 + threadIdx.x;
        if (e < EE) atomicAdd(&degi[ei[EE + e]], 1);
    } else {
        int gid = (blockIdx.x - FB_W - FB_DEG) * 256 + threadIdx.x;
        if (gid >= EE * 16) return;
        int e = gid >> 4, g = gid & 15;
        int dst = __ldg(&ei[EE + e]);
        float4 v = __ldg(((const float4*)ea) + (size_t)e * 16 + g);
        red_add_v4(seg + (size_t)dst * IN_EDGE + g * 4, v);
    }
}

// ---------------------------------------------------------------------------
// single-kernel exclusive scan (decoupled lookback over 196 blocks)
// ---------------------------------------------------------------------------
__global__ void scan_fused(const int* __restrict__ d, int* __restrict__ bflag,
                           int* __restrict__ rowptr, int* __restrict__ cursor,
                           float* __restrict__ inv) {
    __shared__ int s[256];
    __shared__ int sred[256];
    int b = blockIdx.x;
    int t = threadIdx.x;
    int i = b * 256 + t;
    int v = (i < NN) ? d[i] : 0;
    s[t] = v;
    __syncthreads();
    #pragma unroll
    for (int o = 1; o < 256; o <<= 1) {
        int tv = (t >= o) ? s[t - o] : 0;
        __syncthreads();
        s[t] += tv;
        __syncthreads();
    }
    int incl = s[t];
    int agg = s[255];
    if (t == 0) atomicExch(&bflag[b], agg + 1);   // publish (value in flag word)
    // lookback: thread t polls block t (b <= 195 < 256)
    int pval = 0;
    if (t < b) {
        int x;
        do { x = atomicAdd(&bflag[t], 0); } while (x == 0);
        pval = x - 1;
    }
    sred[t] = pval;
    __syncthreads();
    #pragma unroll
    for (int o = 128; o > 0; o >>= 1) {
        if (t < o) sred[t] += sred[t + o];
        __syncthreads();
    }
    int boffv = sred[0];
    if (i < NN) {
        int excl = incl - v + boffv;
        rowptr[i] = excl;
        cursor[i] = excl;
        inv[i] = 1.0f / (float)max(v, 1);
    }
    if (b == NB - 1 && t == 255) rowptr[NN] = boffv + agg;
}

__global__ void csr_fill(const int* __restrict__ ei, int* __restrict__ cursor,
                         int* __restrict__ csrc) {
    int e = blockIdx.x * blockDim.x + threadIdx.x;
    if (e >= EE) return;
    int dst = __ldg(&ei[EE + e]);
    int p = atomicAdd(&cursor[dst], 1);
    csrc[p] = __ldg(&ei[e]);
}

// fused: agg = sum_neighbors(x_hi) ; c = (1+eps)*x + agg*inv + eam -> ch (fp16 hi)
__global__ void gather_combine(const int* __restrict__ rowptr, const int* __restrict__ csrc,
                               const __half* __restrict__ xh,
                               const __half* __restrict__ xl,
                               const __half* __restrict__ eamh,
                               const __half* __restrict__ eaml,
                               const float* __restrict__ inv,
                               const float* __restrict__ eps_p, int layer,
                               __half* __restrict__ ch) {
    int w = (blockIdx.x * blockDim.x + threadIdx.x) >> 5;
    if (w >= NN) return;
    int lane = threadIdx.x & 31;
    int beg = __ldg(&rowptr[w]), end = __ldg(&rowptr[w + 1]);
    float a0 = 0.f, a1 = 0.f, a2 = 0.f, a3 = 0.f;
    for (int j = beg; j < end; j++) {
        int s = __ldg(&csrc[j]);
        uint2 hv = __ldg((const uint2*)(xh + (size_t)s * HH) + lane);
        __half2 h0 = *(__half2*)&hv.x;
        __half2 h1 = *(__half2*)&hv.y;
        a0 += __low2float(h0); a1 += __high2float(h0);
        a2 += __low2float(h1); a3 += __high2float(h1);
    }
    float iv = __ldg(&inv[w]);
    float epsv = 1.f + __ldg(&eps_p[layer]);
    uint2 hs = __ldg((const uint2*)(xh + (size_t)w * HH) + lane);
    uint2 ls = __ldg((const uint2*)(xl + (size_t)w * HH) + lane);
    float2 x01 = unpack2(hs.x, ls.x);
    float2 x23 = unpack2(hs.y, ls.y);
    uint2 eh = __ldg((const uint2*)(eamh + (size_t)w * HH) + lane);
    uint2 el = __ldg((const uint2*)(eaml + (size_t)w * HH) + lane);
    float2 e01 = unpack2(eh.x, el.x);
    float2 e23 = unpack2(eh.y, el.y);
    uint2 h;
    h.x = pack2(epsv * x01.x + a0 * iv + e01.x, epsv * x01.y + a1 * iv + e01.y);
    h.y = pack2(epsv * x23.x + a2 * iv + e23.x, epsv * x23.y + a3 * iv + e23.y);
    *(uint2*)(ch + (size_t)w * HH + lane * 4) = h;
}

// ---------------------------------------------------------------------------
// Fused GIN MLP: x = relu( relu(c @ W1 + b1) @ W2 + b2 )  — h1 stays in smem.
// BM=64, 128 threads (4 warps, warp tile 32x32), 3 CTAs/SM.
// smem: c 16K (rows 256B) | h1 32K (rows 512B) | B 2x8K
// ---------------------------------------------------------------------------
__global__ void __launch_bounds__(128, 3)
mlp_fused(const __half* __restrict__ C, const __half* __restrict__ W1h,
          const float* __restrict__ b1, const __half* __restrict__ W2h,
          const float* __restrict__ b2,
          __half* __restrict__ Xh, __half* __restrict__ Xl) {
    extern __shared__ char smem[];
    const uint32_t sC = smem_u32(smem);
    const uint32_t sH = sC + 16384;
    const uint32_t sB = sC + 49152;

    const int tid  = threadIdx.x;
    const int lane = tid & 31;
    const int wid  = tid >> 5;     // 0..3
    const int wm   = wid & 1;
    const int wn   = wid >> 1;
    const int rowBase = blockIdx.x * 64;

    // load c tile 64x128 fp16, row stride 256B, swizzled
    #pragma unroll
    for (int i = 0; i < 8; i++) {
        int f = tid + i * 128;
        int row = f >> 4, chn = f & 15;
        uint32_t addr = sC + row * 256 + (((uint32_t)(chn * 16)) ^ ((row & 7) << 4));
        int gr = rowBase + row;
        if (gr < NN) cp16(addr, C + (size_t)gr * HH + chn * 8);
        else         zero16(addr);
    }
    asm volatile("cp.async.commit_group;" ::: "memory");

    const uint32_t aRowIdx = (uint32_t)(lane & 15);
    const uint32_t aK16    = (uint32_t)((lane >> 4) << 4);
    const uint32_t bRowIdx = (uint32_t)((lane & 7) + ((lane >> 4) << 3));
    const uint32_t bK16    = (uint32_t)(((lane >> 3) & 1) << 4);
    const int group = lane >> 2;
    const int qc    = (lane & 3) * 2;

    float acc[2][4][4];

    auto loadB = [&](const __half* W, int KT, int gn0, int kb, int stage) {
        #pragma unroll
        for (int i = 0; i < 4; i++) {
            int f = tid + i * 128;
            int row = f >> 3, chn = f & 7;
            uint32_t addr = sB + stage * 8192 + row * 128 +
                            (((uint32_t)(chn * 16)) ^ ((row & 7) << 4));
            cp16(addr, W + (size_t)(gn0 + row) * KT + kb + chn * 8);
        }
        asm volatile("cp.async.commit_group;" ::: "memory");
    };
    auto zacc = [&]() {
        #pragma unroll
        for (int a = 0; a < 2; a++)
            #pragma unroll
            for (int b = 0; b < 4; b++)
                #pragma unroll
                for (int c = 0; c < 4; c++) acc[a][b][c] = 0.f;
    };

    // ---------- phase 1: h1(smem) = relu(c @ W1 + b1), N=256, K=128 ----------
    loadB(W1h, 128, 0, 0, 0);
    for (int t = 0; t < 8; t++) {            // t = cp*2 + kc
        int cp = t >> 1, kc = t & 1;
        if (t + 1 < 8) {
            loadB(W1h, 128, ((t + 1) >> 1) * 64, ((t + 1) & 1) * 64, (t + 1) & 1);
            asm volatile("cp.async.wait_group 1;" ::: "memory");
        } else {
            asm volatile("cp.async.wait_group 0;" ::: "memory");
        }
        __syncthreads();
        if (kc == 0) zacc();
        uint32_t bBuf = sB + (t & 1) * 8192;
        #pragma unroll
        for (int ks = 0; ks < 4; ks++) {
            uint32_t ah[2][4], bh[4][2];
            #pragma unroll
            for (int mi = 0; mi < 2; mi++) {
                uint32_t row = wm * 32 + mi * 16 + aRowIdx;
                uint32_t cb = (uint32_t)(kc * 128 + ks * 32) + aK16;
                ldsm4(ah[mi], sC + row * 256 + (cb ^ ((row & 7) << 4)));
            }
            #pragma unroll
            for (int pr = 0; pr < 2; pr++) {
                uint32_t row = wn * 32 + pr * 16 + bRowIdx;
                uint32_t cb = (uint32_t)(ks * 32) + bK16;
                uint32_t tr[4];
                ldsm4(tr, bBuf + row * 128 + (cb ^ ((row & 7) << 4)));
                bh[pr*2][0] = tr[0]; bh[pr*2][1] = tr[1];
                bh[pr*2+1][0] = tr[2]; bh[pr*2+1][1] = tr[3];
            }
            #pragma unroll
            for (int mi = 0; mi < 2; mi++)
                #pragma unroll
                for (int ni = 0; ni < 4; ni++)
                    mma16816(acc[mi][ni], ah[mi], bh[ni]);
        }
        if (kc == 1) {
            #pragma unroll
            for (int mi = 0; mi < 2; mi++) {
                int r0 = wm * 32 + mi * 16 + group;
                int r1 = r0 + 8;
                #pragma unroll
                for (int ni = 0; ni < 4; ni++) {
                    int c = cp * 64 + wn * 32 + ni * 8 + qc;
                    float bv0 = __ldg(&b1[c]), bv1 = __ldg(&b1[c + 1]);
                    uint32_t p0 = pack2(fmaxf(acc[mi][ni][0] + bv0, 0.f),
                                        fmaxf(acc[mi][ni][1] + bv1, 0.f));
                    uint32_t p1 = pack2(fmaxf(acc[mi][ni][2] + bv0, 0.f),
                                        fmaxf(acc[mi][ni][3] + bv1, 0.f));
                    uint32_t cb = (uint32_t)(c * 2);
                    uint32_t a0 = sH + r0 * 512 + (cb ^ ((r0 & 7) << 4));
                    uint32_t a1 = sH + r1 * 512 + (cb ^ ((r1 & 7) << 4));
                    asm volatile("st.shared.b32 [%0], %1;" :: "r"(a0), "r"(p0) : "memory");
                    asm volatile("st.shared.b32 [%0], %1;" :: "r"(a1), "r"(p1) : "memory");
                }
            }
        }
        __syncthreads();
    }

    // ---------- phase 2: x(split) = relu(h1 @ W2 + b2), N=128, K=256 ----------
    loadB(W2h, 256, 0, 0, 0);
    for (int t = 0; t < 8; t++) {            // t = cp*4 + kc
        int cp = t >> 2, kc = t & 3;
        if (t + 1 < 8) {
            loadB(W2h, 256, ((t + 1) >> 2) * 64, ((t + 1) & 3) * 64, (t + 1) & 1);
            asm volatile("cp.async.wait_group 1;" ::: "memory");
        } else {
            asm volatile("cp.async.wait_group 0;" ::: "memory");
        }
        __syncthreads();
        if (kc == 0) zacc();
        uint32_t bBuf = sB + (t & 1) * 8192;
        #pragma unroll
        for (int ks = 0; ks < 4; ks++) {
            uint32_t ah[2][4], bh[4][2];
            #pragma unroll
            for (int mi = 0; mi < 2; mi++) {
                uint32_t row = wm * 32 + mi * 16 + aRowIdx;
                uint32_t cb = (uint32_t)(kc * 128 + ks * 32) + aK16;
                ldsm4(ah[mi], sH + row * 512 + (cb ^ ((row & 7) << 4)));
            }
            #pragma unroll
            for (int pr = 0; pr < 2; pr++) {
                uint32_t row = wn * 32 + pr * 16 + bRowIdx;
                uint32_t cb = (uint32_t)(ks * 32) + bK16;
                uint32_t tr[4];
                ldsm4(tr, bBuf + row * 128 + (cb ^ ((row & 7) << 4)));
                bh[pr*2][0] = tr[0]; bh[pr*2][1] = tr[1];
                bh[pr*2+1][0] = tr[2]; bh[pr*2+1][1] = tr[3];
            }
            #pragma unroll
            for (int mi = 0; mi < 2; mi++)
                #pragma unroll
                for (int ni = 0; ni < 4; ni++)
                    mma16816(acc[mi][ni], ah[mi], bh[ni]);
        }
        if (kc == 3) {
            #pragma unroll
            for (int mi = 0; mi < 2; mi++) {
                int r0 = rowBase + wm * 32 + mi * 16 + group;
                int r1 = r0 + 8;
                #pragma unroll
                for (int ni = 0; ni < 4; ni++) {
                    int c = cp * 64 + wn * 32 + ni * 8 + qc;
                    float bv0 = __ldg(&b2[c]), bv1 = __ldg(&b2[c + 1]);
                    float v00 = fmaxf(acc[mi][ni][0] + bv0, 0.f);
                    float v01 = fmaxf(acc[mi][ni][1] + bv1, 0.f);
                    float v10 = fmaxf(acc[mi][ni][2] + bv0, 0.f);
                    float v11 = fmaxf(acc[mi][ni][3] + bv1, 0.f);
                    if (r0 < NN) {
                        uint32_t h, l; split2(v00, v01, h, l);
                        *(uint32_t*)(Xh + (size_t)r0 * HH + c) = h;
                        *(uint32_t*)(Xl + (size_t)r0 * HH + c) = l;
                    }
                    if (r1 < NN) {
                        uint32_t h, l; split2(v10, v11, h, l);
                        *(uint32_t*)(Xh + (size_t)r1 * HH + c) = h;
                        *(uint32_t*)(Xl + (size_t)r1 * HH + c) = l;
                    }
                }
            }
        }
        __syncthreads();
    }
}

// ---------------------------------------------------------------------------
// GEMM with fp32-A conversion loader (node & edge encoders). B = fp16 hi only.
// D = (Ah+Al) @ Bh.  EPI: 0 = +bias; 2 = *inv + [deg>0]*bias.  Out: fp16 split.
// ---------------------------------------------------------------------------
#define ROWB 144
template <int KTOT, int EPI>
__global__ void __launch_bounds__(256, 2)
gemm_f32a(const float* __restrict__ A, const __half* __restrict__ Bhi,
          const float* __restrict__ bias,
          __half* __restrict__ Ch, __half* __restrict__ Cl, int Nc,
          const float* __restrict__ inv, const int* __restrict__ degi) {
    extern __shared__ char smem[];
    const uint32_t sb  = smem_u32(smem);
    const uint32_t sAh = sb, sAl = sb + 18432, sBh = sb + 36864;

    const int tid  = threadIdx.x;
    const int lane = tid & 31;
    const int wid  = tid >> 5;
    const int wm   = wid & 3;
    const int wn   = wid >> 2;
    const int rowBase = blockIdx.x * 128;
    const int colBase = blockIdx.y * 64;

    float acc[2][4][4];
    #pragma unroll
    for (int a = 0; a < 2; a++)
        #pragma unroll
        for (int b = 0; b < 4; b++)
            #pragma unroll
            for (int c = 0; c < 4; c++) acc[a][b][c] = 0.f;

    const uint32_t aRow  = (uint32_t)(lane & 15);
    const uint32_t aKoff = (uint32_t)((lane >> 4) << 3);
    const uint32_t bRow  = (uint32_t)((lane & 7) + ((lane >> 4) << 3));
    const uint32_t bKoff = (uint32_t)(((lane >> 3) & 1) << 3);

    for (int kb = 0; kb < KTOT; kb += 64) {
        if (kb) __syncthreads();
        #pragma unroll
        for (int i = 0; i < 2; i++) {
            int f = tid + i * 256;
            int nrow = f >> 3, chunk = f & 7;
            uint32_t dh = sBh + nrow * ROWB + chunk * 16;
            int gn = colBase + nrow;
            if (gn < Nc) cp16(dh, Bhi + (size_t)gn * KTOT + kb + chunk * 8);
            else         zero16(dh);
        }
        asm volatile("cp.async.commit_group;" ::: "memory");

        #pragma unroll
        for (int i = 0; i < 8; i++) {
            int f = tid + i * 256;
            int row = f >> 4;
            int c4  = f & 15;
            int gr = rowBase + row;
            float4 v = make_float4(0.f, 0.f, 0.f, 0.f);
            if (gr < NN) v = __ldg((const float4*)(A + (size_t)gr * KTOT + kb + c4 * 4));
            uint32_t h01, h23, l01, l23;
            split2(v.x, v.y, h01, l01);
            split2(v.z, v.w, h23, l23);
            uint32_t addr = row * ROWB + c4 * 8;
            asm volatile("st.shared.v2.b32 [%0], {%1,%2};"
                         :: "r"(sAh + addr), "r"(h01), "r"(h23) : "memory");
            asm volatile("st.shared.v2.b32 [%0], {%1,%2};"
                         :: "r"(sAl + addr), "r"(l01), "r"(l23) : "memory");
        }
        asm volatile("cp.async.wait_group 0;" ::: "memory");
        __syncthreads();

        #pragma unroll
        for (int ks = 0; ks < 4; ks++) {
            uint32_t ah[2][4], al[2][4], bh[4][2];
            #pragma unroll
            for (int mi = 0; mi < 2; mi++) {
                uint32_t off = (wm * 32 + mi * 16 + aRow) * ROWB + (ks * 16 + aKoff) * 2;
                ldsm4(ah[mi], sAh + off);
                ldsm4(al[mi], sAl + off);
            }
            #pragma unroll
            for (int pr = 0; pr < 2; pr++) {
                uint32_t off = (wn * 32 + pr * 16 + bRow) * ROWB + (ks * 16 + bKoff) * 2;
                uint32_t t[4];
                ldsm4(t, sBh + off);
                bh[pr*2][0] = t[0]; bh[pr*2][1] = t[1];
                bh[pr*2+1][0] = t[2]; bh[pr*2+1][1] = t[3];
            }
            #pragma unroll
            for (int mi = 0; mi < 2; mi++)
                #pragma unroll
                for (int ni = 0; ni < 4; ni++) {
                    mma16816(acc[mi][ni], ah[mi], bh[ni]);
                    mma16816(acc[mi][ni], al[mi], bh[ni]);
                }
        }
    }

    const int group = lane >> 2;
    const int qc    = (lane & 3) * 2;
    #pragma unroll
    for (int mi = 0; mi < 2; mi++) {
        int r0 = rowBase + wm * 32 + mi * 16 + group;
        int r1 = r0 + 8;
        float iv0 = 0.f, m0 = 0.f, iv1 = 0.f, m1 = 0.f;
        if (EPI == 2) {
            if (r0 < NN) { iv0 = __ldg(&inv[r0]); m0 = (__ldg(&degi[r0]) > 0) ? 1.f : 0.f; }
            if (r1 < NN) { iv1 = __ldg(&inv[r1]); m1 = (__ldg(&degi[r1]) > 0) ? 1.f : 0.f; }
        }
        #pragma unroll
        for (int ni = 0; ni < 4; ni++) {
            int c = colBase + wn * 32 + ni * 8 + qc;
            if (c >= Nc) continue;
            float b0 = __ldg(&bias[c]), b1 = __ldg(&bias[c + 1]);
            float2 v0, v1;
            if (EPI == 2) {
                v0.x = acc[mi][ni][0] * iv0 + m0 * b0;
                v0.y = acc[mi][ni][1] * iv0 + m0 * b1;
                v1.x = acc[mi][ni][2] * iv1 + m1 * b0;
                v1.y = acc[mi][ni][3] * iv1 + m1 * b1;
            } else {
                v0.x = acc[mi][ni][0] + b0; v0.y = acc[mi][ni][1] + b1;
                v1.x = acc[mi][ni][2] + b0; v1.y = acc[mi][ni][3] + b1;
            }
            if (r0 < NN) {
                uint32_t h, l; split2(v0.x, v0.y, h, l);
                *(uint32_t*)(Ch + (size_t)r0 * Nc + c) = h;
                *(uint32_t*)(Cl + (size_t)r0 * Nc + c) = l;
            }
            if (r1 < NN) {
                uint32_t h, l; split2(v1.x, v1.y, h, l);
                *(uint32_t*)(Ch + (size_t)r1 * Nc + c) = h;
                *(uint32_t*)(Cl + (size_t)r1 * Nc + c) = l;
            }
        }
    }
}

// ---------------------------------------------------------------------------
// Head GEMM: out(fp32) = (xh + xl) @ lin_W + lin_b  (dual product)
// ---------------------------------------------------------------------------
__global__ void __launch_bounds__(256, 2)
gemm_head(const __half* __restrict__ Ah, const __half* __restrict__ Al,
          const __half* __restrict__ Bhi,
          const float* __restrict__ bias, float* __restrict__ Cf, int Nc) {
    constexpr int KTOT = 128;
    constexpr int STG = 40960;
    extern __shared__ char smem[];
    const uint32_t sb = smem_u32(smem);

    const int tid  = threadIdx.x;
    const int lane = tid & 31;
    const int wid  = tid >> 5;
    const int wm   = wid & 3;
    const int wn   = wid >> 2;
    const int rowBase = blockIdx.x * 128;
    const int colBase = blockIdx.y * 64;

    float acc[2][4][4];
    #pragma unroll
    for (int a = 0; a < 2; a++)
        #pragma unroll
        for (int b = 0; b < 4; b++)
            #pragma unroll
            for (int c = 0; c < 4; c++) acc[a][b][c] = 0.f;

    auto load_slab = [&](int stage, int c) {
        uint32_t base = sb + stage * STG;
        int kb = c * 64;
        #pragma unroll
        for (int i = 0; i < 4; i++) {
            int f = tid + i * 256;
            int row = f >> 3, chn = f & 7;
            uint32_t sw = (uint32_t)(chn * 16) ^ (uint32_t)((row & 7) << 4);
            uint32_t da = base + row * 128 + sw;
            int gr = rowBase + row;
            if (gr < NN) {
                size_t off = (size_t)gr * KTOT + kb + chn * 8;
                cp16(da, Ah + off);
                cp16(da + 16384, Al + off);
            } else { zero16(da); zero16(da + 16384); }
        }
        #pragma unroll
        for (int i = 0; i < 2; i++) {
            int f = tid + i * 256;
            int row = f >> 3, chn = f & 7;
            uint32_t sw = (uint32_t)(chn * 16) ^ (uint32_t)((row & 7) << 4);
            uint32_t db = base + 32768 + row * 128 + sw;
            int gn = colBase + row;
            if (gn < Nc) cp16(db, Bhi + (size_t)gn * KTOT + kb + chn * 8);
            else         zero16(db);
        }
        asm volatile("cp.async.commit_group;" ::: "memory");
    };

    const uint32_t aRowIdx = (uint32_t)(lane & 15);
    const uint32_t aK16    = (uint32_t)((lane >> 4) << 4);
    const uint32_t bRowIdx = (uint32_t)((lane & 7) + ((lane >> 4) << 3));
    const uint32_t bK16    = (uint32_t)(((lane >> 3) & 1) << 4);

    load_slab(0, 0);
    for (int c = 0; c < 2; c++) {
        if (c + 1 < 2) {
            load_slab((c + 1) & 1, c + 1);
            asm volatile("cp.async.wait_group 1;" ::: "memory");
        } else {
            asm volatile("cp.async.wait_group 0;" ::: "memory");
        }
        __syncthreads();
        uint32_t bA = sb + (c & 1) * STG;
        uint32_t bB = bA + 32768;
        #pragma unroll
        for (int ks = 0; ks < 4; ks++) {
            uint32_t ah[2][4], al[2][4], bh[4][2];
            #pragma unroll
            for (int mi = 0; mi < 2; mi++) {
                uint32_t row = wm * 32 + mi * 16 + aRowIdx;
                uint32_t cb = (uint32_t)(ks * 32) + aK16;
                uint32_t off = row * 128 + (cb ^ ((row & 7) << 4));
                ldsm4(ah[mi], bA + off);
                ldsm4(al[mi], bA + 16384 + off);
            }
            #pragma unroll
            for (int pr = 0; pr < 2; pr++) {
                uint32_t row = wn * 32 + pr * 16 + bRowIdx;
                uint32_t cb = (uint32_t)(ks * 32) + bK16;
                uint32_t off = row * 128 + (cb ^ ((row & 7) << 4));
                uint32_t t[4];
                ldsm4(t, bB + off);
                bh[pr*2][0] = t[0]; bh[pr*2][1] = t[1];
                bh[pr*2+1][0] = t[2]; bh[pr*2+1][1] = t[3];
            }
            #pragma unroll
            for (int mi = 0; mi < 2; mi++)
                #pragma unroll
                for (int ni = 0; ni < 4; ni++) {
                    mma16816(acc[mi][ni], ah[mi], bh[ni]);
                    mma16816(acc[mi][ni], al[mi], bh[ni]);
                }
        }
        if (c + 1 < 2) __syncthreads();
    }

    const int group = lane >> 2;
    const int qc    = (lane & 3) * 2;
    #pragma unroll
    for (int mi = 0; mi < 2; mi++) {
        int r0 = rowBase + wm * 32 + mi * 16 + group;
        int r1 = r0 + 8;
        #pragma unroll
        for (int ni = 0; ni < 4; ni++) {
            int c = colBase + wn * 32 + ni * 8 + qc;
            if (c >= Nc) continue;
            float b0 = __ldg(&bias[c]), b1 = __ldg(&bias[c + 1]);
            if (r0 < NN) {
                float2 v0; v0.x = acc[mi][ni][0] + b0; v0.y = acc[mi][ni][1] + b1;
                *(float2*)(Cf + (size_t)r0 * Nc + c) = v0;
            }
            if (r1 < NN) {
                float2 v1; v1.x = acc[mi][ni][2] + b0; v1.y = acc[mi][ni][3] + b1;
                *(float2*)(Cf + (size_t)r1 * Nc + c) = v1;
            }
        }
    }
}

// ---------------------------------------------------------------------------
extern "C" void kernel_launch(void* const* d_in, const int* in_sizes, int n_in,
                              void* d_out, int out_size) {
    const float* x_in   = (const float*)d_in[0];
    const float* eattr  = (const float*)d_in[1];
    const int*   eidx   = (const int*)  d_in[2];
    const float* node_W = (const float*)d_in[3];
    const float* node_b = (const float*)d_in[4];
    const float* edge_W = (const float*)d_in[5];
    const float* edge_b = (const float*)d_in[6];
    const float* W1     = (const float*)d_in[7];
    const float* b1     = (const float*)d_in[8];
    const float* W2     = (const float*)d_in[9];
    const float* b2     = (const float*)d_in[10];
    const float* eps    = (const float*)d_in[11];
    const float* lin_W  = (const float*)d_in[12];
    const float* lin_b  = (const float*)d_in[13];
    float* out = (float*)d_out;

    float *pseg, *pinv;
    int *pdegi, *prowptr, *pcursor, *pbflag, *pcsrc;
    __half *pwh, *pch, *pxh, *pxl, *peamh, *peaml;
    cudaGetSymbolAddress((void**)&pseg, g_seg);
    cudaGetSymbolAddress((void**)&pinv, g_inv);
    cudaGetSymbolAddress((void**)&pdegi, g_degi);
    cudaGetSymbolAddress((void**)&prowptr, g_rowptr);
    cudaGetSymbolAddress((void**)&pcursor, g_cursor);
    cudaGetSymbolAddress((void**)&pbflag, g_bflag);
    cudaGetSymbolAddress((void**)&pcsrc, g_csrc);
    cudaGetSymbolAddress((void**)&pwh,  g_whi);
    cudaGetSymbolAddress((void**)&pch,  g_ch);
    cudaGetSymbolAddress((void**)&pxh,  g_xh);
    cudaGetSymbolAddress((void**)&pxl,  g_xl);
    cudaGetSymbolAddress((void**)&peamh, g_eamh);
    cudaGetSymbolAddress((void**)&peaml, g_eaml);

    constexpr int SM_F32A = 46080;
    constexpr int SM_MLP  = 65536;
    constexpr int SM_HEAD = 81920;
    auto setsm = [](const void* f, int b) {
        cudaFuncSetAttribute(f, cudaFuncAttributeMaxDynamicSharedMemorySize, b);
    };
    setsm((const void*)gemm_f32a<128, 0>, SM_F32A);
    setsm((const void*)gemm_f32a< 64, 2>, SM_F32A);
    setsm((const void*)mlp_fused, SM_MLP);
    setsm((const void*)gemm_head, SM_HEAD);

    // ---- resets (graph-capturable) ----
    cudaMemsetAsync(pdegi, 0, NN * sizeof(int));
    cudaMemsetAsync(pseg, 0, (size_t)NN * IN_EDGE * sizeof(float));
    cudaMemsetAsync(pbflag, 0, NB * sizeof(int));

    // ---- front: weight prep + deg histogram + seg scatter (fused) ----
    front_kernel<<<FB_W + FB_DEG + FB_SEG, 256>>>(node_W, edge_W, W1, W2, lin_W,
                                                  pwh, eidx, pdegi, eattr, pseg);

    // ---- CSR: single-kernel scan + fill ----
    scan_fused<<<NB, 256>>>(pdegi, pbflag, prowptr, pcursor, pinv);
    csr_fill<<<(EE + 255) / 256, 256>>>(eidx, pcursor, pcsrc);

    dim3 g2(TILES_M, 2);

    // node encoder: x(split) = x_in @ node_W + node_b
    gemm_f32a<128, 0><<<g2, 256, SM_F32A>>>(x_in, pwh, node_b,
        pxh, pxl, HH, nullptr, nullptr);
    // edge agg through encoder: eam(split) = (seg @ edge_W)*inv + [deg>0]*edge_b
    gemm_f32a<64, 2><<<g2, 256, SM_F32A>>>(pseg, pwh + 16384, edge_b,
        peamh, peaml, HH, pinv, pdegi);

    for (int l = 0; l < 3; l++) {
        gather_combine<<<(NN * 32 + 255) / 256, 256>>>(prowptr, pcsrc, pxh, pxl,
            peamh, peaml, pinv, eps, l, pch);
        mlp_fused<<<NBM, 128, SM_MLP>>>(pch,
            pwh + 24576 + l * 32768, b1 + (size_t)l * HH2,
            pwh + 122880 + l * 32768, b2 + (size_t)l * HH,
            pxh, pxl);
    }

    // head: out = (xh+xl) @ lin_W + lin_b
    gemm_head<<<g2, 256, SM_HEAD>>>(pxh, pxl, pwh + 221184, lin_b, out, OUTD);
}

// round 12
// speedup vs baseline: 2.2443x; 1.0147x over previous
#include <cuda_runtime.h>
#include <cuda_fp16.h>
#include <cstdint>

#define NN     50000
#define EE     625000
#define IN_EDGE 64
#define HH     128
#define HH2    256
#define OUTD   112
#define TILES_M 391   // ceil(50000/128)
#define NBM    782    // ceil(50000/64)
#define NB     196    // ceil(50000/256)

// ---------------- scratch (device globals; no allocation allowed) ----------
__device__ __align__(16) float g_seg[NN * IN_EDGE];
__device__ float g_inv[NN];
__device__ int   g_degi[NN];
__device__ int   g_rowptr[NN + 1];
__device__ int   g_cursor[NN];
__device__ int   g_bflag[NB];
__device__ int   g_csrc[EE];

// activations
__device__ __align__(16) __half g_xinh[NN * HH];     // x_in rounded fp16
__device__ __align__(16) __half g_segh[NN * IN_EDGE];// seg rounded fp16
__device__ __align__(16) __half g_ch  [NN * HH];     // combined (hi), W1 input
__device__ __align__(16) __half g_xh  [NN * HH];     // node state (split hi)
__device__ __align__(16) __half g_xl  [NN * HH];     // node state (split lo)
__device__ __align__(16) __half g_eamh[NN * HH];     // edge-agg-mean (split)
__device__ __align__(16) __half g_eaml[NN * HH];

// pre-rounded transposed weights, layout [N][K] fp16
__device__ __align__(16) __half g_whi[235520];

// ---------------------------------------------------------------------------
__device__ __forceinline__ uint32_t smem_u32(const void* p) {
    uint32_t a;
    asm("{ .reg .u64 t; cvta.to.shared.u64 t, %1; cvt.u32.u64 %0, t; }"
        : "=r"(a) : "l"(p));
    return a;
}
__device__ __forceinline__ void cp16(uint32_t dst, const void* src) {
    asm volatile("cp.async.cg.shared.global [%0], [%1], 16;"
                 :: "r"(dst), "l"(src) : "memory");
}
__device__ __forceinline__ void zero16(uint32_t dst) {
    asm volatile("st.shared.v4.b32 [%0], {%1,%1,%1,%1};" :: "r"(dst), "r"(0) : "memory");
}
__device__ __forceinline__ void ldsm4(uint32_t* r, uint32_t addr) {
    asm volatile("ldmatrix.sync.aligned.m8n8.x4.shared.b16 {%0,%1,%2,%3}, [%4];"
                 : "=r"(r[0]), "=r"(r[1]), "=r"(r[2]), "=r"(r[3]) : "r"(addr));
}
__device__ __forceinline__ void mma16816(float* d, const uint32_t* a, const uint32_t* b) {
    asm volatile("mma.sync.aligned.m16n8k16.row.col.f32.f16.f16.f32 "
                 "{%0,%1,%2,%3}, {%4,%5,%6,%7}, {%8,%9}, {%0,%1,%2,%3};"
                 : "+f"(d[0]), "+f"(d[1]), "+f"(d[2]), "+f"(d[3])
                 : "r"(a[0]), "r"(a[1]), "r"(a[2]), "r"(a[3]), "r"(b[0]), "r"(b[1]));
}
__device__ __forceinline__ void split2(float a, float b, uint32_t& hi, uint32_t& lo) {
    __half ha = __float2half(a), hb = __float2half(b);
    __half2 h = __halves2half2(ha, hb);
    __half2 l = __halves2half2(
        __float2half(a - __half2float(ha)),
        __float2half(b - __half2float(hb)));
    hi = *(uint32_t*)&h; lo = *(uint32_t*)&l;
}
__device__ __forceinline__ uint32_t pack2(float a, float b) {
    __half2 h = __halves2half2(__float2half(a), __float2half(b));
    return *(uint32_t*)&h;
}
__device__ __forceinline__ float2 unpack2(uint32_t h, uint32_t l) {
    __half2 hh = *(__half2*)&h;
    __half2 ll = *(__half2*)&l;
    return make_float2(__low2float(hh) + __low2float(ll),
                       __high2float(hh) + __high2float(ll));
}
__device__ __forceinline__ void red_add_v4(float* addr, float4 v) {
    asm volatile("red.global.add.v4.f32 [%0], {%1,%2,%3,%4};"
                 :: "l"(addr), "f"(v.x), "f"(v.y), "f"(v.z), "f"(v.w) : "memory");
}

// ---------------------------------------------------------------------------
// front: weight prep + degree histogram + seg scatter + x_in fp16 rounding
// ---------------------------------------------------------------------------
#define FB_W   920
#define FB_DEG 2442
#define FB_SEG 39063
#define FB_X   3125     // 50000*128/8 elems per thread / 256
__global__ void front_kernel(const float* __restrict__ node_W, const float* __restrict__ edge_W,
                             const float* __restrict__ W1, const float* __restrict__ W2,
                             const float* __restrict__ lin_W,
                             __half* __restrict__ hi,
                             const int* __restrict__ ei, int* __restrict__ degi,
                             const float* __restrict__ ea, float* __restrict__ seg,
                             const float* __restrict__ x_in, __half* __restrict__ xinh) {
    if (blockIdx.x < FB_W) {
        int i = blockIdx.x * 256 + threadIdx.x;
        if (i >= 235520) return;
        const float* src; int K, Nc, idx;
        if (i < 16384)       { src = node_W;                 K = 128; Nc = 128; idx = i; }
        else if (i < 24576)  { src = edge_W;                 K =  64; Nc = 128; idx = i - 16384; }
        else if (i < 122880) { int j = i - 24576;  src = W1 + (j / 32768) * 32768; K = 128; Nc = 256; idx = j % 32768; }
        else if (i < 221184) { int j = i - 122880; src = W2 + (j / 32768) * 32768; K = 256; Nc = 128; idx = j % 32768; }
        else                 { src = lin_W;                  K = 128; Nc = 112; idx = i - 221184; }
        int n = idx / K, k = idx % K;
        hi[i] = __float2half(__ldg(&src[(size_t)k * Nc + n]));
    } else if (blockIdx.x < FB_W + FB_DEG) {
        int e = (blockIdx.x - FB_W) * 256 + threadIdx.x;
        if (e < EE) atomicAdd(&degi[ei[EE + e]], 1);
    } else if (blockIdx.x < FB_W + FB_DEG + FB_SEG) {
        int gid = (blockIdx.x - FB_W - FB_DEG) * 256 + threadIdx.x;
        if (gid >= EE * 16) return;
        int e = gid >> 4, g = gid & 15;
        int dst = __ldg(&ei[EE + e]);
        float4 v = __ldg(((const float4*)ea) + (size_t)e * 16 + g);
        red_add_v4(seg + (size_t)dst * IN_EDGE + g * 4, v);
    } else {
        int gid = (blockIdx.x - FB_W - FB_DEG - FB_SEG) * 256 + threadIdx.x;
        size_t base = (size_t)gid * 8;
        if (base >= (size_t)NN * HH) return;
        float4 v0 = __ldg((const float4*)(x_in + base));
        float4 v1 = __ldg((const float4*)(x_in + base + 4));
        uint4 o;
        o.x = pack2(v0.x, v0.y); o.y = pack2(v0.z, v0.w);
        o.z = pack2(v1.x, v1.y); o.w = pack2(v1.z, v1.w);
        *(uint4*)(xinh + base) = o;
    }
}

// seg fp32 -> fp16
__global__ void seg2h(const float* __restrict__ seg, __half* __restrict__ segh) {
    size_t base = ((size_t)blockIdx.x * 256 + threadIdx.x) * 8;
    if (base >= (size_t)NN * IN_EDGE) return;
    float4 v0 = __ldg((const float4*)(seg + base));
    float4 v1 = __ldg((const float4*)(seg + base + 4));
    uint4 o;
    o.x = pack2(v0.x, v0.y); o.y = pack2(v0.z, v0.w);
    o.z = pack2(v1.x, v1.y); o.w = pack2(v1.z, v1.w);
    *(uint4*)(segh + base) = o;
}

// ---------------------------------------------------------------------------
// single-kernel exclusive scan (decoupled lookback over 196 blocks)
// ---------------------------------------------------------------------------
__global__ void scan_fused(const int* __restrict__ d, int* __restrict__ bflag,
                           int* __restrict__ rowptr, int* __restrict__ cursor,
                           float* __restrict__ inv) {
    __shared__ int s[256];
    __shared__ int sred[256];
    int b = blockIdx.x;
    int t = threadIdx.x;
    int i = b * 256 + t;
    int v = (i < NN) ? d[i] : 0;
    s[t] = v;
    __syncthreads();
    #pragma unroll
    for (int o = 1; o < 256; o <<= 1) {
        int tv = (t >= o) ? s[t - o] : 0;
        __syncthreads();
        s[t] += tv;
        __syncthreads();
    }
    int incl = s[t];
    int agg = s[255];
    if (t == 0) atomicExch(&bflag[b], agg + 1);
    int pval = 0;
    if (t < b) {
        int x;
        do { x = atomicAdd(&bflag[t], 0); } while (x == 0);
        pval = x - 1;
    }
    sred[t] = pval;
    __syncthreads();
    #pragma unroll
    for (int o = 128; o > 0; o >>= 1) {
        if (t < o) sred[t] += sred[t + o];
        __syncthreads();
    }
    int boffv = sred[0];
    if (i < NN) {
        int excl = incl - v + boffv;
        rowptr[i] = excl;
        cursor[i] = excl;
        inv[i] = 1.0f / (float)max(v, 1);
    }
    if (b == NB - 1 && t == 255) rowptr[NN] = boffv + agg;
}

__global__ void csr_fill(const int* __restrict__ ei, int* __restrict__ cursor,
                         int* __restrict__ csrc) {
    int e = blockIdx.x * blockDim.x + threadIdx.x;
    if (e >= EE) return;
    int dst = __ldg(&ei[EE + e]);
    int p = atomicAdd(&cursor[dst], 1);
    csrc[p] = __ldg(&ei[e]);
}

// fused: agg = sum_neighbors(x_hi) ; c = (1+eps)*x + agg*inv + eam -> ch (fp16 hi)
__global__ void gather_combine(const int* __restrict__ rowptr, const int* __restrict__ csrc,
                               const __half* __restrict__ xh,
                               const __half* __restrict__ xl,
                               const __half* __restrict__ eamh,
                               const __half* __restrict__ eaml,
                               const float* __restrict__ inv,
                               const float* __restrict__ eps_p, int layer,
                               __half* __restrict__ ch) {
    int w = (blockIdx.x * blockDim.x + threadIdx.x) >> 5;
    if (w >= NN) return;
    int lane = threadIdx.x & 31;
    int beg = __ldg(&rowptr[w]), end = __ldg(&rowptr[w + 1]);
    float a0 = 0.f, a1 = 0.f, a2 = 0.f, a3 = 0.f;
    for (int j = beg; j < end; j++) {
        int s = __ldg(&csrc[j]);
        uint2 hv = __ldg((const uint2*)(xh + (size_t)s * HH) + lane);
        __half2 h0 = *(__half2*)&hv.x;
        __half2 h1 = *(__half2*)&hv.y;
        a0 += __low2float(h0); a1 += __high2float(h0);
        a2 += __low2float(h1); a3 += __high2float(h1);
    }
    float iv = __ldg(&inv[w]);
    float epsv = 1.f + __ldg(&eps_p[layer]);
    uint2 hs = __ldg((const uint2*)(xh + (size_t)w * HH) + lane);
    uint2 ls = __ldg((const uint2*)(xl + (size_t)w * HH) + lane);
    float2 x01 = unpack2(hs.x, ls.x);
    float2 x23 = unpack2(hs.y, ls.y);
    uint2 eh = __ldg((const uint2*)(eamh + (size_t)w * HH) + lane);
    uint2 el = __ldg((const uint2*)(eaml + (size_t)w * HH) + lane);
    float2 e01 = unpack2(eh.x, el.x);
    float2 e23 = unpack2(eh.y, el.y);
    uint2 h;
    h.x = pack2(epsv * x01.x + a0 * iv + e01.x, epsv * x01.y + a1 * iv + e01.y);
    h.y = pack2(epsv * x23.x + a2 * iv + e23.x, epsv * x23.y + a3 * iv + e23.y);
    *(uint2*)(ch + (size_t)w * HH + lane * 4) = h;
}

// ---------------------------------------------------------------------------
// Fused GIN MLP: x = relu( relu(c @ W1 + b1) @ W2 + b2 )  — h1 stays in smem.
// ---------------------------------------------------------------------------
__global__ void __launch_bounds__(128, 3)
mlp_fused(const __half* __restrict__ C, const __half* __restrict__ W1h,
          const float* __restrict__ b1, const __half* __restrict__ W2h,
          const float* __restrict__ b2,
          __half* __restrict__ Xh, __half* __restrict__ Xl) {
    extern __shared__ char smem[];
    const uint32_t sC = smem_u32(smem);
    const uint32_t sH = sC + 16384;
    const uint32_t sB = sC + 49152;

    const int tid  = threadIdx.x;
    const int lane = tid & 31;
    const int wid  = tid >> 5;
    const int wm   = wid & 1;
    const int wn   = wid >> 1;
    const int rowBase = blockIdx.x * 64;

    #pragma unroll
    for (int i = 0; i < 8; i++) {
        int f = tid + i * 128;
        int row = f >> 4, chn = f & 15;
        uint32_t addr = sC + row * 256 + (((uint32_t)(chn * 16)) ^ ((row & 7) << 4));
        int gr = rowBase + row;
        if (gr < NN) cp16(addr, C + (size_t)gr * HH + chn * 8);
        else         zero16(addr);
    }
    asm volatile("cp.async.commit_group;" ::: "memory");

    const uint32_t aRowIdx = (uint32_t)(lane & 15);
    const uint32_t aK16    = (uint32_t)((lane >> 4) << 4);
    const uint32_t bRowIdx = (uint32_t)((lane & 7) + ((lane >> 4) << 3));
    const uint32_t bK16    = (uint32_t)(((lane >> 3) & 1) << 4);
    const int group = lane >> 2;
    const int qc    = (lane & 3) * 2;

    float acc[2][4][4];

    auto loadB = [&](const __half* W, int KT, int gn0, int kb, int stage) {
        #pragma unroll
        for (int i = 0; i < 4; i++) {
            int f = tid + i * 128;
            int row = f >> 3, chn = f & 7;
            uint32_t addr = sB + stage * 8192 + row * 128 +
                            (((uint32_t)(chn * 16)) ^ ((row & 7) << 4));
            cp16(addr, W + (size_t)(gn0 + row) * KT + kb + chn * 8);
        }
        asm volatile("cp.async.commit_group;" ::: "memory");
    };
    auto zacc = [&]() {
        #pragma unroll
        for (int a = 0; a < 2; a++)
            #pragma unroll
            for (int b = 0; b < 4; b++)
                #pragma unroll
                for (int c = 0; c < 4; c++) acc[a][b][c] = 0.f;
    };

    // ---------- phase 1 ----------
    loadB(W1h, 128, 0, 0, 0);
    for (int t = 0; t < 8; t++) {
        int cp = t >> 1, kc = t & 1;
        if (t + 1 < 8) {
            loadB(W1h, 128, ((t + 1) >> 1) * 64, ((t + 1) & 1) * 64, (t + 1) & 1);
            asm volatile("cp.async.wait_group 1;" ::: "memory");
        } else {
            asm volatile("cp.async.wait_group 0;" ::: "memory");
        }
        __syncthreads();
        if (kc == 0) zacc();
        uint32_t bBuf = sB + (t & 1) * 8192;
        #pragma unroll
        for (int ks = 0; ks < 4; ks++) {
            uint32_t ah[2][4], bh[4][2];
            #pragma unroll
            for (int mi = 0; mi < 2; mi++) {
                uint32_t row = wm * 32 + mi * 16 + aRowIdx;
                uint32_t cb = (uint32_t)(kc * 128 + ks * 32) + aK16;
                ldsm4(ah[mi], sC + row * 256 + (cb ^ ((row & 7) << 4)));
            }
            #pragma unroll
            for (int pr = 0; pr < 2; pr++) {
                uint32_t row = wn * 32 + pr * 16 + bRowIdx;
                uint32_t cb = (uint32_t)(ks * 32) + bK16;
                uint32_t tr[4];
                ldsm4(tr, bBuf + row * 128 + (cb ^ ((row & 7) << 4)));
                bh[pr*2][0] = tr[0]; bh[pr*2][1] = tr[1];
                bh[pr*2+1][0] = tr[2]; bh[pr*2+1][1] = tr[3];
            }
            #pragma unroll
            for (int mi = 0; mi < 2; mi++)
                #pragma unroll
                for (int ni = 0; ni < 4; ni++)
                    mma16816(acc[mi][ni], ah[mi], bh[ni]);
        }
        if (kc == 1) {
            #pragma unroll
            for (int mi = 0; mi < 2; mi++) {
                int r0 = wm * 32 + mi * 16 + group;
                int r1 = r0 + 8;
                #pragma unroll
                for (int ni = 0; ni < 4; ni++) {
                    int c = cp * 64 + wn * 32 + ni * 8 + qc;
                    float bv0 = __ldg(&b1[c]), bv1 = __ldg(&b1[c + 1]);
                    uint32_t p0 = pack2(fmaxf(acc[mi][ni][0] + bv0, 0.f),
                                        fmaxf(acc[mi][ni][1] + bv1, 0.f));
                    uint32_t p1 = pack2(fmaxf(acc[mi][ni][2] + bv0, 0.f),
                                        fmaxf(acc[mi][ni][3] + bv1, 0.f));
                    uint32_t cb = (uint32_t)(c * 2);
                    uint32_t a0 = sH + r0 * 512 + (cb ^ ((r0 & 7) << 4));
                    uint32_t a1 = sH + r1 * 512 + (cb ^ ((r1 & 7) << 4));
                    asm volatile("st.shared.b32 [%0], %1;" :: "r"(a0), "r"(p0) : "memory");
                    asm volatile("st.shared.b32 [%0], %1;" :: "r"(a1), "r"(p1) : "memory");
                }
            }
        }
        __syncthreads();
    }

    // ---------- phase 2 ----------
    loadB(W2h, 256, 0, 0, 0);
    for (int t = 0; t < 8; t++) {
        int cp = t >> 2, kc = t & 3;
        if (t + 1 < 8) {
            loadB(W2h, 256, ((t + 1) >> 2) * 64, ((t + 1) & 3) * 64, (t + 1) & 1);
            asm volatile("cp.async.wait_group 1;" ::: "memory");
        } else {
            asm volatile("cp.async.wait_group 0;" ::: "memory");
        }
        __syncthreads();
        if (kc == 0) zacc();
        uint32_t bBuf = sB + (t & 1) * 8192;
        #pragma unroll
        for (int ks = 0; ks < 4; ks++) {
            uint32_t ah[2][4], bh[4][2];
            #pragma unroll
            for (int mi = 0; mi < 2; mi++) {
                uint32_t row = wm * 32 + mi * 16 + aRowIdx;
                uint32_t cb = (uint32_t)(kc * 128 + ks * 32) + aK16;
                ldsm4(ah[mi], sH + row * 512 + (cb ^ ((row & 7) << 4)));
            }
            #pragma unroll
            for (int pr = 0; pr < 2; pr++) {
                uint32_t row = wn * 32 + pr * 16 + bRowIdx;
                uint32_t cb = (uint32_t)(ks * 32) + bK16;
                uint32_t tr[4];
                ldsm4(tr, bBuf + row * 128 + (cb ^ ((row & 7) << 4)));
                bh[pr*2][0] = tr[0]; bh[pr*2][1] = tr[1];
                bh[pr*2+1][0] = tr[2]; bh[pr*2+1][1] = tr[3];
            }
            #pragma unroll
            for (int mi = 0; mi < 2; mi++)
                #pragma unroll
                for (int ni = 0; ni < 4; ni++)
                    mma16816(acc[mi][ni], ah[mi], bh[ni]);
        }
        if (kc == 3) {
            #pragma unroll
            for (int mi = 0; mi < 2; mi++) {
                int r0 = rowBase + wm * 32 + mi * 16 + group;
                int r1 = r0 + 8;
                #pragma unroll
                for (int ni = 0; ni < 4; ni++) {
                    int c = cp * 64 + wn * 32 + ni * 8 + qc;
                    float bv0 = __ldg(&b2[c]), bv1 = __ldg(&b2[c + 1]);
                    float v00 = fmaxf(acc[mi][ni][0] + bv0, 0.f);
                    float v01 = fmaxf(acc[mi][ni][1] + bv1, 0.f);
                    float v10 = fmaxf(acc[mi][ni][2] + bv0, 0.f);
                    float v11 = fmaxf(acc[mi][ni][3] + bv1, 0.f);
                    if (r0 < NN) {
                        uint32_t h, l; split2(v00, v01, h, l);
                        *(uint32_t*)(Xh + (size_t)r0 * HH + c) = h;
                        *(uint32_t*)(Xl + (size_t)r0 * HH + c) = l;
                    }
                    if (r1 < NN) {
                        uint32_t h, l; split2(v10, v11, h, l);
                        *(uint32_t*)(Xh + (size_t)r1 * HH + c) = h;
                        *(uint32_t*)(Xl + (size_t)r1 * HH + c) = l;
                    }
                }
            }
        }
        __syncthreads();
    }
}

// ---------------------------------------------------------------------------
// Unified pipelined fp16 GEMM.
// NPROD: 1 = A@Bh ; 2 = (Ah+Al)@Bh
// EPI:   0 = +bias ; 2 = *inv + [deg>0]*bias
// OUTMODE: 0 fp32 ; 2 fp16 split
// ---------------------------------------------------------------------------
template <int KTOT, int EPI, int OUTMODE, int NPROD>
__global__ void __launch_bounds__(256, 2)
gemm_hf(const __half* __restrict__ Ah, const __half* __restrict__ Al,
        const __half* __restrict__ Bhi,
        const float* __restrict__ bias, float* __restrict__ Cf,
        __half* __restrict__ Ch, __half* __restrict__ Cl, int Nc,
        const float* __restrict__ inv, const int* __restrict__ degi) {
    constexpr int CHUNKS = KTOT / 64;
    constexpr int ASZ = 16384 * NPROD;
    constexpr int STG = ASZ + 8192;
    extern __shared__ char smem[];
    const uint32_t sb = smem_u32(smem);

    const int tid  = threadIdx.x;
    const int lane = tid & 31;
    const int wid  = tid >> 5;
    const int wm   = wid & 3;
    const int wn   = wid >> 2;
    const int rowBase = blockIdx.x * 128;
    const int colBase = blockIdx.y * 64;

    float acc[2][4][4];
    #pragma unroll
    for (int a = 0; a < 2; a++)
        #pragma unroll
        for (int b = 0; b < 4; b++)
            #pragma unroll
            for (int c = 0; c < 4; c++) acc[a][b][c] = 0.f;

    auto load_slab = [&](int stage, int c) {
        uint32_t base = sb + stage * STG;
        int kb = c * 64;
        #pragma unroll
        for (int i = 0; i < 4; i++) {
            int f = tid + i * 256;
            int row = f >> 3, chn = f & 7;
            uint32_t sw = (uint32_t)(chn * 16) ^ (uint32_t)((row & 7) << 4);
            uint32_t da = base + row * 128 + sw;
            int gr = rowBase + row;
            if (gr < NN) {
                size_t off = (size_t)gr * KTOT + kb + chn * 8;
                cp16(da, Ah + off);
                if (NPROD == 2) cp16(da + 16384, Al + off);
            } else {
                zero16(da);
                if (NPROD == 2) zero16(da + 16384);
            }
        }
        #pragma unroll
        for (int i = 0; i < 2; i++) {
            int f = tid + i * 256;
            int row = f >> 3, chn = f & 7;
            uint32_t sw = (uint32_t)(chn * 16) ^ (uint32_t)((row & 7) << 4);
            uint32_t db = base + ASZ + row * 128 + sw;
            int gn = colBase + row;
            if (gn < Nc) cp16(db, Bhi + (size_t)gn * KTOT + kb + chn * 8);
            else         zero16(db);
        }
        asm volatile("cp.async.commit_group;" ::: "memory");
    };

    const uint32_t aRowIdx = (uint32_t)(lane & 15);
    const uint32_t aK16    = (uint32_t)((lane >> 4) << 4);
    const uint32_t bRowIdx = (uint32_t)((lane & 7) + ((lane >> 4) << 3));
    const uint32_t bK16    = (uint32_t)(((lane >> 3) & 1) << 4);

    load_slab(0, 0);

    for (int c = 0; c < CHUNKS; c++) {
        if (c + 1 < CHUNKS) {
            load_slab((c + 1) & 1, c + 1);
            asm volatile("cp.async.wait_group 1;" ::: "memory");
        } else {
            asm volatile("cp.async.wait_group 0;" ::: "memory");
        }
        __syncthreads();

        uint32_t bA = sb + (c & 1) * STG;
        uint32_t bB = bA + ASZ;
        #pragma unroll
        for (int ks = 0; ks < 4; ks++) {
            uint32_t ah[2][4], al[2][4], bh[4][2];
            #pragma unroll
            for (int mi = 0; mi < 2; mi++) {
                uint32_t row = wm * 32 + mi * 16 + aRowIdx;
                uint32_t cb = (uint32_t)(ks * 32) + aK16;
                uint32_t off = row * 128 + (cb ^ ((row & 7) << 4));
                ldsm4(ah[mi], bA + off);
                if (NPROD == 2) ldsm4(al[mi], bA + 16384 + off);
            }
            #pragma unroll
            for (int pr = 0; pr < 2; pr++) {
                uint32_t row = wn * 32 + pr * 16 + bRowIdx;
                uint32_t cb = (uint32_t)(ks * 32) + bK16;
                uint32_t off = row * 128 + (cb ^ ((row & 7) << 4));
                uint32_t t[4];
                ldsm4(t, bB + off);
                bh[pr*2][0] = t[0]; bh[pr*2][1] = t[1];
                bh[pr*2+1][0] = t[2]; bh[pr*2+1][1] = t[3];
            }
            #pragma unroll
            for (int mi = 0; mi < 2; mi++)
                #pragma unroll
                for (int ni = 0; ni < 4; ni++) {
                    mma16816(acc[mi][ni], ah[mi], bh[ni]);
                    if (NPROD == 2) mma16816(acc[mi][ni], al[mi], bh[ni]);
                }
        }
        if (c + 1 < CHUNKS) __syncthreads();
    }

    const int group = lane >> 2;
    const int qc    = (lane & 3) * 2;
    #pragma unroll
    for (int mi = 0; mi < 2; mi++) {
        int r0 = rowBase + wm * 32 + mi * 16 + group;
        int r1 = r0 + 8;
        float iv0 = 0.f, m0 = 0.f, iv1 = 0.f, m1 = 0.f;
        if (EPI == 2) {
            if (r0 < NN) { iv0 = __ldg(&inv[r0]); m0 = (__ldg(&degi[r0]) > 0) ? 1.f : 0.f; }
            if (r1 < NN) { iv1 = __ldg(&inv[r1]); m1 = (__ldg(&degi[r1]) > 0) ? 1.f : 0.f; }
        }
        #pragma unroll
        for (int ni = 0; ni < 4; ni++) {
            int c = colBase + wn * 32 + ni * 8 + qc;
            if (c >= Nc) continue;
            float b0 = __ldg(&bias[c]), b1 = __ldg(&bias[c + 1]);
            float2 v0, v1;
            if (EPI == 2) {
                v0.x = acc[mi][ni][0] * iv0 + m0 * b0;
                v0.y = acc[mi][ni][1] * iv0 + m0 * b1;
                v1.x = acc[mi][ni][2] * iv1 + m1 * b0;
                v1.y = acc[mi][ni][3] * iv1 + m1 * b1;
            } else {
                v0.x = acc[mi][ni][0] + b0; v0.y = acc[mi][ni][1] + b1;
                v1.x = acc[mi][ni][2] + b0; v1.y = acc[mi][ni][3] + b1;
            }
            if (r0 < NN) {
                if (OUTMODE == 0) *(float2*)(Cf + (size_t)r0 * Nc + c) = v0;
                else {
                    uint32_t h, l; split2(v0.x, v0.y, h, l);
                    *(uint32_t*)(Ch + (size_t)r0 * Nc + c) = h;
                    *(uint32_t*)(Cl + (size_t)r0 * Nc + c) = l;
                }
            }
            if (r1 < NN) {
                if (OUTMODE == 0) *(float2*)(Cf + (size_t)r1 * Nc + c) = v1;
                else {
                    uint32_t h, l; split2(v1.x, v1.y, h, l);
                    *(uint32_t*)(Ch + (size_t)r1 * Nc + c) = h;
                    *(uint32_t*)(Cl + (size_t)r1 * Nc + c) = l;
                }
            }
        }
    }
}

// ---------------------------------------------------------------------------
extern "C" void kernel_launch(void* const* d_in, const int* in_sizes, int n_in,
                              void* d_out, int out_size) {
    const float* x_in   = (const float*)d_in[0];
    const float* eattr  = (const float*)d_in[1];
    const int*   eidx   = (const int*)  d_in[2];
    const float* node_W = (const float*)d_in[3];
    const float* node_b = (const float*)d_in[4];
    const float* edge_W = (const float*)d_in[5];
    const float* edge_b = (const float*)d_in[6];
    const float* W1     = (const float*)d_in[7];
    const float* b1     = (const float*)d_in[8];
    const float* W2     = (const float*)d_in[9];
    const float* b2     = (const float*)d_in[10];
    const float* eps    = (const float*)d_in[11];
    const float* lin_W  = (const float*)d_in[12];
    const float* lin_b  = (const float*)d_in[13];
    float* out = (float*)d_out;

    float *pseg, *pinv;
    int *pdegi, *prowptr, *pcursor, *pbflag, *pcsrc;
    __half *pwh, *pch, *pxh, *pxl, *peamh, *peaml, *pxinh, *psegh;
    cudaGetSymbolAddress((void**)&pseg, g_seg);
    cudaGetSymbolAddress((void**)&pinv, g_inv);
    cudaGetSymbolAddress((void**)&pdegi, g_degi);
    cudaGetSymbolAddress((void**)&prowptr, g_rowptr);
    cudaGetSymbolAddress((void**)&pcursor, g_cursor);
    cudaGetSymbolAddress((void**)&pbflag, g_bflag);
    cudaGetSymbolAddress((void**)&pcsrc, g_csrc);
    cudaGetSymbolAddress((void**)&pwh,  g_whi);
    cudaGetSymbolAddress((void**)&pch,  g_ch);
    cudaGetSymbolAddress((void**)&pxh,  g_xh);
    cudaGetSymbolAddress((void**)&pxl,  g_xl);
    cudaGetSymbolAddress((void**)&peamh, g_eamh);
    cudaGetSymbolAddress((void**)&peaml, g_eaml);
    cudaGetSymbolAddress((void**)&pxinh, g_xinh);
    cudaGetSymbolAddress((void**)&psegh, g_segh);

    constexpr int SM_HF1  = 49152;
    constexpr int SM_HF2  = 81920;
    constexpr int SM_MLP  = 65536;
    auto setsm = [](const void* f, int b) {
        cudaFuncSetAttribute(f, cudaFuncAttributeMaxDynamicSharedMemorySize, b);
    };
    setsm((const void*)gemm_hf<128, 0, 2, 1>, SM_HF1);
    setsm((const void*)gemm_hf< 64, 2, 2, 1>, SM_HF1);
    setsm((const void*)gemm_hf<128, 0, 0, 2>, SM_HF2);
    setsm((const void*)mlp_fused, SM_MLP);

    // ---- resets ----
    cudaMemsetAsync(pdegi, 0, NN * sizeof(int));
    cudaMemsetAsync(pseg, 0, (size_t)NN * IN_EDGE * sizeof(float));
    cudaMemsetAsync(pbflag, 0, NB * sizeof(int));

    // ---- front: weight prep + deg + seg scatter + x_in round ----
    front_kernel<<<FB_W + FB_DEG + FB_SEG + FB_X, 256>>>(
        node_W, edge_W, W1, W2, lin_W, pwh, eidx, pdegi, eattr, pseg, x_in, pxinh);

    // ---- seg fp32 -> fp16 ----
    seg2h<<<(NN * IN_EDGE / 8 + 255) / 256, 256>>>(pseg, psegh);

    // ---- CSR ----
    scan_fused<<<NB, 256>>>(pdegi, pbflag, prowptr, pcursor, pinv);
    csr_fill<<<(EE + 255) / 256, 256>>>(eidx, pcursor, pcsrc);

    dim3 g2(TILES_M, 2);

    // node encoder: x(split) = xinh @ node_W + node_b  (1-product pipelined)
    gemm_hf<128, 0, 2, 1><<<g2, 256, SM_HF1>>>(pxinh, nullptr, pwh, node_b,
        nullptr, pxh, pxl, HH, nullptr, nullptr);
    // edge encoder: eam(split) = (segh @ edge_W)*inv + [deg>0]*edge_b
    gemm_hf<64, 2, 2, 1><<<g2, 256, SM_HF1>>>(psegh, nullptr, pwh + 16384, edge_b,
        nullptr, peamh, peaml, HH, pinv, pdegi);

    for (int l = 0; l < 3; l++) {
        gather_combine<<<(NN * 32 + 255) / 256, 256>>>(prowptr, pcsrc, pxh, pxl,
            peamh, peaml, pinv, eps, l, pch);
        mlp_fused<<<NBM, 128, SM_MLP>>>(pch,
            pwh + 24576 + l * 32768, b1 + (size_t)l * HH2,
            pwh + 122880 + l * 32768, b2 + (size_t)l * HH,
            pxh, pxl);
    }

    // head: out = (xh+xl) @ lin_W + lin_b
    gemm_hf<128, 0, 0, 2><<<g2, 256, SM_HF2>>>(pxh, pxl, pwh + 221184, lin_b,
        out, nullptr, nullptr, OUTD, nullptr, nullptr);
}

// round 13
// speedup vs baseline: 2.2791x; 1.0155x over previous
#include <cuda_runtime.h>
#include <cuda_fp16.h>
#include <cstdint>

#define NN     50000
#define EE     625000
#define IN_EDGE 64
#define HH     128
#define HH2    256
#define OUTD   112
#define TILES_M 391   // ceil(50000/128)
#define NBM    782    // ceil(50000/64)
#define NB     196    // ceil(50000/256)

// ---------------- scratch (device globals; no allocation allowed) ----------
__device__ __align__(16) float g_seg[NN * IN_EDGE];
__device__ float g_inv[NN];
__device__ int   g_degi[NN];
__device__ int   g_rowptr[NN + 1];
__device__ int   g_cursor[NN];
__device__ int   g_bflag[NB];
__device__ int   g_csrc[EE];

// activations
__device__ __align__(16) __half g_xinh[NN * HH];     // x_in rounded fp16
__device__ __align__(16) __half g_segh[NN * IN_EDGE];// seg rounded fp16
__device__ __align__(16) __half g_ch  [NN * HH];     // combined (hi), W1 input
__device__ __align__(16) __half g_xh  [NN * HH];     // node state (split hi)
__device__ __align__(16) __half g_xl  [NN * HH];     // node state (split lo)
__device__ __align__(16) __half g_eamh[NN * HH];     // edge-agg-mean (split)
__device__ __align__(16) __half g_eaml[NN * HH];

// pre-rounded transposed weights, layout [N][K] fp16
__device__ __align__(16) __half g_whi[235520];

// ---------------------------------------------------------------------------
__device__ __forceinline__ uint32_t smem_u32(const void* p) {
    uint32_t a;
    asm("{ .reg .u64 t; cvta.to.shared.u64 t, %1; cvt.u32.u64 %0, t; }"
        : "=r"(a) : "l"(p));
    return a;
}
__device__ __forceinline__ void cp16(uint32_t dst, const void* src) {
    asm volatile("cp.async.cg.shared.global [%0], [%1], 16;"
                 :: "r"(dst), "l"(src) : "memory");
}
__device__ __forceinline__ void zero16(uint32_t dst) {
    asm volatile("st.shared.v4.b32 [%0], {%1,%1,%1,%1};" :: "r"(dst), "r"(0) : "memory");
}
__device__ __forceinline__ void ldsm4(uint32_t* r, uint32_t addr) {
    asm volatile("ldmatrix.sync.aligned.m8n8.x4.shared.b16 {%0,%1,%2,%3}, [%4];"
                 : "=r"(r[0]), "=r"(r[1]), "=r"(r[2]), "=r"(r[3]) : "r"(addr));
}
__device__ __forceinline__ void mma16816(float* d, const uint32_t* a, const uint32_t* b) {
    asm volatile("mma.sync.aligned.m16n8k16.row.col.f32.f16.f16.f32 "
                 "{%0,%1,%2,%3}, {%4,%5,%6,%7}, {%8,%9}, {%0,%1,%2,%3};"
                 : "+f"(d[0]), "+f"(d[1]), "+f"(d[2]), "+f"(d[3])
                 : "r"(a[0]), "r"(a[1]), "r"(a[2]), "r"(a[3]), "r"(b[0]), "r"(b[1]));
}
__device__ __forceinline__ void split2(float a, float b, uint32_t& hi, uint32_t& lo) {
    __half ha = __float2half(a), hb = __float2half(b);
    __half2 h = __halves2half2(ha, hb);
    __half2 l = __halves2half2(
        __float2half(a - __half2float(ha)),
        __float2half(b - __half2float(hb)));
    hi = *(uint32_t*)&h; lo = *(uint32_t*)&l;
}
__device__ __forceinline__ uint32_t pack2(float a, float b) {
    __half2 h = __halves2half2(__float2half(a), __float2half(b));
    return *(uint32_t*)&h;
}
__device__ __forceinline__ float2 unpack2(uint32_t h, uint32_t l) {
    __half2 hh = *(__half2*)&h;
    __half2 ll = *(__half2*)&l;
    return make_float2(__low2float(hh) + __low2float(ll),
                       __high2float(hh) + __high2float(ll));
}
__device__ __forceinline__ void red_add_v4(float* addr, float4 v) {
    asm volatile("red.global.add.v4.f32 [%0], {%1,%2,%3,%4};"
                 :: "l"(addr), "f"(v.x), "f"(v.y), "f"(v.z), "f"(v.w) : "memory");
}

// ---------------------------------------------------------------------------
// front: weight prep + degree histogram + seg scatter + x_in fp16 rounding
// ---------------------------------------------------------------------------
#define FB_W   920
#define FB_DEG 2442
#define FB_SEG 39063
#define FB_X   3125
__global__ void front_kernel(const float* __restrict__ node_W, const float* __restrict__ edge_W,
                             const float* __restrict__ W1, const float* __restrict__ W2,
                             const float* __restrict__ lin_W,
                             __half* __restrict__ hi,
                             const int* __restrict__ ei, int* __restrict__ degi,
                             const float* __restrict__ ea, float* __restrict__ seg,
                             const float* __restrict__ x_in, __half* __restrict__ xinh) {
    if (blockIdx.x < FB_W) {
        int i = blockIdx.x * 256 + threadIdx.x;
        if (i >= 235520) return;
        const float* src; int K, Nc, idx;
        if (i < 16384)       { src = node_W;                 K = 128; Nc = 128; idx = i; }
        else if (i < 24576)  { src = edge_W;                 K =  64; Nc = 128; idx = i - 16384; }
        else if (i < 122880) { int j = i - 24576;  src = W1 + (j / 32768) * 32768; K = 128; Nc = 256; idx = j % 32768; }
        else if (i < 221184) { int j = i - 122880; src = W2 + (j / 32768) * 32768; K = 256; Nc = 128; idx = j % 32768; }
        else                 { src = lin_W;                  K = 128; Nc = 112; idx = i - 221184; }
        int n = idx / K, k = idx % K;
        hi[i] = __float2half(__ldg(&src[(size_t)k * Nc + n]));
    } else if (blockIdx.x < FB_W + FB_DEG) {
        int e = (blockIdx.x - FB_W) * 256 + threadIdx.x;
        if (e < EE) atomicAdd(&degi[ei[EE + e]], 1);
    } else if (blockIdx.x < FB_W + FB_DEG + FB_SEG) {
        int gid = (blockIdx.x - FB_W - FB_DEG) * 256 + threadIdx.x;
        if (gid >= EE * 16) return;
        int e = gid >> 4, g = gid & 15;
        int dst = __ldg(&ei[EE + e]);
        float4 v = __ldg(((const float4*)ea) + (size_t)e * 16 + g);
        red_add_v4(seg + (size_t)dst * IN_EDGE + g * 4, v);
    } else {
        int gid = (blockIdx.x - FB_W - FB_DEG - FB_SEG) * 256 + threadIdx.x;
        size_t base = (size_t)gid * 8;
        if (base >= (size_t)NN * HH) return;
        float4 v0 = __ldg((const float4*)(x_in + base));
        float4 v1 = __ldg((const float4*)(x_in + base + 4));
        uint4 o;
        o.x = pack2(v0.x, v0.y); o.y = pack2(v0.z, v0.w);
        o.z = pack2(v1.x, v1.y); o.w = pack2(v1.z, v1.w);
        *(uint4*)(xinh + base) = o;
    }
}

// ---------------------------------------------------------------------------
// single-kernel exclusive scan (decoupled lookback over 196 blocks)
// ---------------------------------------------------------------------------
__global__ void scan_fused(const int* __restrict__ d, int* __restrict__ bflag,
                           int* __restrict__ rowptr, int* __restrict__ cursor,
                           float* __restrict__ inv) {
    __shared__ int s[256];
    __shared__ int sred[256];
    int b = blockIdx.x;
    int t = threadIdx.x;
    int i = b * 256 + t;
    int v = (i < NN) ? d[i] : 0;
    s[t] = v;
    __syncthreads();
    #pragma unroll
    for (int o = 1; o < 256; o <<= 1) {
        int tv = (t >= o) ? s[t - o] : 0;
        __syncthreads();
        s[t] += tv;
        __syncthreads();
    }
    int incl = s[t];
    int agg = s[255];
    if (t == 0) atomicExch(&bflag[b], agg + 1);
    int pval = 0;
    if (t < b) {
        int x;
        do { x = atomicAdd(&bflag[t], 0); } while (x == 0);
        pval = x - 1;
    }
    sred[t] = pval;
    __syncthreads();
    #pragma unroll
    for (int o = 128; o > 0; o >>= 1) {
        if (t < o) sred[t] += sred[t + o];
        __syncthreads();
    }
    int boffv = sred[0];
    if (i < NN) {
        int excl = incl - v + boffv;
        rowptr[i] = excl;
        cursor[i] = excl;
        inv[i] = 1.0f / (float)max(v, 1);
    }
    if (b == NB - 1 && t == 255) rowptr[NN] = boffv + agg;
}

// merged: seg fp32->fp16 conversion + csr fill (independent work, overlapped)
#define MB_SEG 1563   // ceil(50000*64/8/256)
__global__ void mid_kernel(const float* __restrict__ seg, __half* __restrict__ segh,
                           const int* __restrict__ ei, int* __restrict__ cursor,
                           int* __restrict__ csrc) {
    if (blockIdx.x < MB_SEG) {
        size_t base = ((size_t)blockIdx.x * 256 + threadIdx.x) * 8;
        if (base >= (size_t)NN * IN_EDGE) return;
        float4 v0 = __ldg((const float4*)(seg + base));
        float4 v1 = __ldg((const float4*)(seg + base + 4));
        uint4 o;
        o.x = pack2(v0.x, v0.y); o.y = pack2(v0.z, v0.w);
        o.z = pack2(v1.x, v1.y); o.w = pack2(v1.z, v1.w);
        *(uint4*)(segh + base) = o;
    } else {
        int e = (blockIdx.x - MB_SEG) * 256 + threadIdx.x;
        if (e >= EE) return;
        int dst = __ldg(&ei[EE + e]);
        int p = atomicAdd(&cursor[dst], 1);
        csrc[p] = __ldg(&ei[e]);
    }
}

// fused: agg = sum_neighbors(x_hi) ; c = (1+eps)*x + agg*inv + eam -> ch (fp16 hi)
__global__ void gather_combine(const int* __restrict__ rowptr, const int* __restrict__ csrc,
                               const __half* __restrict__ xh,
                               const __half* __restrict__ xl,
                               const __half* __restrict__ eamh,
                               const __half* __restrict__ eaml,
                               const float* __restrict__ inv,
                               const float* __restrict__ eps_p, int layer,
                               __half* __restrict__ ch) {
    int w = (blockIdx.x * blockDim.x + threadIdx.x) >> 5;
    if (w >= NN) return;
    int lane = threadIdx.x & 31;
    int beg = __ldg(&rowptr[w]), end = __ldg(&rowptr[w + 1]);
    float a0 = 0.f, a1 = 0.f, a2 = 0.f, a3 = 0.f;
    for (int j = beg; j < end; j++) {
        int s = __ldg(&csrc[j]);
        uint2 hv = __ldg((const uint2*)(xh + (size_t)s * HH) + lane);
        __half2 h0 = *(__half2*)&hv.x;
        __half2 h1 = *(__half2*)&hv.y;
        a0 += __low2float(h0); a1 += __high2float(h0);
        a2 += __low2float(h1); a3 += __high2float(h1);
    }
    float iv = __ldg(&inv[w]);
    float epsv = 1.f + __ldg(&eps_p[layer]);
    uint2 hs = __ldg((const uint2*)(xh + (size_t)w * HH) + lane);
    uint2 ls = __ldg((const uint2*)(xl + (size_t)w * HH) + lane);
    float2 x01 = unpack2(hs.x, ls.x);
    float2 x23 = unpack2(hs.y, ls.y);
    uint2 eh = __ldg((const uint2*)(eamh + (size_t)w * HH) + lane);
    uint2 el = __ldg((const uint2*)(eaml + (size_t)w * HH) + lane);
    float2 e01 = unpack2(eh.x, el.x);
    float2 e23 = unpack2(eh.y, el.y);
    uint2 h;
    h.x = pack2(epsv * x01.x + a0 * iv + e01.x, epsv * x01.y + a1 * iv + e01.y);
    h.y = pack2(epsv * x23.x + a2 * iv + e23.x, epsv * x23.y + a3 * iv + e23.y);
    *(uint2*)(ch + (size_t)w * HH + lane * 4) = h;
}

// ---------------------------------------------------------------------------
// Fused GIN MLP: x = relu( relu(c @ W1 + b1) @ W2 + b2 ).  h1 stays in smem.
// HEAD=1 (last layer): x stays in smem too; phase 3 computes
//   out = (xh+xl) @ lin_W + lin_b directly (head fused, no global x).
// smem: sC 16K | sH 32K | sB 16K [| HEAD: sXh 16K | sXl 16K]
// ---------------------------------------------------------------------------
template <int HEAD>
__global__ void __launch_bounds__(128, 2)
mlp_fused(const __half* __restrict__ C, const __half* __restrict__ W1h,
          const float* __restrict__ b1, const __half* __restrict__ W2h,
          const float* __restrict__ b2,
          __half* __restrict__ Xh, __half* __restrict__ Xl,
          const __half* __restrict__ Wlin, const float* __restrict__ blin,
          float* __restrict__ out) {
    extern __shared__ char smem[];
    const uint32_t sC = smem_u32(smem);
    const uint32_t sH = sC + 16384;
    const uint32_t sB = sC + 49152;
    const uint32_t sXh = sB + 16384;    // HEAD only
    const uint32_t sXl = sXh + 16384;   // HEAD only

    const int tid  = threadIdx.x;
    const int lane = tid & 31;
    const int wid  = tid >> 5;
    const int wm   = wid & 1;
    const int wn   = wid >> 1;
    const int rowBase = blockIdx.x * 64;

    #pragma unroll
    for (int i = 0; i < 8; i++) {
        int f = tid + i * 128;
        int row = f >> 4, chn = f & 15;
        uint32_t addr = sC + row * 256 + (((uint32_t)(chn * 16)) ^ ((row & 7) << 4));
        int gr = rowBase + row;
        if (gr < NN) cp16(addr, C + (size_t)gr * HH + chn * 8);
        else         zero16(addr);
    }
    asm volatile("cp.async.commit_group;" ::: "memory");

    const uint32_t aRowIdx = (uint32_t)(lane & 15);
    const uint32_t aK16    = (uint32_t)((lane >> 4) << 4);
    const uint32_t bRowIdx = (uint32_t)((lane & 7) + ((lane >> 4) << 3));
    const uint32_t bK16    = (uint32_t)(((lane >> 3) & 1) << 4);
    const int group = lane >> 2;
    const int qc    = (lane & 3) * 2;

    float acc[2][4][4];

    auto loadB = [&](const __half* W, int KT, int gn0, int kb, int stage, int NcB) {
        #pragma unroll
        for (int i = 0; i < 4; i++) {
            int f = tid + i * 128;
            int row = f >> 3, chn = f & 7;
            uint32_t addr = sB + stage * 8192 + row * 128 +
                            (((uint32_t)(chn * 16)) ^ ((row & 7) << 4));
            if (gn0 + row < NcB) cp16(addr, W + (size_t)(gn0 + row) * KT + kb + chn * 8);
            else                 zero16(addr);
        }
        asm volatile("cp.async.commit_group;" ::: "memory");
    };
    auto zacc = [&]() {
        #pragma unroll
        for (int a = 0; a < 2; a++)
            #pragma unroll
            for (int b = 0; b < 4; b++)
                #pragma unroll
                for (int c = 0; c < 4; c++) acc[a][b][c] = 0.f;
    };

    // ---------- phase 1: h1(smem) = relu(c @ W1 + b1), N=256, K=128 ----------
    loadB(W1h, 128, 0, 0, 0, 256);
    for (int t = 0; t < 8; t++) {
        int cp = t >> 1, kc = t & 1;
        if (t + 1 < 8) {
            loadB(W1h, 128, ((t + 1) >> 1) * 64, ((t + 1) & 1) * 64, (t + 1) & 1, 256);
            asm volatile("cp.async.wait_group 1;" ::: "memory");
        } else {
            asm volatile("cp.async.wait_group 0;" ::: "memory");
        }
        __syncthreads();
        if (kc == 0) zacc();
        uint32_t bBuf = sB + (t & 1) * 8192;
        #pragma unroll
        for (int ks = 0; ks < 4; ks++) {
            uint32_t ah[2][4], bh[4][2];
            #pragma unroll
            for (int mi = 0; mi < 2; mi++) {
                uint32_t row = wm * 32 + mi * 16 + aRowIdx;
                uint32_t cb = (uint32_t)(kc * 128 + ks * 32) + aK16;
                ldsm4(ah[mi], sC + row * 256 + (cb ^ ((row & 7) << 4)));
            }
            #pragma unroll
            for (int pr = 0; pr < 2; pr++) {
                uint32_t row = wn * 32 + pr * 16 + bRowIdx;
                uint32_t cb = (uint32_t)(ks * 32) + bK16;
                uint32_t tr[4];
                ldsm4(tr, bBuf + row * 128 + (cb ^ ((row & 7) << 4)));
                bh[pr*2][0] = tr[0]; bh[pr*2][1] = tr[1];
                bh[pr*2+1][0] = tr[2]; bh[pr*2+1][1] = tr[3];
            }
            #pragma unroll
            for (int mi = 0; mi < 2; mi++)
                #pragma unroll
                for (int ni = 0; ni < 4; ni++)
                    mma16816(acc[mi][ni], ah[mi], bh[ni]);
        }
        if (kc == 1) {
            #pragma unroll
            for (int mi = 0; mi < 2; mi++) {
                int r0 = wm * 32 + mi * 16 + group;
                int r1 = r0 + 8;
                #pragma unroll
                for (int ni = 0; ni < 4; ni++) {
                    int c = cp * 64 + wn * 32 + ni * 8 + qc;
                    float bv0 = __ldg(&b1[c]), bv1 = __ldg(&b1[c + 1]);
                    uint32_t p0 = pack2(fmaxf(acc[mi][ni][0] + bv0, 0.f),
                                        fmaxf(acc[mi][ni][1] + bv1, 0.f));
                    uint32_t p1 = pack2(fmaxf(acc[mi][ni][2] + bv0, 0.f),
                                        fmaxf(acc[mi][ni][3] + bv1, 0.f));
                    uint32_t cb = (uint32_t)(c * 2);
                    uint32_t a0 = sH + r0 * 512 + (cb ^ ((r0 & 7) << 4));
                    uint32_t a1 = sH + r1 * 512 + (cb ^ ((r1 & 7) << 4));
                    asm volatile("st.shared.b32 [%0], %1;" :: "r"(a0), "r"(p0) : "memory");
                    asm volatile("st.shared.b32 [%0], %1;" :: "r"(a1), "r"(p1) : "memory");
                }
            }
        }
        __syncthreads();
    }

    // ---------- phase 2: x = relu(h1 @ W2 + b2), N=128, K=256 ----------
    loadB(W2h, 256, 0, 0, 0, 128);
    for (int t = 0; t < 8; t++) {
        int cp = t >> 2, kc = t & 3;
        if (t + 1 < 8) {
            loadB(W2h, 256, ((t + 1) >> 2) * 64, ((t + 1) & 3) * 64, (t + 1) & 1, 128);
            asm volatile("cp.async.wait_group 1;" ::: "memory");
        } else {
            asm volatile("cp.async.wait_group 0;" ::: "memory");
        }
        __syncthreads();
        if (kc == 0) zacc();
        uint32_t bBuf = sB + (t & 1) * 8192;
        #pragma unroll
        for (int ks = 0; ks < 4; ks++) {
            uint32_t ah[2][4], bh[4][2];
            #pragma unroll
            for (int mi = 0; mi < 2; mi++) {
                uint32_t row = wm * 32 + mi * 16 + aRowIdx;
                uint32_t cb = (uint32_t)(kc * 128 + ks * 32) + aK16;
                ldsm4(ah[mi], sH + row * 512 + (cb ^ ((row & 7) << 4)));
            }
            #pragma unroll
            for (int pr = 0; pr < 2; pr++) {
                uint32_t row = wn * 32 + pr * 16 + bRowIdx;
                uint32_t cb = (uint32_t)(ks * 32) + bK16;
                uint32_t tr[4];
                ldsm4(tr, bBuf + row * 128 + (cb ^ ((row & 7) << 4)));
                bh[pr*2][0] = tr[0]; bh[pr*2][1] = tr[1];
                bh[pr*2+1][0] = tr[2]; bh[pr*2+1][1] = tr[3];
            }
            #pragma unroll
            for (int mi = 0; mi < 2; mi++)
                #pragma unroll
                for (int ni = 0; ni < 4; ni++)
                    mma16816(acc[mi][ni], ah[mi], bh[ni]);
        }
        if (kc == 3) {
            #pragma unroll
            for (int mi = 0; mi < 2; mi++) {
                int rl0 = wm * 32 + mi * 16 + group;
                int rl1 = rl0 + 8;
                int r0 = rowBase + rl0;
                int r1 = rowBase + rl1;
                #pragma unroll
                for (int ni = 0; ni < 4; ni++) {
                    int c = cp * 64 + wn * 32 + ni * 8 + qc;
                    float bv0 = __ldg(&b2[c]), bv1 = __ldg(&b2[c + 1]);
                    float v00 = fmaxf(acc[mi][ni][0] + bv0, 0.f);
                    float v01 = fmaxf(acc[mi][ni][1] + bv1, 0.f);
                    float v10 = fmaxf(acc[mi][ni][2] + bv0, 0.f);
                    float v11 = fmaxf(acc[mi][ni][3] + bv1, 0.f);
                    uint32_t h0, l0, h1, l1;
                    split2(v00, v01, h0, l0);
                    split2(v10, v11, h1, l1);
                    if (HEAD == 0) {
                        if (r0 < NN) {
                            *(uint32_t*)(Xh + (size_t)r0 * HH + c) = h0;
                            *(uint32_t*)(Xl + (size_t)r0 * HH + c) = l0;
                        }
                        if (r1 < NN) {
                            *(uint32_t*)(Xh + (size_t)r1 * HH + c) = h1;
                            *(uint32_t*)(Xl + (size_t)r1 * HH + c) = l1;
                        }
                    } else {
                        uint32_t cb = (uint32_t)(c * 2);
                        uint32_t a0 = rl0 * 256 + (cb ^ ((rl0 & 7) << 4));
                        uint32_t a1 = rl1 * 256 + (cb ^ ((rl1 & 7) << 4));
                        asm volatile("st.shared.b32 [%0], %1;" :: "r"(sXh + a0), "r"(h0) : "memory");
                        asm volatile("st.shared.b32 [%0], %1;" :: "r"(sXl + a0), "r"(l0) : "memory");
                        asm volatile("st.shared.b32 [%0], %1;" :: "r"(sXh + a1), "r"(h1) : "memory");
                        asm volatile("st.shared.b32 [%0], %1;" :: "r"(sXl + a1), "r"(l1) : "memory");
                    }
                }
            }
        }
        __syncthreads();
    }

    // ---------- phase 3 (HEAD): out = (xh+xl) @ lin_W + lin_b, N=112, K=128 ----
    if (HEAD == 1) {
        loadB(Wlin, 128, 0, 0, 0, OUTD);
        for (int t = 0; t < 4; t++) {
            int cp = t >> 1, kc = t & 1;
            if (t + 1 < 4) {
                loadB(Wlin, 128, ((t + 1) >> 1) * 64, ((t + 1) & 1) * 64, (t + 1) & 1, OUTD);
                asm volatile("cp.async.wait_group 1;" ::: "memory");
            } else {
                asm volatile("cp.async.wait_group 0;" ::: "memory");
            }
            __syncthreads();
            if (kc == 0) zacc();
            uint32_t bBuf = sB + (t & 1) * 8192;
            #pragma unroll
            for (int ks = 0; ks < 4; ks++) {
                uint32_t ah[2][4], al[2][4], bh[4][2];
                #pragma unroll
                for (int mi = 0; mi < 2; mi++) {
                    uint32_t row = wm * 32 + mi * 16 + aRowIdx;
                    uint32_t cb = (uint32_t)(kc * 128 + ks * 32) + aK16;
                    uint32_t off = row * 256 + (cb ^ ((row & 7) << 4));
                    ldsm4(ah[mi], sXh + off);
                    ldsm4(al[mi], sXl + off);
                }
                #pragma unroll
                for (int pr = 0; pr < 2; pr++) {
                    uint32_t row = wn * 32 + pr * 16 + bRowIdx;
                    uint32_t cb = (uint32_t)(ks * 32) + bK16;
                    uint32_t tr[4];
                    ldsm4(tr, bBuf + row * 128 + (cb ^ ((row & 7) << 4)));
                    bh[pr*2][0] = tr[0]; bh[pr*2][1] = tr[1];
                    bh[pr*2+1][0] = tr[2]; bh[pr*2+1][1] = tr[3];
                }
                #pragma unroll
                for (int mi = 0; mi < 2; mi++)
                    #pragma unroll
                    for (int ni = 0; ni < 4; ni++) {
                        mma16816(acc[mi][ni], ah[mi], bh[ni]);
                        mma16816(acc[mi][ni], al[mi], bh[ni]);
                    }
            }
            if (kc == 1) {
                #pragma unroll
                for (int mi = 0; mi < 2; mi++) {
                    int r0 = rowBase + wm * 32 + mi * 16 + group;
                    int r1 = r0 + 8;
                    #pragma unroll
                    for (int ni = 0; ni < 4; ni++) {
                        int c = cp * 64 + wn * 32 + ni * 8 + qc;
                        if (c >= OUTD) continue;
                        float bv0 = __ldg(&blin[c]), bv1 = __ldg(&blin[c + 1]);
                        if (r0 < NN) {
                            float2 v; v.x = acc[mi][ni][0] + bv0; v.y = acc[mi][ni][1] + bv1;
                            *(float2*)(out + (size_t)r0 * OUTD + c) = v;
                        }
                        if (r1 < NN) {
                            float2 v; v.x = acc[mi][ni][2] + bv0; v.y = acc[mi][ni][3] + bv1;
                            *(float2*)(out + (size_t)r1 * OUTD + c) = v;
                        }
                    }
                }
            }
            __syncthreads();
        }
    }
}

// ---------------------------------------------------------------------------
// Unified pipelined fp16 GEMM (encoders). NPROD=1 only here.
// EPI: 0 = +bias ; 2 = *inv + [deg>0]*bias.   Out: fp16 split.
// ---------------------------------------------------------------------------
template <int KTOT, int EPI>
__global__ void __launch_bounds__(256, 2)
gemm_hf(const __half* __restrict__ Ah, const __half* __restrict__ Bhi,
        const float* __restrict__ bias,
        __half* __restrict__ Ch, __half* __restrict__ Cl, int Nc,
        const float* __restrict__ inv, const int* __restrict__ degi) {
    constexpr int CHUNKS = KTOT / 64;
    constexpr int STG = 24576;
    extern __shared__ char smem[];
    const uint32_t sb = smem_u32(smem);

    const int tid  = threadIdx.x;
    const int lane = tid & 31;
    const int wid  = tid >> 5;
    const int wm   = wid & 3;
    const int wn   = wid >> 2;
    const int rowBase = blockIdx.x * 128;
    const int colBase = blockIdx.y * 64;

    float acc[2][4][4];
    #pragma unroll
    for (int a = 0; a < 2; a++)
        #pragma unroll
        for (int b = 0; b < 4; b++)
            #pragma unroll
            for (int c = 0; c < 4; c++) acc[a][b][c] = 0.f;

    auto load_slab = [&](int stage, int c) {
        uint32_t base = sb + stage * STG;
        int kb = c * 64;
        #pragma unroll
        for (int i = 0; i < 4; i++) {
            int f = tid + i * 256;
            int row = f >> 3, chn = f & 7;
            uint32_t sw = (uint32_t)(chn * 16) ^ (uint32_t)((row & 7) << 4);
            uint32_t da = base + row * 128 + sw;
            int gr = rowBase + row;
            if (gr < NN) cp16(da, Ah + (size_t)gr * KTOT + kb + chn * 8);
            else         zero16(da);
        }
        #pragma unroll
        for (int i = 0; i < 2; i++) {
            int f = tid + i * 256;
            int row = f >> 3, chn = f & 7;
            uint32_t sw = (uint32_t)(chn * 16) ^ (uint32_t)((row & 7) << 4);
            uint32_t db = base + 16384 + row * 128 + sw;
            int gn = colBase + row;
            if (gn < Nc) cp16(db, Bhi + (size_t)gn * KTOT + kb + chn * 8);
            else         zero16(db);
        }
        asm volatile("cp.async.commit_group;" ::: "memory");
    };

    const uint32_t aRowIdx = (uint32_t)(lane & 15);
    const uint32_t aK16    = (uint32_t)((lane >> 4) << 4);
    const uint32_t bRowIdx = (uint32_t)((lane & 7) + ((lane >> 4) << 3));
    const uint32_t bK16    = (uint32_t)(((lane >> 3) & 1) << 4);

    load_slab(0, 0);

    for (int c = 0; c < CHUNKS; c++) {
        if (c + 1 < CHUNKS) {
            load_slab((c + 1) & 1, c + 1);
            asm volatile("cp.async.wait_group 1;" ::: "memory");
        } else {
            asm volatile("cp.async.wait_group 0;" ::: "memory");
        }
        __syncthreads();

        uint32_t bA = sb + (c & 1) * STG;
        uint32_t bB = bA + 16384;
        #pragma unroll
        for (int ks = 0; ks < 4; ks++) {
            uint32_t ah[2][4], bh[4][2];
            #pragma unroll
            for (int mi = 0; mi < 2; mi++) {
                uint32_t row = wm * 32 + mi * 16 + aRowIdx;
                uint32_t cb = (uint32_t)(ks * 32) + aK16;
                ldsm4(ah[mi], bA + row * 128 + (cb ^ ((row & 7) << 4)));
            }
            #pragma unroll
            for (int pr = 0; pr < 2; pr++) {
                uint32_t row = wn * 32 + pr * 16 + bRowIdx;
                uint32_t cb = (uint32_t)(ks * 32) + bK16;
                uint32_t t[4];
                ldsm4(t, bB + row * 128 + (cb ^ ((row & 7) << 4)));
                bh[pr*2][0] = t[0]; bh[pr*2][1] = t[1];
                bh[pr*2+1][0] = t[2]; bh[pr*2+1][1] = t[3];
            }
            #pragma unroll
            for (int mi = 0; mi < 2; mi++)
                #pragma unroll
                for (int ni = 0; ni < 4; ni++)
                    mma16816(acc[mi][ni], ah[mi], bh[ni]);
        }
        if (c + 1 < CHUNKS) __syncthreads();
    }

    const int group = lane >> 2;
    const int qc    = (lane & 3) * 2;
    #pragma unroll
    for (int mi = 0; mi < 2; mi++) {
        int r0 = rowBase + wm * 32 + mi * 16 + group;
        int r1 = r0 + 8;
        float iv0 = 0.f, m0 = 0.f, iv1 = 0.f, m1 = 0.f;
        if (EPI == 2) {
            if (r0 < NN) { iv0 = __ldg(&inv[r0]); m0 = (__ldg(&degi[r0]) > 0) ? 1.f : 0.f; }
            if (r1 < NN) { iv1 = __ldg(&inv[r1]); m1 = (__ldg(&degi[r1]) > 0) ? 1.f : 0.f; }
        }
        #pragma unroll
        for (int ni = 0; ni < 4; ni++) {
            int c = colBase + wn * 32 + ni * 8 + qc;
            if (c >= Nc) continue;
            float b0 = __ldg(&bias[c]), b1 = __ldg(&bias[c + 1]);
            float2 v0, v1;
            if (EPI == 2) {
                v0.x = acc[mi][ni][0] * iv0 + m0 * b0;
                v0.y = acc[mi][ni][1] * iv0 + m0 * b1;
                v1.x = acc[mi][ni][2] * iv1 + m1 * b0;
                v1.y = acc[mi][ni][3] * iv1 + m1 * b1;
            } else {
                v0.x = acc[mi][ni][0] + b0; v0.y = acc[mi][ni][1] + b1;
                v1.x = acc[mi][ni][2] + b0; v1.y = acc[mi][ni][3] + b1;
            }
            if (r0 < NN) {
                uint32_t h, l; split2(v0.x, v0.y, h, l);
                *(uint32_t*)(Ch + (size_t)r0 * Nc + c) = h;
                *(uint32_t*)(Cl + (size_t)r0 * Nc + c) = l;
            }
            if (r1 < NN) {
                uint32_t h, l; split2(v1.x, v1.y, h, l);
                *(uint32_t*)(Ch + (size_t)r1 * Nc + c) = h;
                *(uint32_t*)(Cl + (size_t)r1 * Nc + c) = l;
            }
        }
    }
}

// ---------------------------------------------------------------------------
extern "C" void kernel_launch(void* const* d_in, const int* in_sizes, int n_in,
                              void* d_out, int out_size) {
    const float* x_in   = (const float*)d_in[0];
    const float* eattr  = (const float*)d_in[1];
    const int*   eidx   = (const int*)  d_in[2];
    const float* node_W = (const float*)d_in[3];
    const float* node_b = (const float*)d_in[4];
    const float* edge_W = (const float*)d_in[5];
    const float* edge_b = (const float*)d_in[6];
    const float* W1     = (const float*)d_in[7];
    const float* b1     = (const float*)d_in[8];
    const float* W2     = (const float*)d_in[9];
    const float* b2     = (const float*)d_in[10];
    const float* eps    = (const float*)d_in[11];
    const float* lin_W  = (const float*)d_in[12];
    const float* lin_b  = (const float*)d_in[13];
    float* out = (float*)d_out;

    float *pseg, *pinv;
    int *pdegi, *prowptr, *pcursor, *pbflag, *pcsrc;
    __half *pwh, *pch, *pxh, *pxl, *peamh, *peaml, *pxinh, *psegh;
    cudaGetSymbolAddress((void**)&pseg, g_seg);
    cudaGetSymbolAddress((void**)&pinv, g_inv);
    cudaGetSymbolAddress((void**)&pdegi, g_degi);
    cudaGetSymbolAddress((void**)&prowptr, g_rowptr);
    cudaGetSymbolAddress((void**)&pcursor, g_cursor);
    cudaGetSymbolAddress((void**)&pbflag, g_bflag);
    cudaGetSymbolAddress((void**)&pcsrc, g_csrc);
    cudaGetSymbolAddress((void**)&pwh,  g_whi);
    cudaGetSymbolAddress((void**)&pch,  g_ch);
    cudaGetSymbolAddress((void**)&pxh,  g_xh);
    cudaGetSymbolAddress((void**)&pxl,  g_xl);
    cudaGetSymbolAddress((void**)&peamh, g_eamh);
    cudaGetSymbolAddress((void**)&peaml, g_eaml);
    cudaGetSymbolAddress((void**)&pxinh, g_xinh);
    cudaGetSymbolAddress((void**)&psegh, g_segh);

    constexpr int SM_HF   = 49152;
    constexpr int SM_MLP0 = 65536;
    constexpr int SM_MLP1 = 98304;
    auto setsm = [](const void* f, int b) {
        cudaFuncSetAttribute(f, cudaFuncAttributeMaxDynamicSharedMemorySize, b);
    };
    setsm((const void*)gemm_hf<128, 0>, SM_HF);
    setsm((const void*)gemm_hf< 64, 2>, SM_HF);
    setsm((const void*)mlp_fused<0>, SM_MLP0);
    setsm((const void*)mlp_fused<1>, SM_MLP1);

    // ---- resets ----
    cudaMemsetAsync(pdegi, 0, NN * sizeof(int));
    cudaMemsetAsync(pseg, 0, (size_t)NN * IN_EDGE * sizeof(float));
    cudaMemsetAsync(pbflag, 0, NB * sizeof(int));

    // ---- front: weight prep + deg + seg scatter + x_in round ----
    front_kernel<<<FB_W + FB_DEG + FB_SEG + FB_X, 256>>>(
        node_W, edge_W, W1, W2, lin_W, pwh, eidx, pdegi, eattr, pseg, x_in, pxinh);

    // ---- scan, then merged seg2h + csr_fill ----
    scan_fused<<<NB, 256>>>(pdegi, pbflag, prowptr, pcursor, pinv);
    mid_kernel<<<MB_SEG + (EE + 255) / 256, 256>>>(pseg, psegh, eidx, pcursor, pcsrc);

    dim3 g2(TILES_M, 2);

    // node encoder: x(split) = xinh @ node_W + node_b
    gemm_hf<128, 0><<<g2, 256, SM_HF>>>(pxinh, pwh, node_b,
        pxh, pxl, HH, nullptr, nullptr);
    // edge encoder: eam(split) = (segh @ edge_W)*inv + [deg>0]*edge_b
    gemm_hf<64, 2><<<g2, 256, SM_HF>>>(psegh, pwh + 16384, edge_b,
        peamh, peaml, HH, pinv, pdegi);

    for (int l = 0; l < 3; l++) {
        gather_combine<<<(NN * 32 + 255) / 256, 256>>>(prowptr, pcsrc, pxh, pxl,
            peamh, peaml, pinv, eps, l, pch);
        if (l < 2) {
            mlp_fused<0><<<NBM, 128, SM_MLP0>>>(pch,
                pwh + 24576 + l * 32768, b1 + (size_t)l * HH2,
                pwh + 122880 + l * 32768, b2 + (size_t)l * HH,
                pxh, pxl, nullptr, nullptr, nullptr);
        } else {
            mlp_fused<1><<<NBM, 128, SM_MLP1>>>(pch,
                pwh + 24576 + l * 32768, b1 + (size_t)l * HH2,
                pwh + 122880 + l * 32768, b2 + (size_t)l * HH,
                nullptr, nullptr, pwh + 221184, lin_b, out);
        }
    }
}

// round 14
// speedup vs baseline: 2.3173x; 1.0167x over previous
#include <cuda_runtime.h>
#include <cuda_fp16.h>
#include <cstdint>

#define NN     50000
#define EE     625000
#define IN_EDGE 64
#define HH     128
#define HH2    256
#define OUTD   112
#define TILES_M 391   // ceil(50000/128)
#define NBM    782    // ceil(50000/64)
#define NB     196    // ceil(50000/256)

// ---------------- scratch (device globals; no allocation allowed) ----------
__device__ __align__(16) float g_seg[NN * IN_EDGE];
__device__ float g_inv[NN];
__device__ int   g_degi[NN];
__device__ int   g_rowptr[NN + 1];
__device__ int   g_cursor[NN];
__device__ int   g_bflag[NB];
__device__ int   g_csrc[EE];

// activations
__device__ __align__(16) __half g_xinh[NN * HH];     // x_in rounded fp16
__device__ __align__(16) __half g_segh[NN * IN_EDGE];// seg rounded fp16
__device__ __align__(16) __half g_ch  [NN * HH];     // combined (hi), W1 input
__device__ __align__(16) __half g_xh  [NN * HH];     // node state (split hi)
__device__ __align__(16) __half g_xl  [NN * HH];     // node state (split lo)
__device__ __align__(16) __half g_eamh[NN * HH];     // edge-agg-mean (split)
__device__ __align__(16) __half g_eaml[NN * HH];

// pre-rounded transposed weights, layout [N][K] fp16
__device__ __align__(16) __half g_whi[235520];

// ---------------------------------------------------------------------------
__device__ __forceinline__ uint32_t smem_u32(const void* p) {
    uint32_t a;
    asm("{ .reg .u64 t; cvta.to.shared.u64 t, %1; cvt.u32.u64 %0, t; }"
        : "=r"(a) : "l"(p));
    return a;
}
__device__ __forceinline__ void cp16(uint32_t dst, const void* src) {
    asm volatile("cp.async.cg.shared.global [%0], [%1], 16;"
                 :: "r"(dst), "l"(src) : "memory");
}
__device__ __forceinline__ void zero16(uint32_t dst) {
    asm volatile("st.shared.v4.b32 [%0], {%1,%1,%1,%1};" :: "r"(dst), "r"(0) : "memory");
}
__device__ __forceinline__ void ldsm4(uint32_t* r, uint32_t addr) {
    asm volatile("ldmatrix.sync.aligned.m8n8.x4.shared.b16 {%0,%1,%2,%3}, [%4];"
                 : "=r"(r[0]), "=r"(r[1]), "=r"(r[2]), "=r"(r[3]) : "r"(addr));
}
__device__ __forceinline__ void mma16816(float* d, const uint32_t* a, const uint32_t* b) {
    asm volatile("mma.sync.aligned.m16n8k16.row.col.f32.f16.f16.f32 "
                 "{%0,%1,%2,%3}, {%4,%5,%6,%7}, {%8,%9}, {%0,%1,%2,%3};"
                 : "+f"(d[0]), "+f"(d[1]), "+f"(d[2]), "+f"(d[3])
                 : "r"(a[0]), "r"(a[1]), "r"(a[2]), "r"(a[3]), "r"(b[0]), "r"(b[1]));
}
__device__ __forceinline__ void split2(float a, float b, uint32_t& hi, uint32_t& lo) {
    __half ha = __float2half(a), hb = __float2half(b);
    __half2 h = __halves2half2(ha, hb);
    __half2 l = __halves2half2(
        __float2half(a - __half2float(ha)),
        __float2half(b - __half2float(hb)));
    hi = *(uint32_t*)&h; lo = *(uint32_t*)&l;
}
__device__ __forceinline__ uint32_t pack2(float a, float b) {
    __half2 h = __halves2half2(__float2half(a), __float2half(b));
    return *(uint32_t*)&h;
}
__device__ __forceinline__ float2 unpack2(uint32_t h, uint32_t l) {
    __half2 hh = *(__half2*)&h;
    __half2 ll = *(__half2*)&l;
    return make_float2(__low2float(hh) + __low2float(ll),
                       __high2float(hh) + __high2float(ll));
}
__device__ __forceinline__ void red_add_v4(float* addr, float4 v) {
    asm volatile("red.global.add.v4.f32 [%0], {%1,%2,%3,%4};"
                 :: "l"(addr), "f"(v.x), "f"(v.y), "f"(v.z), "f"(v.w) : "memory");
}

// ---------------------------------------------------------------------------
// front: weight prep + degree histogram + seg scatter + x_in fp16 rounding
// ---------------------------------------------------------------------------
#define FB_W   920
#define FB_DEG 2442
#define FB_SEG 39063
#define FB_X   3125
__global__ void front_kernel(const float* __restrict__ node_W, const float* __restrict__ edge_W,
                             const float* __restrict__ W1, const float* __restrict__ W2,
                             const float* __restrict__ lin_W,
                             __half* __restrict__ hi,
                             const int* __restrict__ ei, int* __restrict__ degi,
                             const float* __restrict__ ea, float* __restrict__ seg,
                             const float* __restrict__ x_in, __half* __restrict__ xinh) {
    if (blockIdx.x < FB_W) {
        int i = blockIdx.x * 256 + threadIdx.x;
        if (i >= 235520) return;
        const float* src; int K, Nc, idx;
        if (i < 16384)       { src = node_W;                 K = 128; Nc = 128; idx = i; }
        else if (i < 24576)  { src = edge_W;                 K =  64; Nc = 128; idx = i - 16384; }
        else if (i < 122880) { int j = i - 24576;  src = W1 + (j / 32768) * 32768; K = 128; Nc = 256; idx = j % 32768; }
        else if (i < 221184) { int j = i - 122880; src = W2 + (j / 32768) * 32768; K = 256; Nc = 128; idx = j % 32768; }
        else                 { src = lin_W;                  K = 128; Nc = 112; idx = i - 221184; }
        int n = idx / K, k = idx % K;
        hi[i] = __float2half(__ldg(&src[(size_t)k * Nc + n]));
    } else if (blockIdx.x < FB_W + FB_DEG) {
        int e = (blockIdx.x - FB_W) * 256 + threadIdx.x;
        if (e < EE) atomicAdd(&degi[ei[EE + e]], 1);
    } else if (blockIdx.x < FB_W + FB_DEG + FB_SEG) {
        int gid = (blockIdx.x - FB_W - FB_DEG) * 256 + threadIdx.x;
        if (gid >= EE * 16) return;
        int e = gid >> 4, g = gid & 15;
        int dst = __ldg(&ei[EE + e]);
        float4 v = __ldg(((const float4*)ea) + (size_t)e * 16 + g);
        red_add_v4(seg + (size_t)dst * IN_EDGE + g * 4, v);
    } else {
        int gid = (blockIdx.x - FB_W - FB_DEG - FB_SEG) * 256 + threadIdx.x;
        size_t base = (size_t)gid * 8;
        if (base >= (size_t)NN * HH) return;
        float4 v0 = __ldg((const float4*)(x_in + base));
        float4 v1 = __ldg((const float4*)(x_in + base + 4));
        uint4 o;
        o.x = pack2(v0.x, v0.y); o.y = pack2(v0.z, v0.w);
        o.z = pack2(v1.x, v1.y); o.w = pack2(v1.z, v1.w);
        *(uint4*)(xinh + base) = o;
    }
}

// ---------------------------------------------------------------------------
// single-kernel exclusive scan (decoupled lookback over 196 blocks)
// ---------------------------------------------------------------------------
__global__ void scan_fused(const int* __restrict__ d, int* __restrict__ bflag,
                           int* __restrict__ rowptr, int* __restrict__ cursor,
                           float* __restrict__ inv) {
    __shared__ int s[256];
    __shared__ int sred[256];
    int b = blockIdx.x;
    int t = threadIdx.x;
    int i = b * 256 + t;
    int v = (i < NN) ? d[i] : 0;
    s[t] = v;
    __syncthreads();
    #pragma unroll
    for (int o = 1; o < 256; o <<= 1) {
        int tv = (t >= o) ? s[t - o] : 0;
        __syncthreads();
        s[t] += tv;
        __syncthreads();
    }
    int incl = s[t];
    int agg = s[255];
    if (t == 0) atomicExch(&bflag[b], agg + 1);
    int pval = 0;
    if (t < b) {
        int x;
        do { x = atomicAdd(&bflag[t], 0); } while (x == 0);
        pval = x - 1;
    }
    sred[t] = pval;
    __syncthreads();
    #pragma unroll
    for (int o = 128; o > 0; o >>= 1) {
        if (t < o) sred[t] += sred[t + o];
        __syncthreads();
    }
    int boffv = sred[0];
    if (i < NN) {
        int excl = incl - v + boffv;
        rowptr[i] = excl;
        cursor[i] = excl;
        inv[i] = 1.0f / (float)max(v, 1);
    }
    if (b == NB - 1 && t == 255) rowptr[NN] = boffv + agg;
}

// merged: seg fp32->fp16 conversion + csr fill
#define MB_SEG 1563
__global__ void mid_kernel(const float* __restrict__ seg, __half* __restrict__ segh,
                           const int* __restrict__ ei, int* __restrict__ cursor,
                           int* __restrict__ csrc) {
    if (blockIdx.x < MB_SEG) {
        size_t base = ((size_t)blockIdx.x * 256 + threadIdx.x) * 8;
        if (base >= (size_t)NN * IN_EDGE) return;
        float4 v0 = __ldg((const float4*)(seg + base));
        float4 v1 = __ldg((const float4*)(seg + base + 4));
        uint4 o;
        o.x = pack2(v0.x, v0.y); o.y = pack2(v0.z, v0.w);
        o.z = pack2(v1.x, v1.y); o.w = pack2(v1.z, v1.w);
        *(uint4*)(segh + base) = o;
    } else {
        int e = (blockIdx.x - MB_SEG) * 256 + threadIdx.x;
        if (e >= EE) return;
        int dst = __ldg(&ei[EE + e]);
        int p = atomicAdd(&cursor[dst], 1);
        csrc[p] = __ldg(&ei[e]);
    }
}

// fused: agg = sum_neighbors(x_hi) ; c = (1+eps)*x + agg*inv + eam -> ch (fp16 hi)
__global__ void gather_combine(const int* __restrict__ rowptr, const int* __restrict__ csrc,
                               const __half* __restrict__ xh,
                               const __half* __restrict__ xl,
                               const __half* __restrict__ eamh,
                               const __half* __restrict__ eaml,
                               const float* __restrict__ inv,
                               const float* __restrict__ eps_p, int layer,
                               __half* __restrict__ ch) {
    int w = (blockIdx.x * blockDim.x + threadIdx.x) >> 5;
    if (w >= NN) return;
    int lane = threadIdx.x & 31;
    int beg = __ldg(&rowptr[w]), end = __ldg(&rowptr[w + 1]);
    float a0 = 0.f, a1 = 0.f, a2 = 0.f, a3 = 0.f;
    for (int j = beg; j < end; j++) {
        int s = __ldg(&csrc[j]);
        uint2 hv = __ldg((const uint2*)(xh + (size_t)s * HH) + lane);
        __half2 h0 = *(__half2*)&hv.x;
        __half2 h1 = *(__half2*)&hv.y;
        a0 += __low2float(h0); a1 += __high2float(h0);
        a2 += __low2float(h1); a3 += __high2float(h1);
    }
    float iv = __ldg(&inv[w]);
    float epsv = 1.f + __ldg(&eps_p[layer]);
    uint2 hs = __ldg((const uint2*)(xh + (size_t)w * HH) + lane);
    uint2 ls = __ldg((const uint2*)(xl + (size_t)w * HH) + lane);
    float2 x01 = unpack2(hs.x, ls.x);
    float2 x23 = unpack2(hs.y, ls.y);
    uint2 eh = __ldg((const uint2*)(eamh + (size_t)w * HH) + lane);
    uint2 el = __ldg((const uint2*)(eaml + (size_t)w * HH) + lane);
    float2 e01 = unpack2(eh.x, el.x);
    float2 e23 = unpack2(eh.y, el.y);
    uint2 h;
    h.x = pack2(epsv * x01.x + a0 * iv + e01.x, epsv * x01.y + a1 * iv + e01.y);
    h.y = pack2(epsv * x23.x + a2 * iv + e23.x, epsv * x23.y + a3 * iv + e23.y);
    *(uint2*)(ch + (size_t)w * HH + lane * 4) = h;
}

// ---------------------------------------------------------------------------
// Fused GIN MLP (HEAD=1: + output head in phase 3, x never hits global).
// ---------------------------------------------------------------------------
template <int HEAD>
__global__ void __launch_bounds__(128, 2)
mlp_fused(const __half* __restrict__ C, const __half* __restrict__ W1h,
          const float* __restrict__ b1, const __half* __restrict__ W2h,
          const float* __restrict__ b2,
          __half* __restrict__ Xh, __half* __restrict__ Xl,
          const __half* __restrict__ Wlin, const float* __restrict__ blin,
          float* __restrict__ out) {
    extern __shared__ char smem[];
    const uint32_t sC = smem_u32(smem);
    const uint32_t sH = sC + 16384;
    const uint32_t sB = sC + 49152;
    const uint32_t sXh = sB + 16384;
    const uint32_t sXl = sXh + 16384;

    const int tid  = threadIdx.x;
    const int lane = tid & 31;
    const int wid  = tid >> 5;
    const int wm   = wid & 1;
    const int wn   = wid >> 1;
    const int rowBase = blockIdx.x * 64;

    #pragma unroll
    for (int i = 0; i < 8; i++) {
        int f = tid + i * 128;
        int row = f >> 4, chn = f & 15;
        uint32_t addr = sC + row * 256 + (((uint32_t)(chn * 16)) ^ ((row & 7) << 4));
        int gr = rowBase + row;
        if (gr < NN) cp16(addr, C + (size_t)gr * HH + chn * 8);
        else         zero16(addr);
    }
    asm volatile("cp.async.commit_group;" ::: "memory");

    const uint32_t aRowIdx = (uint32_t)(lane & 15);
    const uint32_t aK16    = (uint32_t)((lane >> 4) << 4);
    const uint32_t bRowIdx = (uint32_t)((lane & 7) + ((lane >> 4) << 3));
    const uint32_t bK16    = (uint32_t)(((lane >> 3) & 1) << 4);
    const int group = lane >> 2;
    const int qc    = (lane & 3) * 2;

    float acc[2][4][4];

    auto loadB = [&](const __half* W, int KT, int gn0, int kb, int stage, int NcB) {
        #pragma unroll
        for (int i = 0; i < 4; i++) {
            int f = tid + i * 128;
            int row = f >> 3, chn = f & 7;
            uint32_t addr = sB + stage * 8192 + row * 128 +
                            (((uint32_t)(chn * 16)) ^ ((row & 7) << 4));
            if (gn0 + row < NcB) cp16(addr, W + (size_t)(gn0 + row) * KT + kb + chn * 8);
            else                 zero16(addr);
        }
        asm volatile("cp.async.commit_group;" ::: "memory");
    };
    auto zacc = [&]() {
        #pragma unroll
        for (int a = 0; a < 2; a++)
            #pragma unroll
            for (int b = 0; b < 4; b++)
                #pragma unroll
                for (int c = 0; c < 4; c++) acc[a][b][c] = 0.f;
    };

    // ---------- phase 1: h1(smem) = relu(c @ W1 + b1), N=256, K=128 ----------
    loadB(W1h, 128, 0, 0, 0, 256);
    for (int t = 0; t < 8; t++) {
        int cp = t >> 1, kc = t & 1;
        if (t + 1 < 8) {
            loadB(W1h, 128, ((t + 1) >> 1) * 64, ((t + 1) & 1) * 64, (t + 1) & 1, 256);
            asm volatile("cp.async.wait_group 1;" ::: "memory");
        } else {
            asm volatile("cp.async.wait_group 0;" ::: "memory");
        }
        __syncthreads();
        if (kc == 0) zacc();
        uint32_t bBuf = sB + (t & 1) * 8192;
        #pragma unroll
        for (int ks = 0; ks < 4; ks++) {
            uint32_t ah[2][4], bh[4][2];
            #pragma unroll
            for (int mi = 0; mi < 2; mi++) {
                uint32_t row = wm * 32 + mi * 16 + aRowIdx;
                uint32_t cb = (uint32_t)(kc * 128 + ks * 32) + aK16;
                ldsm4(ah[mi], sC + row * 256 + (cb ^ ((row & 7) << 4)));
            }
            #pragma unroll
            for (int pr = 0; pr < 2; pr++) {
                uint32_t row = wn * 32 + pr * 16 + bRowIdx;
                uint32_t cb = (uint32_t)(ks * 32) + bK16;
                uint32_t tr[4];
                ldsm4(tr, bBuf + row * 128 + (cb ^ ((row & 7) << 4)));
                bh[pr*2][0] = tr[0]; bh[pr*2][1] = tr[1];
                bh[pr*2+1][0] = tr[2]; bh[pr*2+1][1] = tr[3];
            }
            #pragma unroll
            for (int mi = 0; mi < 2; mi++)
                #pragma unroll
                for (int ni = 0; ni < 4; ni++)
                    mma16816(acc[mi][ni], ah[mi], bh[ni]);
        }
        if (kc == 1) {
            #pragma unroll
            for (int mi = 0; mi < 2; mi++) {
                int r0 = wm * 32 + mi * 16 + group;
                int r1 = r0 + 8;
                #pragma unroll
                for (int ni = 0; ni < 4; ni++) {
                    int c = cp * 64 + wn * 32 + ni * 8 + qc;
                    float bv0 = __ldg(&b1[c]), bv1 = __ldg(&b1[c + 1]);
                    uint32_t p0 = pack2(fmaxf(acc[mi][ni][0] + bv0, 0.f),
                                        fmaxf(acc[mi][ni][1] + bv1, 0.f));
                    uint32_t p1 = pack2(fmaxf(acc[mi][ni][2] + bv0, 0.f),
                                        fmaxf(acc[mi][ni][3] + bv1, 0.f));
                    uint32_t cb = (uint32_t)(c * 2);
                    uint32_t a0 = sH + r0 * 512 + (cb ^ ((r0 & 7) << 4));
                    uint32_t a1 = sH + r1 * 512 + (cb ^ ((r1 & 7) << 4));
                    asm volatile("st.shared.b32 [%0], %1;" :: "r"(a0), "r"(p0) : "memory");
                    asm volatile("st.shared.b32 [%0], %1;" :: "r"(a1), "r"(p1) : "memory");
                }
            }
        }
        __syncthreads();
    }

    // ---------- phase 2: x = relu(h1 @ W2 + b2), N=128, K=256 ----------
    loadB(W2h, 256, 0, 0, 0, 128);
    for (int t = 0; t < 8; t++) {
        int cp = t >> 2, kc = t & 3;
        if (t + 1 < 8) {
            loadB(W2h, 256, ((t + 1) >> 2) * 64, ((t + 1) & 3) * 64, (t + 1) & 1, 128);
            asm volatile("cp.async.wait_group 1;" ::: "memory");
        } else {
            asm volatile("cp.async.wait_group 0;" ::: "memory");
        }
        __syncthreads();
        if (kc == 0) zacc();
        uint32_t bBuf = sB + (t & 1) * 8192;
        #pragma unroll
        for (int ks = 0; ks < 4; ks++) {
            uint32_t ah[2][4], bh[4][2];
            #pragma unroll
            for (int mi = 0; mi < 2; mi++) {
                uint32_t row = wm * 32 + mi * 16 + aRowIdx;
                uint32_t cb = (uint32_t)(kc * 128 + ks * 32) + aK16;
                ldsm4(ah[mi], sH + row * 512 + (cb ^ ((row & 7) << 4)));
            }
            #pragma unroll
            for (int pr = 0; pr < 2; pr++) {
                uint32_t row = wn * 32 + pr * 16 + bRowIdx;
                uint32_t cb = (uint32_t)(ks * 32) + bK16;
                uint32_t tr[4];
                ldsm4(tr, bBuf + row * 128 + (cb ^ ((row & 7) << 4)));
                bh[pr*2][0] = tr[0]; bh[pr*2][1] = tr[1];
                bh[pr*2+1][0] = tr[2]; bh[pr*2+1][1] = tr[3];
            }
            #pragma unroll
            for (int mi = 0; mi < 2; mi++)
                #pragma unroll
                for (int ni = 0; ni < 4; ni++)
                    mma16816(acc[mi][ni], ah[mi], bh[ni]);
        }
        if (kc == 3) {
            #pragma unroll
            for (int mi = 0; mi < 2; mi++) {
                int rl0 = wm * 32 + mi * 16 + group;
                int rl1 = rl0 + 8;
                int r0 = rowBase + rl0;
                int r1 = rowBase + rl1;
                #pragma unroll
                for (int ni = 0; ni < 4; ni++) {
                    int c = cp * 64 + wn * 32 + ni * 8 + qc;
                    float bv0 = __ldg(&b2[c]), bv1 = __ldg(&b2[c + 1]);
                    float v00 = fmaxf(acc[mi][ni][0] + bv0, 0.f);
                    float v01 = fmaxf(acc[mi][ni][1] + bv1, 0.f);
                    float v10 = fmaxf(acc[mi][ni][2] + bv0, 0.f);
                    float v11 = fmaxf(acc[mi][ni][3] + bv1, 0.f);
                    uint32_t h0, l0, h1, l1;
                    split2(v00, v01, h0, l0);
                    split2(v10, v11, h1, l1);
                    if (HEAD == 0) {
                        if (r0 < NN) {
                            *(uint32_t*)(Xh + (size_t)r0 * HH + c) = h0;
                            *(uint32_t*)(Xl + (size_t)r0 * HH + c) = l0;
                        }
                        if (r1 < NN) {
                            *(uint32_t*)(Xh + (size_t)r1 * HH + c) = h1;
                            *(uint32_t*)(Xl + (size_t)r1 * HH + c) = l1;
                        }
                    } else {
                        uint32_t cb = (uint32_t)(c * 2);
                        uint32_t a0 = rl0 * 256 + (cb ^ ((rl0 & 7) << 4));
                        uint32_t a1 = rl1 * 256 + (cb ^ ((rl1 & 7) << 4));
                        asm volatile("st.shared.b32 [%0], %1;" :: "r"(sXh + a0), "r"(h0) : "memory");
                        asm volatile("st.shared.b32 [%0], %1;" :: "r"(sXl + a0), "r"(l0) : "memory");
                        asm volatile("st.shared.b32 [%0], %1;" :: "r"(sXh + a1), "r"(h1) : "memory");
                        asm volatile("st.shared.b32 [%0], %1;" :: "r"(sXl + a1), "r"(l1) : "memory");
                    }
                }
            }
        }
        __syncthreads();
    }

    // ---------- phase 3 (HEAD): out = (xh+xl) @ lin_W + lin_b ----------
    if (HEAD == 1) {
        loadB(Wlin, 128, 0, 0, 0, OUTD);
        for (int t = 0; t < 4; t++) {
            int cp = t >> 1, kc = t & 1;
            if (t + 1 < 4) {
                loadB(Wlin, 128, ((t + 1) >> 1) * 64, ((t + 1) & 1) * 64, (t + 1) & 1, OUTD);
                asm volatile("cp.async.wait_group 1;" ::: "memory");
            } else {
                asm volatile("cp.async.wait_group 0;" ::: "memory");
            }
            __syncthreads();
            if (kc == 0) zacc();
            uint32_t bBuf = sB + (t & 1) * 8192;
            #pragma unroll
            for (int ks = 0; ks < 4; ks++) {
                uint32_t ah[2][4], al[2][4], bh[4][2];
                #pragma unroll
                for (int mi = 0; mi < 2; mi++) {
                    uint32_t row = wm * 32 + mi * 16 + aRowIdx;
                    uint32_t cb = (uint32_t)(kc * 128 + ks * 32) + aK16;
                    uint32_t off = row * 256 + (cb ^ ((row & 7) << 4));
                    ldsm4(ah[mi], sXh + off);
                    ldsm4(al[mi], sXl + off);
                }
                #pragma unroll
                for (int pr = 0; pr < 2; pr++) {
                    uint32_t row = wn * 32 + pr * 16 + bRowIdx;
                    uint32_t cb = (uint32_t)(ks * 32) + bK16;
                    uint32_t tr[4];
                    ldsm4(tr, bBuf + row * 128 + (cb ^ ((row & 7) << 4)));
                    bh[pr*2][0] = tr[0]; bh[pr*2][1] = tr[1];
                    bh[pr*2+1][0] = tr[2]; bh[pr*2+1][1] = tr[3];
                }
                #pragma unroll
                for (int mi = 0; mi < 2; mi++)
                    #pragma unroll
                    for (int ni = 0; ni < 4; ni++) {
                        mma16816(acc[mi][ni], ah[mi], bh[ni]);
                        mma16816(acc[mi][ni], al[mi], bh[ni]);
                    }
            }
            if (kc == 1) {
                #pragma unroll
                for (int mi = 0; mi < 2; mi++) {
                    int r0 = rowBase + wm * 32 + mi * 16 + group;
                    int r1 = r0 + 8;
                    #pragma unroll
                    for (int ni = 0; ni < 4; ni++) {
                        int c = cp * 64 + wn * 32 + ni * 8 + qc;
                        if (c >= OUTD) continue;
                        float bv0 = __ldg(&blin[c]), bv1 = __ldg(&blin[c + 1]);
                        if (r0 < NN) {
                            float2 v; v.x = acc[mi][ni][0] + bv0; v.y = acc[mi][ni][1] + bv1;
                            *(float2*)(out + (size_t)r0 * OUTD + c) = v;
                        }
                        if (r1 < NN) {
                            float2 v; v.x = acc[mi][ni][2] + bv0; v.y = acc[mi][ni][3] + bv1;
                            *(float2*)(out + (size_t)r1 * OUTD + c) = v;
                        }
                    }
                }
            }
            __syncthreads();
        }
    }
}

// ---------------------------------------------------------------------------
// MERGED encoder kernel: grid (TILES_M, 4).
//  by>>1 == 0: node encoder  x(split) = xinh @ Wnode + node_b   (K=128, EPI 0)
//  by>>1 == 1: edge encoder  eam(split) = (segh @ Wedge)*inv + [deg>0]*edge_b (K=64, EPI 2)
// Runtime-K pipelined loader; bit-identical arithmetic to round-13 encoders.
// ---------------------------------------------------------------------------
__global__ void __launch_bounds__(256, 2)
enc_kernel(const __half* __restrict__ xinh, const __half* __restrict__ segh,
           const __half* __restrict__ wall,
           const float* __restrict__ node_b, const float* __restrict__ edge_b,
           __half* __restrict__ xh, __half* __restrict__ xl,
           __half* __restrict__ eamh, __half* __restrict__ eaml,
           const float* __restrict__ inv, const int* __restrict__ degi) {
    constexpr int STG = 24576;
    extern __shared__ char smem[];
    const uint32_t sb = smem_u32(smem);

    const int task = blockIdx.y >> 1;          // 0 = node, 1 = edge
    const int colBase = (blockIdx.y & 1) * 64;
    const int KT      = task ? 64 : 128;
    const int CHUNKS  = task ? 1 : 2;
    const __half* Ah  = task ? segh : xinh;
    const __half* Bhi = task ? (wall + 16384) : wall;
    const float* bias = task ? edge_b : node_b;
    __half* Ch = task ? eamh : xh;
    __half* Cl = task ? eaml : xl;

    const int tid  = threadIdx.x;
    const int lane = tid & 31;
    const int wid  = tid >> 5;
    const int wm   = wid & 3;
    const int wn   = wid >> 2;
    const int rowBase = blockIdx.x * 128;

    float acc[2][4][4];
    #pragma unroll
    for (int a = 0; a < 2; a++)
        #pragma unroll
        for (int b = 0; b < 4; b++)
            #pragma unroll
            for (int c = 0; c < 4; c++) acc[a][b][c] = 0.f;

    auto load_slab = [&](int stage, int c) {
        uint32_t base = sb + stage * STG;
        int kb = c * 64;
        #pragma unroll
        for (int i = 0; i < 4; i++) {
            int f = tid + i * 256;
            int row = f >> 3, chn = f & 7;
            uint32_t sw = (uint32_t)(chn * 16) ^ (uint32_t)((row & 7) << 4);
            uint32_t da = base + row * 128 + sw;
            int gr = rowBase + row;
            if (gr < NN) cp16(da, Ah + (size_t)gr * KT + kb + chn * 8);
            else         zero16(da);
        }
        #pragma unroll
        for (int i = 0; i < 2; i++) {
            int f = tid + i * 256;
            int row = f >> 3, chn = f & 7;
            uint32_t sw = (uint32_t)(chn * 16) ^ (uint32_t)((row & 7) << 4);
            uint32_t db = base + 16384 + row * 128 + sw;
            cp16(db, Bhi + (size_t)(colBase + row) * KT + kb + chn * 8);
        }
        asm volatile("cp.async.commit_group;" ::: "memory");
    };

    const uint32_t aRowIdx = (uint32_t)(lane & 15);
    const uint32_t aK16    = (uint32_t)((lane >> 4) << 4);
    const uint32_t bRowIdx = (uint32_t)((lane & 7) + ((lane >> 4) << 3));
    const uint32_t bK16    = (uint32_t)(((lane >> 3) & 1) << 4);

    load_slab(0, 0);

    for (int c = 0; c < CHUNKS; c++) {
        if (c + 1 < CHUNKS) {
            load_slab((c + 1) & 1, c + 1);
            asm volatile("cp.async.wait_group 1;" ::: "memory");
        } else {
            asm volatile("cp.async.wait_group 0;" ::: "memory");
        }
        __syncthreads();

        uint32_t bA = sb + (c & 1) * STG;
        uint32_t bB = bA + 16384;
        #pragma unroll
        for (int ks = 0; ks < 4; ks++) {
            uint32_t ah[2][4], bh[4][2];
            #pragma unroll
            for (int mi = 0; mi < 2; mi++) {
                uint32_t row = wm * 32 + mi * 16 + aRowIdx;
                uint32_t cb = (uint32_t)(ks * 32) + aK16;
                ldsm4(ah[mi], bA + row * 128 + (cb ^ ((row & 7) << 4)));
            }
            #pragma unroll
            for (int pr = 0; pr < 2; pr++) {
                uint32_t row = wn * 32 + pr * 16 + bRowIdx;
                uint32_t cb = (uint32_t)(ks * 32) + bK16;
                uint32_t t[4];
                ldsm4(t, bB + row * 128 + (cb ^ ((row & 7) << 4)));
                bh[pr*2][0] = t[0]; bh[pr*2][1] = t[1];
                bh[pr*2+1][0] = t[2]; bh[pr*2+1][1] = t[3];
            }
            #pragma unroll
            for (int mi = 0; mi < 2; mi++)
                #pragma unroll
                for (int ni = 0; ni < 4; ni++)
                    mma16816(acc[mi][ni], ah[mi], bh[ni]);
        }
        if (c + 1 < CHUNKS) __syncthreads();
    }

    const int group = lane >> 2;
    const int qc    = (lane & 3) * 2;
    #pragma unroll
    for (int mi = 0; mi < 2; mi++) {
        int r0 = rowBase + wm * 32 + mi * 16 + group;
        int r1 = r0 + 8;
        float iv0 = 0.f, m0 = 0.f, iv1 = 0.f, m1 = 0.f;
        if (task == 1) {
            if (r0 < NN) { iv0 = __ldg(&inv[r0]); m0 = (__ldg(&degi[r0]) > 0) ? 1.f : 0.f; }
            if (r1 < NN) { iv1 = __ldg(&inv[r1]); m1 = (__ldg(&degi[r1]) > 0) ? 1.f : 0.f; }
        }
        #pragma unroll
        for (int ni = 0; ni < 4; ni++) {
            int c = colBase + wn * 32 + ni * 8 + qc;
            float b0 = __ldg(&bias[c]), b1 = __ldg(&bias[c + 1]);
            float2 v0, v1;
            if (task == 1) {
                v0.x = acc[mi][ni][0] * iv0 + m0 * b0;
                v0.y = acc[mi][ni][1] * iv0 + m0 * b1;
                v1.x = acc[mi][ni][2] * iv1 + m1 * b0;
                v1.y = acc[mi][ni][3] * iv1 + m1 * b1;
            } else {
                v0.x = acc[mi][ni][0] + b0; v0.y = acc[mi][ni][1] + b1;
                v1.x = acc[mi][ni][2] + b0; v1.y = acc[mi][ni][3] + b1;
            }
            if (r0 < NN) {
                uint32_t h, l; split2(v0.x, v0.y, h, l);
                *(uint32_t*)(Ch + (size_t)r0 * HH + c) = h;
                *(uint32_t*)(Cl + (size_t)r0 * HH + c) = l;
            }
            if (r1 < NN) {
                uint32_t h, l; split2(v1.x, v1.y, h, l);
                *(uint32_t*)(Ch + (size_t)r1 * HH + c) = h;
                *(uint32_t*)(Cl + (size_t)r1 * HH + c) = l;
            }
        }
    }
}

// ---------------------------------------------------------------------------
extern "C" void kernel_launch(void* const* d_in, const int* in_sizes, int n_in,
                              void* d_out, int out_size) {
    const float* x_in   = (const float*)d_in[0];
    const float* eattr  = (const float*)d_in[1];
    const int*   eidx   = (const int*)  d_in[2];
    const float* node_W = (const float*)d_in[3];
    const float* node_b = (const float*)d_in[4];
    const float* edge_W = (const float*)d_in[5];
    const float* edge_b = (const float*)d_in[6];
    const float* W1     = (const float*)d_in[7];
    const float* b1     = (const float*)d_in[8];
    const float* W2     = (const float*)d_in[9];
    const float* b2     = (const float*)d_in[10];
    const float* eps    = (const float*)d_in[11];
    const float* lin_W  = (const float*)d_in[12];
    const float* lin_b  = (const float*)d_in[13];
    float* out = (float*)d_out;

    float *pseg, *pinv;
    int *pdegi, *prowptr, *pcursor, *pbflag, *pcsrc;
    __half *pwh, *pch, *pxh, *pxl, *peamh, *peaml, *pxinh, *psegh;
    cudaGetSymbolAddress((void**)&pseg, g_seg);
    cudaGetSymbolAddress((void**)&pinv, g_inv);
    cudaGetSymbolAddress((void**)&pdegi, g_degi);
    cudaGetSymbolAddress((void**)&prowptr, g_rowptr);
    cudaGetSymbolAddress((void**)&pcursor, g_cursor);
    cudaGetSymbolAddress((void**)&pbflag, g_bflag);
    cudaGetSymbolAddress((void**)&pcsrc, g_csrc);
    cudaGetSymbolAddress((void**)&pwh,  g_whi);
    cudaGetSymbolAddress((void**)&pch,  g_ch);
    cudaGetSymbolAddress((void**)&pxh,  g_xh);
    cudaGetSymbolAddress((void**)&pxl,  g_xl);
    cudaGetSymbolAddress((void**)&peamh, g_eamh);
    cudaGetSymbolAddress((void**)&peaml, g_eaml);
    cudaGetSymbolAddress((void**)&pxinh, g_xinh);
    cudaGetSymbolAddress((void**)&psegh, g_segh);

    constexpr int SM_ENC  = 49152;
    constexpr int SM_MLP0 = 65536;
    constexpr int SM_MLP1 = 98304;
    auto setsm = [](const void* f, int b) {
        cudaFuncSetAttribute(f, cudaFuncAttributeMaxDynamicSharedMemorySize, b);
    };
    setsm((const void*)enc_kernel, SM_ENC);
    setsm((const void*)mlp_fused<0>, SM_MLP0);
    setsm((const void*)mlp_fused<1>, SM_MLP1);

    // ---- resets ----
    cudaMemsetAsync(pdegi, 0, NN * sizeof(int));
    cudaMemsetAsync(pseg, 0, (size_t)NN * IN_EDGE * sizeof(float));
    cudaMemsetAsync(pbflag, 0, NB * sizeof(int));

    // ---- front: weight prep + deg + seg scatter + x_in round ----
    front_kernel<<<FB_W + FB_DEG + FB_SEG + FB_X, 256>>>(
        node_W, edge_W, W1, W2, lin_W, pwh, eidx, pdegi, eattr, pseg, x_in, pxinh);

    // ---- scan, then merged seg2h + csr_fill ----
    scan_fused<<<NB, 256>>>(pdegi, pbflag, prowptr, pcursor, pinv);
    mid_kernel<<<MB_SEG + (EE + 255) / 256, 256>>>(pseg, psegh, eidx, pcursor, pcsrc);

    // ---- merged encoders (node + edge in one launch) ----
    enc_kernel<<<dim3(TILES_M, 4), 256, SM_ENC>>>(pxinh, psegh, pwh,
        node_b, edge_b, pxh, pxl, peamh, peaml, pinv, pdegi);

    for (int l = 0; l < 3; l++) {
        gather_combine<<<(NN * 32 + 255) / 256, 256>>>(prowptr, pcsrc, pxh, pxl,
            peamh, peaml, pinv, eps, l, pch);
        if (l < 2) {
            mlp_fused<0><<<NBM, 128, SM_MLP0>>>(pch,
                pwh + 24576 + l * 32768, b1 + (size_t)l * HH2,
                pwh + 122880 + l * 32768, b2 + (size_t)l * HH,
                pxh, pxl, nullptr, nullptr, nullptr);
        } else {
            mlp_fused<1><<<NBM, 128, SM_MLP1>>>(pch,
                pwh + 24576 + l * 32768, b1 + (size_t)l * HH2,
                pwh + 122880 + l * 32768, b2 + (size_t)l * HH,
                nullptr, nullptr, pwh + 221184, lin_b, out);
        }
    }
}

// round 15
// speedup vs baseline: 2.3468x; 1.0127x over previous
#include <cuda_runtime.h>
#include <cuda_fp16.h>
#include <cstdint>

#define NN     50000
#define EE     625000
#define IN_EDGE 64
#define HH     128
#define HH2    256
#define OUTD   112
#define TILES_M 391   // ceil(50000/128)
#define NBM    782    // ceil(50000/64)
#define NB     196    // ceil(50000/256)

// ---------------- scratch (device globals; no allocation allowed) ----------
__device__ __align__(16) float g_seg[NN * IN_EDGE];
__device__ float g_inv[NN];
__device__ int   g_degi[NN];
__device__ int   g_rowptr[NN + 1];
__device__ int   g_cursor[NN];
__device__ int   g_bflag[NB];
__device__ int   g_csrc[EE];

// activations
__device__ __align__(16) __half g_xinh[NN * HH];     // x_in rounded fp16
__device__ __align__(16) __half g_segh[NN * IN_EDGE];// seg rounded fp16
__device__ __align__(16) __half g_ch  [NN * HH];     // combined (hi), W1 input
__device__ __align__(16) __half g_xh  [NN * HH];     // node state (split hi)
__device__ __align__(16) __half g_xl  [NN * HH];     // node state (split lo)
__device__ __align__(16) __half g_eamh[NN * HH];     // edge-agg-mean (split)
__device__ __align__(16) __half g_eaml[NN * HH];

// pre-rounded transposed weights, layout [N][K] fp16
__device__ __align__(16) __half g_whi[235520];

// ---------------------------------------------------------------------------
__device__ __forceinline__ uint32_t smem_u32(const void* p) {
    uint32_t a;
    asm("{ .reg .u64 t; cvta.to.shared.u64 t, %1; cvt.u32.u64 %0, t; }"
        : "=r"(a) : "l"(p));
    return a;
}
__device__ __forceinline__ void cp16(uint32_t dst, const void* src) {
    asm volatile("cp.async.cg.shared.global [%0], [%1], 16;"
                 :: "r"(dst), "l"(src) : "memory");
}
__device__ __forceinline__ void zero16(uint32_t dst) {
    asm volatile("st.shared.v4.b32 [%0], {%1,%1,%1,%1};" :: "r"(dst), "r"(0) : "memory");
}
__device__ __forceinline__ void ldsm4(uint32_t* r, uint32_t addr) {
    asm volatile("ldmatrix.sync.aligned.m8n8.x4.shared.b16 {%0,%1,%2,%3}, [%4];"
                 : "=r"(r[0]), "=r"(r[1]), "=r"(r[2]), "=r"(r[3]) : "r"(addr));
}
__device__ __forceinline__ void mma16816(float* d, const uint32_t* a, const uint32_t* b) {
    asm volatile("mma.sync.aligned.m16n8k16.row.col.f32.f16.f16.f32 "
                 "{%0,%1,%2,%3}, {%4,%5,%6,%7}, {%8,%9}, {%0,%1,%2,%3};"
                 : "+f"(d[0]), "+f"(d[1]), "+f"(d[2]), "+f"(d[3])
                 : "r"(a[0]), "r"(a[1]), "r"(a[2]), "r"(a[3]), "r"(b[0]), "r"(b[1]));
}
__device__ __forceinline__ void split2(float a, float b, uint32_t& hi, uint32_t& lo) {
    __half ha = __float2half(a), hb = __float2half(b);
    __half2 h = __halves2half2(ha, hb);
    __half2 l = __halves2half2(
        __float2half(a - __half2float(ha)),
        __float2half(b - __half2float(hb)));
    hi = *(uint32_t*)&h; lo = *(uint32_t*)&l;
}
__device__ __forceinline__ uint32_t pack2(float a, float b) {
    __half2 h = __halves2half2(__float2half(a), __float2half(b));
    return *(uint32_t*)&h;
}
__device__ __forceinline__ float2 unpack2(uint32_t h, uint32_t l) {
    __half2 hh = *(__half2*)&h;
    __half2 ll = *(__half2*)&l;
    return make_float2(__low2float(hh) + __low2float(ll),
                       __high2float(hh) + __high2float(ll));
}
__device__ __forceinline__ void red_add_v4(float* addr, float4 v) {
    asm volatile("red.global.add.v4.f32 [%0], {%1,%2,%3,%4};"
                 :: "l"(addr), "f"(v.x), "f"(v.y), "f"(v.z), "f"(v.w) : "memory");
}

// ---------------------------------------------------------------------------
// front: weight prep + degree histogram + seg scatter + x_in fp16 rounding
// ---------------------------------------------------------------------------
#define FB_W   920
#define FB_DEG 2442
#define FB_SEG 39063
#define FB_X   3125
__global__ void front_kernel(const float* __restrict__ node_W, const float* __restrict__ edge_W,
                             const float* __restrict__ W1, const float* __restrict__ W2,
                             const float* __restrict__ lin_W,
                             __half* __restrict__ hi,
                             const int* __restrict__ ei, int* __restrict__ degi,
                             const float* __restrict__ ea, float* __restrict__ seg,
                             const float* __restrict__ x_in, __half* __restrict__ xinh) {
    if (blockIdx.x < FB_W) {
        int i = blockIdx.x * 256 + threadIdx.x;
        if (i >= 235520) return;
        const float* src; int K, Nc, idx;
        if (i < 16384)       { src = node_W;                 K = 128; Nc = 128; idx = i; }
        else if (i < 24576)  { src = edge_W;                 K =  64; Nc = 128; idx = i - 16384; }
        else if (i < 122880) { int j = i - 24576;  src = W1 + (j / 32768) * 32768; K = 128; Nc = 256; idx = j % 32768; }
        else if (i < 221184) { int j = i - 122880; src = W2 + (j / 32768) * 32768; K = 256; Nc = 128; idx = j % 32768; }
        else                 { src = lin_W;                  K = 128; Nc = 112; idx = i - 221184; }
        int n = idx / K, k = idx % K;
        hi[i] = __float2half(__ldg(&src[(size_t)k * Nc + n]));
    } else if (blockIdx.x < FB_W + FB_DEG) {
        int e = (blockIdx.x - FB_W) * 256 + threadIdx.x;
        if (e < EE) atomicAdd(&degi[ei[EE + e]], 1);
    } else if (blockIdx.x < FB_W + FB_DEG + FB_SEG) {
        int gid = (blockIdx.x - FB_W - FB_DEG) * 256 + threadIdx.x;
        if (gid >= EE * 16) return;
        int e = gid >> 4, g = gid & 15;
        int dst = __ldg(&ei[EE + e]);
        float4 v = __ldg(((const float4*)ea) + (size_t)e * 16 + g);
        red_add_v4(seg + (size_t)dst * IN_EDGE + g * 4, v);
    } else {
        int gid = (blockIdx.x - FB_W - FB_DEG - FB_SEG) * 256 + threadIdx.x;
        size_t base = (size_t)gid * 8;
        if (base >= (size_t)NN * HH) return;
        float4 v0 = __ldg((const float4*)(x_in + base));
        float4 v1 = __ldg((const float4*)(x_in + base + 4));
        uint4 o;
        o.x = pack2(v0.x, v0.y); o.y = pack2(v0.z, v0.w);
        o.z = pack2(v1.x, v1.y); o.w = pack2(v1.z, v1.w);
        *(uint4*)(xinh + base) = o;
    }
}

// ---------------------------------------------------------------------------
// single-kernel exclusive scan (decoupled lookback over 196 blocks)
// ---------------------------------------------------------------------------
__global__ void scan_fused(const int* __restrict__ d, int* __restrict__ bflag,
                           int* __restrict__ rowptr, int* __restrict__ cursor,
                           float* __restrict__ inv) {
    __shared__ int s[256];
    __shared__ int sred[256];
    int b = blockIdx.x;
    int t = threadIdx.x;
    int i = b * 256 + t;
    int v = (i < NN) ? d[i] : 0;
    s[t] = v;
    __syncthreads();
    #pragma unroll
    for (int o = 1; o < 256; o <<= 1) {
        int tv = (t >= o) ? s[t - o] : 0;
        __syncthreads();
        s[t] += tv;
        __syncthreads();
    }
    int incl = s[t];
    int agg = s[255];
    if (t == 0) atomicExch(&bflag[b], agg + 1);
    int pval = 0;
    if (t < b) {
        int x;
        do { x = atomicAdd(&bflag[t], 0); } while (x == 0);
        pval = x - 1;
    }
    sred[t] = pval;
    __syncthreads();
    #pragma unroll
    for (int o = 128; o > 0; o >>= 1) {
        if (t < o) sred[t] += sred[t + o];
        __syncthreads();
    }
    int boffv = sred[0];
    if (i < NN) {
        int excl = incl - v + boffv;
        rowptr[i] = excl;
        cursor[i] = excl;
        inv[i] = 1.0f / (float)max(v, 1);
    }
    if (b == NB - 1 && t == 255) rowptr[NN] = boffv + agg;
}

// merged: seg fp32->fp16 conversion + csr fill
#define MB_SEG 1563
__global__ void mid_kernel(const float* __restrict__ seg, __half* __restrict__ segh,
                           const int* __restrict__ ei, int* __restrict__ cursor,
                           int* __restrict__ csrc) {
    if (blockIdx.x < MB_SEG) {
        size_t base = ((size_t)blockIdx.x * 256 + threadIdx.x) * 8;
        if (base >= (size_t)NN * IN_EDGE) return;
        float4 v0 = __ldg((const float4*)(seg + base));
        float4 v1 = __ldg((const float4*)(seg + base + 4));
        uint4 o;
        o.x = pack2(v0.x, v0.y); o.y = pack2(v0.z, v0.w);
        o.z = pack2(v1.x, v1.y); o.w = pack2(v1.z, v1.w);
        *(uint4*)(segh + base) = o;
    } else {
        int e = (blockIdx.x - MB_SEG) * 256 + threadIdx.x;
        if (e >= EE) return;
        int dst = __ldg(&ei[EE + e]);
        int p = atomicAdd(&cursor[dst], 1);
        csrc[p] = __ldg(&ei[e]);
    }
}

// fused: agg = sum_neighbors(x_hi) ; c = (1+eps)*x + agg*inv + eam -> ch (fp16 hi)
__global__ void gather_combine(const int* __restrict__ rowptr, const int* __restrict__ csrc,
                               const __half* __restrict__ xh,
                               const __half* __restrict__ xl,
                               const __half* __restrict__ eamh,
                               const __half* __restrict__ eaml,
                               const float* __restrict__ inv,
                               const float* __restrict__ eps_p, int layer,
                               __half* __restrict__ ch) {
    int w = (blockIdx.x * blockDim.x + threadIdx.x) >> 5;
    if (w >= NN) return;
    int lane = threadIdx.x & 31;
    int beg = __ldg(&rowptr[w]), end = __ldg(&rowptr[w + 1]);
    float a0 = 0.f, a1 = 0.f, a2 = 0.f, a3 = 0.f;
    for (int j = beg; j < end; j++) {
        int s = __ldg(&csrc[j]);
        uint2 hv = __ldg((const uint2*)(xh + (size_t)s * HH) + lane);
        __half2 h0 = *(__half2*)&hv.x;
        __half2 h1 = *(__half2*)&hv.y;
        a0 += __low2float(h0); a1 += __high2float(h0);
        a2 += __low2float(h1); a3 += __high2float(h1);
    }
    float iv = __ldg(&inv[w]);
    float epsv = 1.f + __ldg(&eps_p[layer]);
    uint2 hs = __ldg((const uint2*)(xh + (size_t)w * HH) + lane);
    uint2 ls = __ldg((const uint2*)(xl + (size_t)w * HH) + lane);
    float2 x01 = unpack2(hs.x, ls.x);
    float2 x23 = unpack2(hs.y, ls.y);
    uint2 eh = __ldg((const uint2*)(eamh + (size_t)w * HH) + lane);
    uint2 el = __ldg((const uint2*)(eaml + (size_t)w * HH) + lane);
    float2 e01 = unpack2(eh.x, el.x);
    float2 e23 = unpack2(eh.y, el.y);
    uint2 h;
    h.x = pack2(epsv * x01.x + a0 * iv + e01.x, epsv * x01.y + a1 * iv + e01.y);
    h.y = pack2(epsv * x23.x + a2 * iv + e23.x, epsv * x23.y + a3 * iv + e23.y);
    *(uint2*)(ch + (size_t)w * HH + lane * 4) = h;
}

// ---------------------------------------------------------------------------
// Fused GIN MLP (HEAD=1: + output head in phase 3, x never hits global).
// HEAD=0 runs 3 CTAs/SM (64KB smem); HEAD=1 runs 2 (96KB smem).
// ---------------------------------------------------------------------------
template <int HEAD>
__global__ void __launch_bounds__(128, HEAD ? 2 : 3)
mlp_fused(const __half* __restrict__ C, const __half* __restrict__ W1h,
          const float* __restrict__ b1, const __half* __restrict__ W2h,
          const float* __restrict__ b2,
          __half* __restrict__ Xh, __half* __restrict__ Xl,
          const __half* __restrict__ Wlin, const float* __restrict__ blin,
          float* __restrict__ out) {
    extern __shared__ char smem[];
    const uint32_t sC = smem_u32(smem);
    const uint32_t sH = sC + 16384;
    const uint32_t sB = sC + 49152;
    const uint32_t sXh = sB + 16384;
    const uint32_t sXl = sXh + 16384;

    const int tid  = threadIdx.x;
    const int lane = tid & 31;
    const int wid  = tid >> 5;
    const int wm   = wid & 1;
    const int wn   = wid >> 1;
    const int rowBase = blockIdx.x * 64;

    #pragma unroll
    for (int i = 0; i < 8; i++) {
        int f = tid + i * 128;
        int row = f >> 4, chn = f & 15;
        uint32_t addr = sC + row * 256 + (((uint32_t)(chn * 16)) ^ ((row & 7) << 4));
        int gr = rowBase + row;
        if (gr < NN) cp16(addr, C + (size_t)gr * HH + chn * 8);
        else         zero16(addr);
    }
    asm volatile("cp.async.commit_group;" ::: "memory");

    const uint32_t aRowIdx = (uint32_t)(lane & 15);
    const uint32_t aK16    = (uint32_t)((lane >> 4) << 4);
    const uint32_t bRowIdx = (uint32_t)((lane & 7) + ((lane >> 4) << 3));
    const uint32_t bK16    = (uint32_t)(((lane >> 3) & 1) << 4);
    const int group = lane >> 2;
    const int qc    = (lane & 3) * 2;

    float acc[2][4][4];

    auto loadB = [&](const __half* W, int KT, int gn0, int kb, int stage, int NcB) {
        #pragma unroll
        for (int i = 0; i < 4; i++) {
            int f = tid + i * 128;
            int row = f >> 3, chn = f & 7;
            uint32_t addr = sB + stage * 8192 + row * 128 +
                            (((uint32_t)(chn * 16)) ^ ((row & 7) << 4));
            if (gn0 + row < NcB) cp16(addr, W + (size_t)(gn0 + row) * KT + kb + chn * 8);
            else                 zero16(addr);
        }
        asm volatile("cp.async.commit_group;" ::: "memory");
    };
    auto zacc = [&]() {
        #pragma unroll
        for (int a = 0; a < 2; a++)
            #pragma unroll
            for (int b = 0; b < 4; b++)
                #pragma unroll
                for (int c = 0; c < 4; c++) acc[a][b][c] = 0.f;
    };

    // ---------- phase 1: h1(smem) = relu(c @ W1 + b1), N=256, K=128 ----------
    loadB(W1h, 128, 0, 0, 0, 256);
    for (int t = 0; t < 8; t++) {
        int cp = t >> 1, kc = t & 1;
        if (t + 1 < 8) {
            loadB(W1h, 128, ((t + 1) >> 1) * 64, ((t + 1) & 1) * 64, (t + 1) & 1, 256);
            asm volatile("cp.async.wait_group 1;" ::: "memory");
        } else {
            asm volatile("cp.async.wait_group 0;" ::: "memory");
        }
        __syncthreads();
        if (kc == 0) zacc();
        uint32_t bBuf = sB + (t & 1) * 8192;
        #pragma unroll
        for (int ks = 0; ks < 4; ks++) {
            uint32_t ah[2][4], bh[4][2];
            #pragma unroll
            for (int mi = 0; mi < 2; mi++) {
                uint32_t row = wm * 32 + mi * 16 + aRowIdx;
                uint32_t cb = (uint32_t)(kc * 128 + ks * 32) + aK16;
                ldsm4(ah[mi], sC + row * 256 + (cb ^ ((row & 7) << 4)));
            }
            #pragma unroll
            for (int pr = 0; pr < 2; pr++) {
                uint32_t row = wn * 32 + pr * 16 + bRowIdx;
                uint32_t cb = (uint32_t)(ks * 32) + bK16;
                uint32_t tr[4];
                ldsm4(tr, bBuf + row * 128 + (cb ^ ((row & 7) << 4)));
                bh[pr*2][0] = tr[0]; bh[pr*2][1] = tr[1];
                bh[pr*2+1][0] = tr[2]; bh[pr*2+1][1] = tr[3];
            }
            #pragma unroll
            for (int mi = 0; mi < 2; mi++)
                #pragma unroll
                for (int ni = 0; ni < 4; ni++)
                    mma16816(acc[mi][ni], ah[mi], bh[ni]);
        }
        if (kc == 1) {
            #pragma unroll
            for (int mi = 0; mi < 2; mi++) {
                int r0 = wm * 32 + mi * 16 + group;
                int r1 = r0 + 8;
                #pragma unroll
                for (int ni = 0; ni < 4; ni++) {
                    int c = cp * 64 + wn * 32 + ni * 8 + qc;
                    float bv0 = __ldg(&b1[c]), bv1 = __ldg(&b1[c + 1]);
                    uint32_t p0 = pack2(fmaxf(acc[mi][ni][0] + bv0, 0.f),
                                        fmaxf(acc[mi][ni][1] + bv1, 0.f));
                    uint32_t p1 = pack2(fmaxf(acc[mi][ni][2] + bv0, 0.f),
                                        fmaxf(acc[mi][ni][3] + bv1, 0.f));
                    uint32_t cb = (uint32_t)(c * 2);
                    uint32_t a0 = sH + r0 * 512 + (cb ^ ((r0 & 7) << 4));
                    uint32_t a1 = sH + r1 * 512 + (cb ^ ((r1 & 7) << 4));
                    asm volatile("st.shared.b32 [%0], %1;" :: "r"(a0), "r"(p0) : "memory");
                    asm volatile("st.shared.b32 [%0], %1;" :: "r"(a1), "r"(p1) : "memory");
                }
            }
        }
        __syncthreads();
    }

    // ---------- phase 2: x = relu(h1 @ W2 + b2), N=128, K=256 ----------
    loadB(W2h, 256, 0, 0, 0, 128);
    for (int t = 0; t < 8; t++) {
        int cp = t >> 2, kc = t & 3;
        if (t + 1 < 8) {
            loadB(W2h, 256, ((t + 1) >> 2) * 64, ((t + 1) & 3) * 64, (t + 1) & 1, 128);
            asm volatile("cp.async.wait_group 1;" ::: "memory");
        } else {
            asm volatile("cp.async.wait_group 0;" ::: "memory");
        }
        __syncthreads();
        if (kc == 0) zacc();
        uint32_t bBuf = sB + (t & 1) * 8192;
        #pragma unroll
        for (int ks = 0; ks < 4; ks++) {
            uint32_t ah[2][4], bh[4][2];
            #pragma unroll
            for (int mi = 0; mi < 2; mi++) {
                uint32_t row = wm * 32 + mi * 16 + aRowIdx;
                uint32_t cb = (uint32_t)(kc * 128 + ks * 32) + aK16;
                ldsm4(ah[mi], sH + row * 512 + (cb ^ ((row & 7) << 4)));
            }
            #pragma unroll
            for (int pr = 0; pr < 2; pr++) {
                uint32_t row = wn * 32 + pr * 16 + bRowIdx;
                uint32_t cb = (uint32_t)(ks * 32) + bK16;
                uint32_t tr[4];
                ldsm4(tr, bBuf + row * 128 + (cb ^ ((row & 7) << 4)));
                bh[pr*2][0] = tr[0]; bh[pr*2][1] = tr[1];
                bh[pr*2+1][0] = tr[2]; bh[pr*2+1][1] = tr[3];
            }
            #pragma unroll
            for (int mi = 0; mi < 2; mi++)
                #pragma unroll
                for (int ni = 0; ni < 4; ni++)
                    mma16816(acc[mi][ni], ah[mi], bh[ni]);
        }
        if (kc == 3) {
            #pragma unroll
            for (int mi = 0; mi < 2; mi++) {
                int rl0 = wm * 32 + mi * 16 + group;
                int rl1 = rl0 + 8;
                int r0 = rowBase + rl0;
                int r1 = rowBase + rl1;
                #pragma unroll
                for (int ni = 0; ni < 4; ni++) {
                    int c = cp * 64 + wn * 32 + ni * 8 + qc;
                    float bv0 = __ldg(&b2[c]), bv1 = __ldg(&b2[c + 1]);
                    float v00 = fmaxf(acc[mi][ni][0] + bv0, 0.f);
                    float v01 = fmaxf(acc[mi][ni][1] + bv1, 0.f);
                    float v10 = fmaxf(acc[mi][ni][2] + bv0, 0.f);
                    float v11 = fmaxf(acc[mi][ni][3] + bv1, 0.f);
                    uint32_t h0, l0, h1, l1;
                    split2(v00, v01, h0, l0);
                    split2(v10, v11, h1, l1);
                    if (HEAD == 0) {
                        if (r0 < NN) {
                            *(uint32_t*)(Xh + (size_t)r0 * HH + c) = h0;
                            *(uint32_t*)(Xl + (size_t)r0 * HH + c) = l0;
                        }
                        if (r1 < NN) {
                            *(uint32_t*)(Xh + (size_t)r1 * HH + c) = h1;
                            *(uint32_t*)(Xl + (size_t)r1 * HH + c) = l1;
                        }
                    } else {
                        uint32_t cb = (uint32_t)(c * 2);
                        uint32_t a0 = rl0 * 256 + (cb ^ ((rl0 & 7) << 4));
                        uint32_t a1 = rl1 * 256 + (cb ^ ((rl1 & 7) << 4));
                        asm volatile("st.shared.b32 [%0], %1;" :: "r"(sXh + a0), "r"(h0) : "memory");
                        asm volatile("st.shared.b32 [%0], %1;" :: "r"(sXl + a0), "r"(l0) : "memory");
                        asm volatile("st.shared.b32 [%0], %1;" :: "r"(sXh + a1), "r"(h1) : "memory");
                        asm volatile("st.shared.b32 [%0], %1;" :: "r"(sXl + a1), "r"(l1) : "memory");
                    }
                }
            }
        }
        __syncthreads();
    }

    // ---------- phase 3 (HEAD): out = (xh+xl) @ lin_W + lin_b ----------
    if (HEAD == 1) {
        loadB(Wlin, 128, 0, 0, 0, OUTD);
        for (int t = 0; t < 4; t++) {
            int cp = t >> 1, kc = t & 1;
            if (t + 1 < 4) {
                loadB(Wlin, 128, ((t + 1) >> 1) * 64, ((t + 1) & 1) * 64, (t + 1) & 1, OUTD);
                asm volatile("cp.async.wait_group 1;" ::: "memory");
            } else {
                asm volatile("cp.async.wait_group 0;" ::: "memory");
            }
            __syncthreads();
            if (kc == 0) zacc();
            uint32_t bBuf = sB + (t & 1) * 8192;
            #pragma unroll
            for (int ks = 0; ks < 4; ks++) {
                uint32_t ah[2][4], al[2][4], bh[4][2];
                #pragma unroll
                for (int mi = 0; mi < 2; mi++) {
                    uint32_t row = wm * 32 + mi * 16 + aRowIdx;
                    uint32_t cb = (uint32_t)(kc * 128 + ks * 32) + aK16;
                    uint32_t off = row * 256 + (cb ^ ((row & 7) << 4));
                    ldsm4(ah[mi], sXh + off);
                    ldsm4(al[mi], sXl + off);
                }
                #pragma unroll
                for (int pr = 0; pr < 2; pr++) {
                    uint32_t row = wn * 32 + pr * 16 + bRowIdx;
                    uint32_t cb = (uint32_t)(ks * 32) + bK16;
                    uint32_t tr[4];
                    ldsm4(tr, bBuf + row * 128 + (cb ^ ((row & 7) << 4)));
                    bh[pr*2][0] = tr[0]; bh[pr*2][1] = tr[1];
                    bh[pr*2+1][0] = tr[2]; bh[pr*2+1][1] = tr[3];
                }
                #pragma unroll
                for (int mi = 0; mi < 2; mi++)
                    #pragma unroll
                    for (int ni = 0; ni < 4; ni++) {
                        mma16816(acc[mi][ni], ah[mi], bh[ni]);
                        mma16816(acc[mi][ni], al[mi], bh[ni]);
                    }
            }
            if (kc == 1) {
                #pragma unroll
                for (int mi = 0; mi < 2; mi++) {
                    int r0 = rowBase + wm * 32 + mi * 16 + group;
                    int r1 = r0 + 8;
                    #pragma unroll
                    for (int ni = 0; ni < 4; ni++) {
                        int c = cp * 64 + wn * 32 + ni * 8 + qc;
                        if (c >= OUTD) continue;
                        float bv0 = __ldg(&blin[c]), bv1 = __ldg(&blin[c + 1]);
                        if (r0 < NN) {
                            float2 v; v.x = acc[mi][ni][0] + bv0; v.y = acc[mi][ni][1] + bv1;
                            *(float2*)(out + (size_t)r0 * OUTD + c) = v;
                        }
                        if (r1 < NN) {
                            float2 v; v.x = acc[mi][ni][2] + bv0; v.y = acc[mi][ni][3] + bv1;
                            *(float2*)(out + (size_t)r1 * OUTD + c) = v;
                        }
                    }
                }
            }
            __syncthreads();
        }
    }
}

// ---------------------------------------------------------------------------
// MERGED encoder kernel: grid (TILES_M, 4), 3 CTAs/SM for latency overlap.
//  by>>1 == 0: node encoder  x(split) = xinh @ Wnode + node_b   (K=128)
//  by>>1 == 1: edge encoder  eam(split) = (segh @ Wedge)*inv + [deg>0]*edge_b (K=64)
// ---------------------------------------------------------------------------
__global__ void __launch_bounds__(256, 3)
enc_kernel(const __half* __restrict__ xinh, const __half* __restrict__ segh,
           const __half* __restrict__ wall,
           const float* __restrict__ node_b, const float* __restrict__ edge_b,
           __half* __restrict__ xh, __half* __restrict__ xl,
           __half* __restrict__ eamh, __half* __restrict__ eaml,
           const float* __restrict__ inv, const int* __restrict__ degi) {
    constexpr int STG = 24576;
    extern __shared__ char smem[];
    const uint32_t sb = smem_u32(smem);

    const int task = blockIdx.y >> 1;
    const int colBase = (blockIdx.y & 1) * 64;
    const int KT      = task ? 64 : 128;
    const int CHUNKS  = task ? 1 : 2;
    const __half* Ah  = task ? segh : xinh;
    const __half* Bhi = task ? (wall + 16384) : wall;
    const float* bias = task ? edge_b : node_b;
    __half* Ch = task ? eamh : xh;
    __half* Cl = task ? eaml : xl;

    const int tid  = threadIdx.x;
    const int lane = tid & 31;
    const int wid  = tid >> 5;
    const int wm   = wid & 3;
    const int wn   = wid >> 2;
    const int rowBase = blockIdx.x * 128;

    float acc[2][4][4];
    #pragma unroll
    for (int a = 0; a < 2; a++)
        #pragma unroll
        for (int b = 0; b < 4; b++)
            #pragma unroll
            for (int c = 0; c < 4; c++) acc[a][b][c] = 0.f;

    auto load_slab = [&](int stage, int c) {
        uint32_t base = sb + stage * STG;
        int kb = c * 64;
        #pragma unroll
        for (int i = 0; i < 4; i++) {
            int f = tid + i * 256;
            int row = f >> 3, chn = f & 7;
            uint32_t sw = (uint32_t)(chn * 16) ^ (uint32_t)((row & 7) << 4);
            uint32_t da = base + row * 128 + sw;
            int gr = rowBase + row;
            if (gr < NN) cp16(da, Ah + (size_t)gr * KT + kb + chn * 8);
            else         zero16(da);
        }
        #pragma unroll
        for (int i = 0; i < 2; i++) {
            int f = tid + i * 256;
            int row = f >> 3, chn = f & 7;
            uint32_t sw = (uint32_t)(chn * 16) ^ (uint32_t)((row & 7) << 4);
            uint32_t db = base + 16384 + row * 128 + sw;
            cp16(db, Bhi + (size_t)(colBase + row) * KT + kb + chn * 8);
        }
        asm volatile("cp.async.commit_group;" ::: "memory");
    };

    const uint32_t aRowIdx = (uint32_t)(lane & 15);
    const uint32_t aK16    = (uint32_t)((lane >> 4) << 4);
    const uint32_t bRowIdx = (uint32_t)((lane & 7) + ((lane >> 4) << 3));
    const uint32_t bK16    = (uint32_t)(((lane >> 3) & 1) << 4);

    load_slab(0, 0);

    for (int c = 0; c < CHUNKS; c++) {
        if (c + 1 < CHUNKS) {
            load_slab((c + 1) & 1, c + 1);
            asm volatile("cp.async.wait_group 1;" ::: "memory");
        } else {
            asm volatile("cp.async.wait_group 0;" ::: "memory");
        }
        __syncthreads();

        uint32_t bA = sb + (c & 1) * STG;
        uint32_t bB = bA + 16384;
        #pragma unroll
        for (int ks = 0; ks < 4; ks++) {
            uint32_t ah[2][4], bh[4][2];
            #pragma unroll
            for (int mi = 0; mi < 2; mi++) {
                uint32_t row = wm * 32 + mi * 16 + aRowIdx;
                uint32_t cb = (uint32_t)(ks * 32) + aK16;
                ldsm4(ah[mi], bA + row * 128 + (cb ^ ((row & 7) << 4)));
            }
            #pragma unroll
            for (int pr = 0; pr < 2; pr++) {
                uint32_t row = wn * 32 + pr * 16 + bRowIdx;
                uint32_t cb = (uint32_t)(ks * 32) + bK16;
                uint32_t t[4];
                ldsm4(t, bB + row * 128 + (cb ^ ((row & 7) << 4)));
                bh[pr*2][0] = t[0]; bh[pr*2][1] = t[1];
                bh[pr*2+1][0] = t[2]; bh[pr*2+1][1] = t[3];
            }
            #pragma unroll
            for (int mi = 0; mi < 2; mi++)
                #pragma unroll
                for (int ni = 0; ni < 4; ni++)
                    mma16816(acc[mi][ni], ah[mi], bh[ni]);
        }
        if (c + 1 < CHUNKS) __syncthreads();
    }

    const int group = lane >> 2;
    const int qc    = (lane & 3) * 2;
    #pragma unroll
    for (int mi = 0; mi < 2; mi++) {
        int r0 = rowBase + wm * 32 + mi * 16 + group;
        int r1 = r0 + 8;
        float iv0 = 0.f, m0 = 0.f, iv1 = 0.f, m1 = 0.f;
        if (task == 1) {
            if (r0 < NN) { iv0 = __ldg(&inv[r0]); m0 = (__ldg(&degi[r0]) > 0) ? 1.f : 0.f; }
            if (r1 < NN) { iv1 = __ldg(&inv[r1]); m1 = (__ldg(&degi[r1]) > 0) ? 1.f : 0.f; }
        }
        #pragma unroll
        for (int ni = 0; ni < 4; ni++) {
            int c = colBase + wn * 32 + ni * 8 + qc;
            float b0 = __ldg(&bias[c]), b1 = __ldg(&bias[c + 1]);
            float2 v0, v1;
            if (task == 1) {
                v0.x = acc[mi][ni][0] * iv0 + m0 * b0;
                v0.y = acc[mi][ni][1] * iv0 + m0 * b1;
                v1.x = acc[mi][ni][2] * iv1 + m1 * b0;
                v1.y = acc[mi][ni][3] * iv1 + m1 * b1;
            } else {
                v0.x = acc[mi][ni][0] + b0; v0.y = acc[mi][ni][1] + b1;
                v1.x = acc[mi][ni][2] + b0; v1.y = acc[mi][ni][3] + b1;
            }
            if (r0 < NN) {
                uint32_t h, l; split2(v0.x, v0.y, h, l);
                *(uint32_t*)(Ch + (size_t)r0 * HH + c) = h;
                *(uint32_t*)(Cl + (size_t)r0 * HH + c) = l;
            }
            if (r1 < NN) {
                uint32_t h, l; split2(v1.x, v1.y, h, l);
                *(uint32_t*)(Ch + (size_t)r1 * HH + c) = h;
                *(uint32_t*)(Cl + (size_t)r1 * HH + c) = l;
            }
        }
    }
}

// ---------------------------------------------------------------------------
extern "C" void kernel_launch(void* const* d_in, const int* in_sizes, int n_in,
                              void* d_out, int out_size) {
    const float* x_in   = (const float*)d_in[0];
    const float* eattr  = (const float*)d_in[1];
    const int*   eidx   = (const int*)  d_in[2];
    const float* node_W = (const float*)d_in[3];
    const float* node_b = (const float*)d_in[4];
    const float* edge_W = (const float*)d_in[5];
    const float* edge_b = (const float*)d_in[6];
    const float* W1     = (const float*)d_in[7];
    const float* b1     = (const float*)d_in[8];
    const float* W2     = (const float*)d_in[9];
    const float* b2     = (const float*)d_in[10];
    const float* eps    = (const float*)d_in[11];
    const float* lin_W  = (const float*)d_in[12];
    const float* lin_b  = (const float*)d_in[13];
    float* out = (float*)d_out;

    float *pseg, *pinv;
    int *pdegi, *prowptr, *pcursor, *pbflag, *pcsrc;
    __half *pwh, *pch, *pxh, *pxl, *peamh, *peaml, *pxinh, *psegh;
    cudaGetSymbolAddress((void**)&pseg, g_seg);
    cudaGetSymbolAddress((void**)&pinv, g_inv);
    cudaGetSymbolAddress((void**)&pdegi, g_degi);
    cudaGetSymbolAddress((void**)&prowptr, g_rowptr);
    cudaGetSymbolAddress((void**)&pcursor, g_cursor);
    cudaGetSymbolAddress((void**)&pbflag, g_bflag);
    cudaGetSymbolAddress((void**)&pcsrc, g_csrc);
    cudaGetSymbolAddress((void**)&pwh,  g_whi);
    cudaGetSymbolAddress((void**)&pch,  g_ch);
    cudaGetSymbolAddress((void**)&pxh,  g_xh);
    cudaGetSymbolAddress((void**)&pxl,  g_xl);
    cudaGetSymbolAddress((void**)&peamh, g_eamh);
    cudaGetSymbolAddress((void**)&peaml, g_eaml);
    cudaGetSymbolAddress((void**)&pxinh, g_xinh);
    cudaGetSymbolAddress((void**)&psegh, g_segh);

    constexpr int SM_ENC  = 49152;
    constexpr int SM_MLP0 = 65536;
    constexpr int SM_MLP1 = 98304;
    auto setsm = [](const void* f, int b) {
        cudaFuncSetAttribute(f, cudaFuncAttributeMaxDynamicSharedMemorySize, b);
    };
    setsm((const void*)enc_kernel, SM_ENC);
    setsm((const void*)mlp_fused<0>, SM_MLP0);
    setsm((const void*)mlp_fused<1>, SM_MLP1);

    // ---- resets ----
    cudaMemsetAsync(pdegi, 0, NN * sizeof(int));
    cudaMemsetAsync(pseg, 0, (size_t)NN * IN_EDGE * sizeof(float));
    cudaMemsetAsync(pbflag, 0, NB * sizeof(int));

    // ---- front: weight prep + deg + seg scatter + x_in round ----
    front_kernel<<<FB_W + FB_DEG + FB_SEG + FB_X, 256>>>(
        node_W, edge_W, W1, W2, lin_W, pwh, eidx, pdegi, eattr, pseg, x_in, pxinh);

    // ---- scan, then merged seg2h + csr_fill ----
    scan_fused<<<NB, 256>>>(pdegi, pbflag, prowptr, pcursor, pinv);
    mid_kernel<<<MB_SEG + (EE + 255) / 256, 256>>>(pseg, psegh, eidx, pcursor, pcsrc);

    // ---- merged encoders (node + edge in one launch) ----
    enc_kernel<<<dim3(TILES_M, 4), 256, SM_ENC>>>(pxinh, psegh, pwh,
        node_b, edge_b, pxh, pxl, peamh, peaml, pinv, pdegi);

    for (int l = 0; l < 3; l++) {
        gather_combine<<<(NN * 32 + 255) / 256, 256>>>(prowptr, pcsrc, pxh, pxl,
            peamh, peaml, pinv, eps, l, pch);
        if (l < 2) {
            mlp_fused<0><<<NBM, 128, SM_MLP0>>>(pch,
                pwh + 24576 + l * 32768, b1 + (size_t)l * HH2,
                pwh + 122880 + l * 32768, b2 + (size_t)l * HH,
                pxh, pxl, nullptr, nullptr, nullptr);
        } else {
            mlp_fused<1><<<NBM, 128, SM_MLP1>>>(pch,
                pwh + 24576 + l * 32768, b1 + (size_t)l * HH2,
                pwh + 122880 + l * 32768, b2 + (size_t)l * HH,
                nullptr, nullptr, pwh + 221184, lin_b, out);
        }
    }
}